// round 1
// baseline (speedup 1.0000x reference)
#include <cuda_runtime.h>
#include <math.h>

// ---------------- problem constants ----------------
#define NN   2048      // nodes
#define BB   16        // batch
#define DD   64        // dim_out
#define DIN  66        // dim_in + dim_out
#define EMB  16        // embed dim
#define OG   128       // gate out (2*D)
#define OU   64        // update out
#define XCOLS (BB*DIN) // 1056, columns of transposed activation matrices

// ---------------- device scratch (no allocation allowed) ----------------
__device__ float g_A   [(size_t)NN*NN];          // E E^T
__device__ float g_S   [(size_t)NN*NN];          // softmax(relu(A)) rows
__device__ float g_Wg  [(size_t)NN*2*DIN*OG];    // per-node gate weights
__device__ float g_Wu  [(size_t)NN*2*DIN*OU];    // per-node update weights
__device__ float g_inpT[(size_t)NN*XCOLS];       // [m][b*66+i] concat(x,state)
__device__ float g_xg1T[(size_t)NN*XCOLS];       // S @ inpT
__device__ float g_candT[(size_t)NN*XCOLS];      // [m][b*66+i] concat(x, z*state)
__device__ float g_xg2T[(size_t)NN*XCOLS];       // S @ candT
__device__ float g_r   [(size_t)BB*NN*DD];
__device__ float g_h   [(size_t)BB*NN*DD];
__device__ float g_hht [(size_t)BB*NN*NN];       // per-batch H H^T (unmasked)
__device__ float g_deg [(size_t)BB*NN*NN];       // masked matmul result -> softmax in place

// ---------------- A = E E^T ----------------
__global__ void k_embed_outer(const float* __restrict__ E) {
    __shared__ float En[16][17], Em[16][17];
    int tx = threadIdx.x, ty = threadIdx.y;
    En[ty][tx] = E[((size_t)blockIdx.y*16 + ty)*EMB + tx];
    Em[ty][tx] = E[((size_t)blockIdx.x*16 + ty)*EMB + tx];
    __syncthreads();
    float s = 0.f;
#pragma unroll
    for (int e = 0; e < 16; e++) s += En[ty][e] * Em[tx][e];
    g_A[((size_t)blockIdx.y*16 + ty)*NN + blockIdx.x*16 + tx] = s;
}

// ---------------- row softmax (mode 0: relu(A)->S ; mode 1: deg in place) ----------------
__global__ void k_rowsoftmax(int mode) {
    __shared__ float buf[NN];
    __shared__ float red[256];
    int row = blockIdx.x;
    int tid = threadIdx.x;
    const float* in;
    float* out;
    if (mode == 0) { in = g_A + (size_t)row*NN; out = g_S + (size_t)row*NN; }
    else {
        size_t off = ((size_t)blockIdx.y*NN + row)*NN;
        in = g_deg + off; out = g_deg + off;
    }
    float mx = -1e30f;
    for (int i = tid; i < NN; i += 256) {
        float v = in[i];
        if (mode == 0) v = v > 0.f ? v : 0.f;
        buf[i] = v;
        mx = fmaxf(mx, v);
    }
    red[tid] = mx; __syncthreads();
    for (int s = 128; s > 0; s >>= 1) {
        if (tid < s) red[tid] = fmaxf(red[tid], red[tid+s]);
        __syncthreads();
    }
    mx = red[0];
    __syncthreads();
    float sum = 0.f;
    for (int i = tid; i < NN; i += 256) {
        float e = __expf(buf[i] - mx);
        buf[i] = e;
        sum += e;
    }
    red[tid] = sum; __syncthreads();
    for (int s = 128; s > 0; s >>= 1) {
        if (tid < s) red[tid] += red[tid+s];
        __syncthreads();
    }
    float inv = 1.0f / red[0];
    for (int i = tid; i < NN; i += 256) out[i] = buf[i] * inv;
}

// ---------------- per-node weights: W[n] = sum_e E[n,e] pool[e] ----------------
__global__ void k_mkW(const float* __restrict__ E, const float* __restrict__ pool,
                      int per_e, int which) {
    __shared__ float Es[16];
    int n = blockIdx.y;
    int j = blockIdx.x*256 + threadIdx.x;
    if (threadIdx.x < 16) Es[threadIdx.x] = E[(size_t)n*EMB + threadIdx.x];
    __syncthreads();
    float s = 0.f;
#pragma unroll
    for (int e = 0; e < 16; e++) s += Es[e] * pool[(size_t)e*per_e + j];
    float* W = (which == 0) ? g_Wg : g_Wu;
    W[(size_t)n*per_e + j] = s;
}

// ---------------- inpT = concat(x,state) transposed; candT gets x-part ----------------
__global__ void k_concat(const float* __restrict__ x, const float* __restrict__ state) {
    int idx = blockIdx.x*256 + threadIdx.x;
    if (idx >= NN*XCOLS) return;
    int n = idx / XCOLS;
    int rem = idx % XCOLS;
    int b = rem / DIN, i = rem % DIN;
    float v;
    if (i < 2) v = x[((size_t)b*NN + n)*2 + i];
    else       v = state[((size_t)b*NN + n)*DD + (i-2)];
    g_inpT[idx] = v;
    if (i < 2) g_candT[idx] = v;
}

// ---------------- xg = S @ X  (M=2048, K=2048, Ncols=1056 with guard) ----------------
__global__ void k_sgemm_SX(int which) {
    const float* Bm = (which == 0) ? g_inpT : g_candT;
    float*       C  = (which == 0) ? g_xg1T : g_xg2T;
    __shared__ __align__(16) float As[16][128];
    __shared__ __align__(16) float Bs[16][128];
    int tid = threadIdx.x;
    int n0 = blockIdx.x*128;  // cols
    int m0 = blockIdx.y*128;  // rows
    int row0 = (tid/16)*8, col0 = (tid%16)*8;
    float acc[8][8] = {};
    int arow = tid >> 1, acs = (tid & 1)*8;
    int brow = tid >> 4, bcs = (tid & 15)*8;
    for (int k0 = 0; k0 < NN; k0 += 16) {
        float4 a0 = *(const float4*)&g_S[(size_t)(m0+arow)*NN + k0 + acs];
        float4 a1 = *(const float4*)&g_S[(size_t)(m0+arow)*NN + k0 + acs + 4];
        As[acs+0][arow]=a0.x; As[acs+1][arow]=a0.y; As[acs+2][arow]=a0.z; As[acs+3][arow]=a0.w;
        As[acs+4][arow]=a1.x; As[acs+5][arow]=a1.y; As[acs+6][arow]=a1.z; As[acs+7][arow]=a1.w;
        float4 b0 = make_float4(0,0,0,0), b1 = make_float4(0,0,0,0);
        int bc = n0 + bcs;
        if (bc < XCOLS) {
            b0 = *(const float4*)&Bm[(size_t)(k0+brow)*XCOLS + bc];
            b1 = *(const float4*)&Bm[(size_t)(k0+brow)*XCOLS + bc + 4];
        }
        *(float4*)&Bs[brow][bcs]   = b0;
        *(float4*)&Bs[brow][bcs+4] = b1;
        __syncthreads();
#pragma unroll
        for (int k = 0; k < 16; k++) {
            float av[8], bv[8];
            float4 t;
            t = *(const float4*)&As[k][row0];   av[0]=t.x; av[1]=t.y; av[2]=t.z; av[3]=t.w;
            t = *(const float4*)&As[k][row0+4]; av[4]=t.x; av[5]=t.y; av[6]=t.z; av[7]=t.w;
            t = *(const float4*)&Bs[k][col0];   bv[0]=t.x; bv[1]=t.y; bv[2]=t.z; bv[3]=t.w;
            t = *(const float4*)&Bs[k][col0+4]; bv[4]=t.x; bv[5]=t.y; bv[6]=t.z; bv[7]=t.w;
#pragma unroll
            for (int i = 0; i < 8; i++)
#pragma unroll
                for (int j = 0; j < 8; j++) acc[i][j] += av[i]*bv[j];
        }
        __syncthreads();
    }
#pragma unroll
    for (int i = 0; i < 8; i++) {
        int row = m0 + row0 + i;
#pragma unroll
        for (int j = 0; j < 8; j++) {
            int col = n0 + col0 + j;
            if (col < XCOLS) C[(size_t)row*XCOLS + col] = acc[i][j];
        }
    }
}

// ---------------- gate apply: z_r = sigmoid(xg @ W[n] + b[n]); write candT z-part, g_r ----------------
__global__ void k_gate_apply(const float* __restrict__ E, const float* __restrict__ gate_b,
                             const float* __restrict__ state) {
    int n = blockIdx.x;
    int o = threadIdx.x;   // 128 threads
    __shared__ float Xs[BB][2*DIN];
    __shared__ float Es[16];
    if (o < 16) Es[o] = E[(size_t)n*EMB + o];
    for (int idx = o; idx < BB*2*DIN; idx += 128) {
        int bb = idx / (2*DIN), i = idx % (2*DIN);
        float v = (i < DIN) ? g_inpT[(size_t)n*XCOLS + bb*DIN + i]
                            : g_xg1T[(size_t)n*XCOLS + bb*DIN + (i - DIN)];
        Xs[bb][i] = v;
    }
    __syncthreads();
    float bias = 0.f;
#pragma unroll
    for (int e = 0; e < 16; e++) bias += Es[e] * gate_b[e*OG + o];
    float acc[BB];
#pragma unroll
    for (int bb = 0; bb < BB; bb++) acc[bb] = bias;
    const float* Wn = g_Wg + (size_t)n*(2*DIN*OG);
    for (int i = 0; i < 2*DIN; i++) {
        float w = Wn[(size_t)i*OG + o];
#pragma unroll
        for (int bb = 0; bb < BB; bb++) acc[bb] += Xs[bb][i] * w;
    }
#pragma unroll
    for (int bb = 0; bb < BB; bb++) {
        float v = 1.0f / (1.0f + __expf(-acc[bb]));
        if (o < DD) { // z
            float st = state[((size_t)bb*NN + n)*DD + o];
            g_candT[(size_t)n*XCOLS + bb*DIN + 2 + o] = v * st;
        } else {      // r
            g_r[((size_t)bb*NN + n)*DD + (o - DD)] = v;
        }
    }
}

// ---------------- update apply: hc = tanh(...); h = r*state + (1-r)*hc ----------------
__global__ void k_upd_apply(const float* __restrict__ E, const float* __restrict__ upd_b,
                            const float* __restrict__ state) {
    int n = blockIdx.x;
    int o = threadIdx.x;   // 64 threads
    __shared__ float Xs[BB][2*DIN];
    __shared__ float Es[16];
    if (o < 16) Es[o] = E[(size_t)n*EMB + o];
    for (int idx = o; idx < BB*2*DIN; idx += 64) {
        int bb = idx / (2*DIN), i = idx % (2*DIN);
        Xs[bb][i] = (i < DIN) ? g_candT[(size_t)n*XCOLS + bb*DIN + i]
                              : g_xg2T[(size_t)n*XCOLS + bb*DIN + (i - DIN)];
    }
    __syncthreads();
    float bias = 0.f;
#pragma unroll
    for (int e = 0; e < 16; e++) bias += Es[e] * upd_b[e*OU + o];
    float acc[BB];
#pragma unroll
    for (int bb = 0; bb < BB; bb++) acc[bb] = bias;
    const float* Wn = g_Wu + (size_t)n*(2*DIN*OU);
    for (int i = 0; i < 2*DIN; i++) {
        float w = Wn[(size_t)i*OU + o];
#pragma unroll
        for (int bb = 0; bb < BB; bb++) acc[bb] += Xs[bb][i] * w;
    }
#pragma unroll
    for (int bb = 0; bb < BB; bb++) {
        float hc = tanhf(acc[bb]);
        size_t ix = ((size_t)bb*NN + n)*DD + o;
        float r = g_r[ix];
        g_h[ix] = r * state[ix] + (1.0f - r) * hc;
    }
}

// ---------------- HHT[b] = H[b] @ H[b]^T  (K=64) ----------------
__global__ void k_hht() {
    int b = blockIdx.z;
    const float* H = g_h + (size_t)b*NN*DD;
    float* C = g_hht + (size_t)b*NN*NN;
    __shared__ __align__(16) float As[32][132];
    __shared__ __align__(16) float Bs[32][132];
    int tid = threadIdx.x;
    int n0 = blockIdx.y*128;   // rows
    int m0 = blockIdx.x*128;   // cols
    int row0 = (tid/16)*8, col0 = (tid%16)*8;
    float acc[8][8] = {};
    int lr = tid >> 1;
    int lh = (tid & 1)*16;
    for (int k0 = 0; k0 < DD; k0 += 32) {
#pragma unroll
        for (int v = 0; v < 4; v++) {
            float4 t = *(const float4*)&H[(size_t)(n0+lr)*DD + k0 + lh + v*4];
            As[lh+v*4+0][lr]=t.x; As[lh+v*4+1][lr]=t.y; As[lh+v*4+2][lr]=t.z; As[lh+v*4+3][lr]=t.w;
            float4 u = *(const float4*)&H[(size_t)(m0+lr)*DD + k0 + lh + v*4];
            Bs[lh+v*4+0][lr]=u.x; Bs[lh+v*4+1][lr]=u.y; Bs[lh+v*4+2][lr]=u.z; Bs[lh+v*4+3][lr]=u.w;
        }
        __syncthreads();
#pragma unroll
        for (int k = 0; k < 32; k++) {
            float av[8], bv[8];
            float4 t;
            t = *(const float4*)&As[k][row0];   av[0]=t.x; av[1]=t.y; av[2]=t.z; av[3]=t.w;
            t = *(const float4*)&As[k][row0+4]; av[4]=t.x; av[5]=t.y; av[6]=t.z; av[7]=t.w;
            t = *(const float4*)&Bs[k][col0];   bv[0]=t.x; bv[1]=t.y; bv[2]=t.z; bv[3]=t.w;
            t = *(const float4*)&Bs[k][col0+4]; bv[4]=t.x; bv[5]=t.y; bv[6]=t.z; bv[7]=t.w;
#pragma unroll
            for (int i = 0; i < 8; i++)
#pragma unroll
                for (int j = 0; j < 8; j++) acc[i][j] += av[i]*bv[j];
        }
        __syncthreads();
    }
#pragma unroll
    for (int i = 0; i < 8; i++) {
        size_t rofs = (size_t)(n0 + row0 + i)*NN + m0 + col0;
        *(float4*)&C[rofs]     = make_float4(acc[i][0], acc[i][1], acc[i][2], acc[i][3]);
        *(float4*)&C[rofs + 4] = make_float4(acc[i][4], acc[i][5], acc[i][6], acc[i][7]);
    }
}

// ---------------- big masked GEMM: deg[b] = (mask(A) * HHT[b]) @ W ----------------
__global__ void k_biggemm(const float* __restrict__ W, int sign) {
    int b = blockIdx.z;
    const float* HH = g_hht + (size_t)b*NN*NN;
    float* C = g_deg + (size_t)b*NN*NN;
    __shared__ __align__(16) float As[16][128];
    __shared__ __align__(16) float Bs[16][128];
    int tid = threadIdx.x;
    int n0 = blockIdx.x*128;
    int m0 = blockIdx.y*128;
    int row0 = (tid/16)*8, col0 = (tid%16)*8;
    float acc[8][8] = {};
    int arow = tid >> 1, acs = (tid & 1)*8;
    int brow = tid >> 4, bcs = (tid & 15)*8;
    for (int k0 = 0; k0 < NN; k0 += 16) {
        size_t aofs = (size_t)(m0+arow)*NN + k0 + acs;
        float4 h0 = *(const float4*)&HH[aofs];
        float4 h1 = *(const float4*)&HH[aofs + 4];
        float4 q0 = *(const float4*)&g_A[aofs];
        float4 q1 = *(const float4*)&g_A[aofs + 4];
        if (sign > 0) {
            h0.x = (q0.x > 0.f) ? h0.x : 0.f;  h0.y = (q0.y > 0.f) ? h0.y : 0.f;
            h0.z = (q0.z > 0.f) ? h0.z : 0.f;  h0.w = (q0.w > 0.f) ? h0.w : 0.f;
            h1.x = (q1.x > 0.f) ? h1.x : 0.f;  h1.y = (q1.y > 0.f) ? h1.y : 0.f;
            h1.z = (q1.z > 0.f) ? h1.z : 0.f;  h1.w = (q1.w > 0.f) ? h1.w : 0.f;
        } else {
            h0.x = (q0.x < 0.f) ? h0.x : 0.f;  h0.y = (q0.y < 0.f) ? h0.y : 0.f;
            h0.z = (q0.z < 0.f) ? h0.z : 0.f;  h0.w = (q0.w < 0.f) ? h0.w : 0.f;
            h1.x = (q1.x < 0.f) ? h1.x : 0.f;  h1.y = (q1.y < 0.f) ? h1.y : 0.f;
            h1.z = (q1.z < 0.f) ? h1.z : 0.f;  h1.w = (q1.w < 0.f) ? h1.w : 0.f;
        }
        As[acs+0][arow]=h0.x; As[acs+1][arow]=h0.y; As[acs+2][arow]=h0.z; As[acs+3][arow]=h0.w;
        As[acs+4][arow]=h1.x; As[acs+5][arow]=h1.y; As[acs+6][arow]=h1.z; As[acs+7][arow]=h1.w;
        float4 b0 = *(const float4*)&W[(size_t)(k0+brow)*NN + n0 + bcs];
        float4 b1 = *(const float4*)&W[(size_t)(k0+brow)*NN + n0 + bcs + 4];
        *(float4*)&Bs[brow][bcs]   = b0;
        *(float4*)&Bs[brow][bcs+4] = b1;
        __syncthreads();
#pragma unroll
        for (int k = 0; k < 16; k++) {
            float av[8], bv[8];
            float4 t;
            t = *(const float4*)&As[k][row0];   av[0]=t.x; av[1]=t.y; av[2]=t.z; av[3]=t.w;
            t = *(const float4*)&As[k][row0+4]; av[4]=t.x; av[5]=t.y; av[6]=t.z; av[7]=t.w;
            t = *(const float4*)&Bs[k][col0];   bv[0]=t.x; bv[1]=t.y; bv[2]=t.z; bv[3]=t.w;
            t = *(const float4*)&Bs[k][col0+4]; bv[4]=t.x; bv[5]=t.y; bv[6]=t.z; bv[7]=t.w;
#pragma unroll
            for (int i = 0; i < 8; i++)
#pragma unroll
                for (int j = 0; j < 8; j++) acc[i][j] += av[i]*bv[j];
        }
        __syncthreads();
    }
#pragma unroll
    for (int i = 0; i < 8; i++) {
        size_t rofs = (size_t)(m0 + row0 + i)*NN + n0 + col0;
        *(float4*)&C[rofs]     = make_float4(acc[i][0], acc[i][1], acc[i][2], acc[i][3]);
        *(float4*)&C[rofs + 4] = make_float4(acc[i][4], acc[i][5], acc[i][6], acc[i][7]);
    }
}

// ---------------- out = (mode0: 0.8h) + alpha * deg @ h  (M=2048,K=2048,Nc=64) ----------------
__global__ void k_deg_h(float* __restrict__ out, float alpha, int mode) {
    int b = blockIdx.z;
    const float* A  = g_deg + (size_t)b*NN*NN;
    const float* Hh = g_h   + (size_t)b*NN*DD;
    __shared__ __align__(16) float As[16][128];
    __shared__ __align__(16) float Bs[16][64];
    int tid = threadIdx.x;
    int m0 = blockIdx.y*128;
    int row0 = (tid/16)*8, col0 = (tid%16)*4;
    float acc[8][4] = {};
    int arow = tid >> 1, acs = (tid & 1)*8;
    int brow = tid >> 4, bcs = (tid & 15)*4;
    for (int k0 = 0; k0 < NN; k0 += 16) {
        float4 a0 = *(const float4*)&A[(size_t)(m0+arow)*NN + k0 + acs];
        float4 a1 = *(const float4*)&A[(size_t)(m0+arow)*NN + k0 + acs + 4];
        As[acs+0][arow]=a0.x; As[acs+1][arow]=a0.y; As[acs+2][arow]=a0.z; As[acs+3][arow]=a0.w;
        As[acs+4][arow]=a1.x; As[acs+5][arow]=a1.y; As[acs+6][arow]=a1.z; As[acs+7][arow]=a1.w;
        float4 bv = *(const float4*)&Hh[(size_t)(k0+brow)*DD + bcs];
        *(float4*)&Bs[brow][bcs] = bv;
        __syncthreads();
#pragma unroll
        for (int k = 0; k < 16; k++) {
            float av[8], bw[4];
            float4 t;
            t = *(const float4*)&As[k][row0];   av[0]=t.x; av[1]=t.y; av[2]=t.z; av[3]=t.w;
            t = *(const float4*)&As[k][row0+4]; av[4]=t.x; av[5]=t.y; av[6]=t.z; av[7]=t.w;
            t = *(const float4*)&Bs[k][col0];   bw[0]=t.x; bw[1]=t.y; bw[2]=t.z; bw[3]=t.w;
#pragma unroll
            for (int i = 0; i < 8; i++)
#pragma unroll
                for (int j = 0; j < 4; j++) acc[i][j] += av[i]*bw[j];
        }
        __syncthreads();
    }
#pragma unroll
    for (int i = 0; i < 8; i++)
#pragma unroll
        for (int j = 0; j < 4; j++) {
            size_t ix = ((size_t)b*NN + m0 + row0 + i)*DD + col0 + j;
            float v = alpha * acc[i][j];
            if (mode == 0) v += 0.8f * g_h[ix];
            else           v += out[ix];
            out[ix] = v;
        }
}

// ---------------- launch ----------------
extern "C" void kernel_launch(void* const* d_in, const int* in_sizes, int n_in,
                              void* d_out, int out_size) {
    const float* x       = (const float*)d_in[0];
    const float* state   = (const float*)d_in[1];
    const float* E       = (const float*)d_in[2];
    const float* Wc      = (const float*)d_in[3];
    const float* Wd      = (const float*)d_in[4];
    const float* gate_w  = (const float*)d_in[5];
    const float* gate_b  = (const float*)d_in[6];
    const float* upd_w   = (const float*)d_in[7];
    const float* upd_b   = (const float*)d_in[8];
    float* out = (float*)d_out;

    // adjacency + supports
    k_embed_outer<<<dim3(128,128), dim3(16,16)>>>(E);
    k_rowsoftmax<<<dim3(NN,1), 256>>>(0);

    // per-node weights
    k_mkW<<<dim3((2*DIN*OG)/256, NN), 256>>>(E, gate_w, 2*DIN*OG, 0);  // 66 x 2048
    k_mkW<<<dim3((2*DIN*OU)/256, NN), 256>>>(E, upd_w,  2*DIN*OU, 1);  // 33 x 2048

    // gate path
    k_concat<<<(NN*XCOLS + 255)/256, 256>>>(x, state);
    k_sgemm_SX<<<dim3((XCOLS + 127)/128, NN/128), 256>>>(0);
    k_gate_apply<<<NN, 128>>>(E, gate_b, state);

    // update path
    k_sgemm_SX<<<dim3((XCOLS + 127)/128, NN/128), 256>>>(1);
    k_upd_apply<<<NN, 64>>>(E, upd_b, state);

    // H H^T
    k_hht<<<dim3(16,16,16), 256>>>();

    // connect branch
    k_biggemm<<<dim3(16,16,16), 256>>>(Wc, +1);
    k_rowsoftmax<<<dim3(NN,16), 256>>>(1);
    k_deg_h<<<dim3(1,16,16), 256>>>(out, -0.1f, 0);

    // disconnect branch
    k_biggemm<<<dim3(16,16,16), 256>>>(Wd, -1);
    k_rowsoftmax<<<dim3(NN,16), 256>>>(1);
    k_deg_h<<<dim3(1,16,16), 256>>>(out, +0.1f, 1);
}

// round 3
// speedup vs baseline: 2.4290x; 2.4290x over previous
#include <cuda_runtime.h>
#include <cuda_fp16.h>
#include <cstdint>
#include <math.h>

// ---------------- problem constants ----------------
#define NN   2048      // nodes
#define BB   16        // batch
#define DD   64        // dim_out
#define DIN  66        // dim_in + dim_out
#define EMB  16        // embed dim
#define OG   128       // gate out (2*D)
#define OU   64        // update out
#define XCOLS (BB*DIN) // 1056

// ---------------- device scratch ----------------
__device__ float g_A   [(size_t)NN*NN];
__device__ float g_S   [(size_t)NN*NN];
__device__ unsigned char g_mask[(size_t)NN*NN];        // 1: A>0, 2: A<0, 0: A==0
__device__ float g_Wg  [(size_t)NN*2*DIN*OG];
__device__ float g_Wu  [(size_t)NN*2*DIN*OU];
__device__ float g_inpT[(size_t)NN*XCOLS];
__device__ float g_xg1T[(size_t)NN*XCOLS];
__device__ float g_candT[(size_t)NN*XCOLS];
__device__ float g_xg2T[(size_t)NN*XCOLS];
__device__ float g_r   [(size_t)BB*NN*DD];
__device__ float g_h   [(size_t)BB*NN*DD];
// pre-masked HHT in fp16 hi/lo, per branch
__device__ __half g_ac_hi[(size_t)BB*NN*NN];
__device__ __half g_ac_lo[(size_t)BB*NN*NN];
__device__ __half g_ad_hi[(size_t)BB*NN*NN];
__device__ __half g_ad_lo[(size_t)BB*NN*NN];
// transposed fp16 weights Wt[n][k]
__device__ __half g_wc[(size_t)NN*NN];
__device__ __half g_wd[(size_t)NN*NN];
__device__ float g_deg [(size_t)BB*NN*NN];             // GEMM out -> softmax in place

// ---------------- A = E E^T + sign mask ----------------
__global__ void k_embed_outer(const float* __restrict__ E) {
    __shared__ float En[16][17], Em[16][17];
    int tx = threadIdx.x, ty = threadIdx.y;
    En[ty][tx] = E[((size_t)blockIdx.y*16 + ty)*EMB + tx];
    Em[ty][tx] = E[((size_t)blockIdx.x*16 + ty)*EMB + tx];
    __syncthreads();
    float s = 0.f;
#pragma unroll
    for (int e = 0; e < 16; e++) s += En[ty][e] * Em[tx][e];
    size_t idx = ((size_t)blockIdx.y*16 + ty)*NN + blockIdx.x*16 + tx;
    g_A[idx] = s;
    g_mask[idx] = (s > 0.f) ? 1 : ((s < 0.f) ? 2 : 0);
}

// ---------------- row softmax ----------------
__global__ void k_rowsoftmax(int mode) {
    __shared__ float buf[NN];
    __shared__ float red[256];
    int row = blockIdx.x;
    int tid = threadIdx.x;
    const float* in;
    float* out;
    if (mode == 0) { in = g_A + (size_t)row*NN; out = g_S + (size_t)row*NN; }
    else {
        size_t off = ((size_t)blockIdx.y*NN + row)*NN;
        in = g_deg + off; out = g_deg + off;
    }
    float mx = -1e30f;
    for (int i = tid; i < NN; i += 256) {
        float v = in[i];
        if (mode == 0) v = v > 0.f ? v : 0.f;
        buf[i] = v;
        mx = fmaxf(mx, v);
    }
    red[tid] = mx; __syncthreads();
    for (int s = 128; s > 0; s >>= 1) {
        if (tid < s) red[tid] = fmaxf(red[tid], red[tid+s]);
        __syncthreads();
    }
    mx = red[0];
    __syncthreads();
    float sum = 0.f;
    for (int i = tid; i < NN; i += 256) {
        float e = __expf(buf[i] - mx);
        buf[i] = e;
        sum += e;
    }
    red[tid] = sum; __syncthreads();
    for (int s = 128; s > 0; s >>= 1) {
        if (tid < s) red[tid] += red[tid+s];
        __syncthreads();
    }
    float inv = 1.0f / red[0];
    for (int i = tid; i < NN; i += 256) out[i] = buf[i] * inv;
}

// ---------------- per-node weights ----------------
__global__ void k_mkW(const float* __restrict__ E, const float* __restrict__ pool,
                      int per_e, int which) {
    __shared__ float Es[16];
    int n = blockIdx.y;
    int j = blockIdx.x*256 + threadIdx.x;
    if (threadIdx.x < 16) Es[threadIdx.x] = E[(size_t)n*EMB + threadIdx.x];
    __syncthreads();
    float s = 0.f;
#pragma unroll
    for (int e = 0; e < 16; e++) s += Es[e] * pool[(size_t)e*per_e + j];
    float* W = (which == 0) ? g_Wg : g_Wu;
    W[(size_t)n*per_e + j] = s;
}

// ---------------- concat ----------------
__global__ void k_concat(const float* __restrict__ x, const float* __restrict__ state) {
    int idx = blockIdx.x*256 + threadIdx.x;
    if (idx >= NN*XCOLS) return;
    int n = idx / XCOLS;
    int rem = idx % XCOLS;
    int b = rem / DIN, i = rem % DIN;
    float v;
    if (i < 2) v = x[((size_t)b*NN + n)*2 + i];
    else       v = state[((size_t)b*NN + n)*DD + (i-2)];
    g_inpT[idx] = v;
    if (i < 2) g_candT[idx] = v;
}

// ---------------- xg = S @ X ----------------
__global__ void k_sgemm_SX(int which) {
    const float* Bm = (which == 0) ? g_inpT : g_candT;
    float*       C  = (which == 0) ? g_xg1T : g_xg2T;
    __shared__ __align__(16) float As[16][128];
    __shared__ __align__(16) float Bs[16][128];
    int tid = threadIdx.x;
    int n0 = blockIdx.x*128;
    int m0 = blockIdx.y*128;
    int row0 = (tid/16)*8, col0 = (tid%16)*8;
    float acc[8][8] = {};
    int arow = tid >> 1, acs = (tid & 1)*8;
    int brow = tid >> 4, bcs = (tid & 15)*8;
    for (int k0 = 0; k0 < NN; k0 += 16) {
        float4 a0 = *(const float4*)&g_S[(size_t)(m0+arow)*NN + k0 + acs];
        float4 a1 = *(const float4*)&g_S[(size_t)(m0+arow)*NN + k0 + acs + 4];
        As[acs+0][arow]=a0.x; As[acs+1][arow]=a0.y; As[acs+2][arow]=a0.z; As[acs+3][arow]=a0.w;
        As[acs+4][arow]=a1.x; As[acs+5][arow]=a1.y; As[acs+6][arow]=a1.z; As[acs+7][arow]=a1.w;
        float4 b0 = make_float4(0,0,0,0), b1 = make_float4(0,0,0,0);
        int bc = n0 + bcs;
        if (bc < XCOLS) {
            b0 = *(const float4*)&Bm[(size_t)(k0+brow)*XCOLS + bc];
            b1 = *(const float4*)&Bm[(size_t)(k0+brow)*XCOLS + bc + 4];
        }
        *(float4*)&Bs[brow][bcs]   = b0;
        *(float4*)&Bs[brow][bcs+4] = b1;
        __syncthreads();
#pragma unroll
        for (int k = 0; k < 16; k++) {
            float av[8], bv[8];
            float4 t;
            t = *(const float4*)&As[k][row0];   av[0]=t.x; av[1]=t.y; av[2]=t.z; av[3]=t.w;
            t = *(const float4*)&As[k][row0+4]; av[4]=t.x; av[5]=t.y; av[6]=t.z; av[7]=t.w;
            t = *(const float4*)&Bs[k][col0];   bv[0]=t.x; bv[1]=t.y; bv[2]=t.z; bv[3]=t.w;
            t = *(const float4*)&Bs[k][col0+4]; bv[4]=t.x; bv[5]=t.y; bv[6]=t.z; bv[7]=t.w;
#pragma unroll
            for (int i = 0; i < 8; i++)
#pragma unroll
                for (int j = 0; j < 8; j++) acc[i][j] += av[i]*bv[j];
        }
        __syncthreads();
    }
#pragma unroll
    for (int i = 0; i < 8; i++) {
        int row = m0 + row0 + i;
#pragma unroll
        for (int j = 0; j < 8; j++) {
            int col = n0 + col0 + j;
            if (col < XCOLS) C[(size_t)row*XCOLS + col] = acc[i][j];
        }
    }
}

// ---------------- gate apply ----------------
__global__ void k_gate_apply(const float* __restrict__ E, const float* __restrict__ gate_b,
                             const float* __restrict__ state) {
    int n = blockIdx.x;
    int o = threadIdx.x;
    __shared__ float Xs[BB][2*DIN];
    __shared__ float Es[16];
    if (o < 16) Es[o] = E[(size_t)n*EMB + o];
    for (int idx = o; idx < BB*2*DIN; idx += 128) {
        int bb = idx / (2*DIN), i = idx % (2*DIN);
        float v = (i < DIN) ? g_inpT[(size_t)n*XCOLS + bb*DIN + i]
                            : g_xg1T[(size_t)n*XCOLS + bb*DIN + (i - DIN)];
        Xs[bb][i] = v;
    }
    __syncthreads();
    float bias = 0.f;
#pragma unroll
    for (int e = 0; e < 16; e++) bias += Es[e] * gate_b[e*OG + o];
    float acc[BB];
#pragma unroll
    for (int bb = 0; bb < BB; bb++) acc[bb] = bias;
    const float* Wn = g_Wg + (size_t)n*(2*DIN*OG);
    for (int i = 0; i < 2*DIN; i++) {
        float w = Wn[(size_t)i*OG + o];
#pragma unroll
        for (int bb = 0; bb < BB; bb++) acc[bb] += Xs[bb][i] * w;
    }
#pragma unroll
    for (int bb = 0; bb < BB; bb++) {
        float v = 1.0f / (1.0f + __expf(-acc[bb]));
        if (o < DD) {
            float st = state[((size_t)bb*NN + n)*DD + o];
            g_candT[(size_t)n*XCOLS + bb*DIN + 2 + o] = v * st;
        } else {
            g_r[((size_t)bb*NN + n)*DD + (o - DD)] = v;
        }
    }
}

// ---------------- update apply ----------------
__global__ void k_upd_apply(const float* __restrict__ E, const float* __restrict__ upd_b,
                            const float* __restrict__ state) {
    int n = blockIdx.x;
    int o = threadIdx.x;
    __shared__ float Xs[BB][2*DIN];
    __shared__ float Es[16];
    if (o < 16) Es[o] = E[(size_t)n*EMB + o];
    for (int idx = o; idx < BB*2*DIN; idx += 64) {
        int bb = idx / (2*DIN), i = idx % (2*DIN);
        Xs[bb][i] = (i < DIN) ? g_candT[(size_t)n*XCOLS + bb*DIN + i]
                              : g_xg2T[(size_t)n*XCOLS + bb*DIN + (i - DIN)];
    }
    __syncthreads();
    float bias = 0.f;
#pragma unroll
    for (int e = 0; e < 16; e++) bias += Es[e] * upd_b[e*OU + o];
    float acc[BB];
#pragma unroll
    for (int bb = 0; bb < BB; bb++) acc[bb] = bias;
    const float* Wn = g_Wu + (size_t)n*(2*DIN*OU);
    for (int i = 0; i < 2*DIN; i++) {
        float w = Wn[(size_t)i*OU + o];
#pragma unroll
        for (int bb = 0; bb < BB; bb++) acc[bb] += Xs[bb][i] * w;
    }
#pragma unroll
    for (int bb = 0; bb < BB; bb++) {
        float hc = tanhf(acc[bb]);
        size_t ix = ((size_t)bb*NN + n)*DD + o;
        float r = g_r[ix];
        g_h[ix] = r * state[ix] + (1.0f - r) * hc;
    }
}

// ---------------- HHT[b] = H[b] @ H[b]^T -> masked fp16 hi/lo per branch ----------------
__global__ void k_hht() {
    int b = blockIdx.z;
    const float* H = g_h + (size_t)b*NN*DD;
    const size_t bofs = (size_t)b*NN*NN;
    __shared__ __align__(16) float As[32][132];
    __shared__ __align__(16) float Bs[32][132];
    int tid = threadIdx.x;
    int n0 = blockIdx.y*128;
    int m0 = blockIdx.x*128;
    int row0 = (tid/16)*8, col0 = (tid%16)*8;
    float acc[8][8] = {};
    int lr = tid >> 1;
    int lh = (tid & 1)*16;
    for (int k0 = 0; k0 < DD; k0 += 32) {
#pragma unroll
        for (int v = 0; v < 4; v++) {
            float4 t = *(const float4*)&H[(size_t)(n0+lr)*DD + k0 + lh + v*4];
            As[lh+v*4+0][lr]=t.x; As[lh+v*4+1][lr]=t.y; As[lh+v*4+2][lr]=t.z; As[lh+v*4+3][lr]=t.w;
            float4 u = *(const float4*)&H[(size_t)(m0+lr)*DD + k0 + lh + v*4];
            Bs[lh+v*4+0][lr]=u.x; Bs[lh+v*4+1][lr]=u.y; Bs[lh+v*4+2][lr]=u.z; Bs[lh+v*4+3][lr]=u.w;
        }
        __syncthreads();
#pragma unroll
        for (int k = 0; k < 32; k++) {
            float av[8], bv[8];
            float4 t;
            t = *(const float4*)&As[k][row0];   av[0]=t.x; av[1]=t.y; av[2]=t.z; av[3]=t.w;
            t = *(const float4*)&As[k][row0+4]; av[4]=t.x; av[5]=t.y; av[6]=t.z; av[7]=t.w;
            t = *(const float4*)&Bs[k][col0];   bv[0]=t.x; bv[1]=t.y; bv[2]=t.z; bv[3]=t.w;
            t = *(const float4*)&Bs[k][col0+4]; bv[4]=t.x; bv[5]=t.y; bv[6]=t.z; bv[7]=t.w;
#pragma unroll
            for (int i = 0; i < 8; i++)
#pragma unroll
                for (int j = 0; j < 8; j++) acc[i][j] += av[i]*bv[j];
        }
        __syncthreads();
    }
#pragma unroll
    for (int i = 0; i < 8; i++) {
        size_t rofs = (size_t)(n0 + row0 + i)*NN + m0 + col0;
        unsigned char mk[8];
        *(uint2*)mk = *(const uint2*)&g_mask[rofs];
        __half ch[8], cl[8], dh[8], dl[8];
#pragma unroll
        for (int j = 0; j < 8; j++) {
            float v = acc[i][j];
            float vc = (mk[j] == 1) ? v : 0.f;
            float vd = (mk[j] == 2) ? v : 0.f;
            __half h1 = __float2half_rn(vc);
            ch[j] = h1; cl[j] = __float2half_rn(vc - __half2float(h1));
            __half h2 = __float2half_rn(vd);
            dh[j] = h2; dl[j] = __float2half_rn(vd - __half2float(h2));
        }
        *(uint4*)&g_ac_hi[bofs + rofs] = *(uint4*)ch;
        *(uint4*)&g_ac_lo[bofs + rofs] = *(uint4*)cl;
        *(uint4*)&g_ad_hi[bofs + rofs] = *(uint4*)dh;
        *(uint4*)&g_ad_lo[bofs + rofs] = *(uint4*)dl;
    }
}

// ---------------- W (fp32 [k][n]) -> transposed fp16 Wt[n][k] ----------------
__global__ void k_convW(const float* __restrict__ W, int which) {
    __shared__ float t[32][33];
    int tx = threadIdx.x, ty = threadIdx.y;    // 32 x 8
    int bx = blockIdx.x*32, by = blockIdx.y*32;
    for (int j = 0; j < 32; j += 8)
        t[ty+j][tx] = W[(size_t)(by+ty+j)*NN + bx+tx];
    __syncthreads();
    __half* Wt = (which == 0) ? g_wc : g_wd;
    for (int j = 0; j < 32; j += 8) {
        float v = t[tx][ty+j];                 // = W[by+tx][bx+ty+j]
        Wt[(size_t)(bx+ty+j)*NN + by+tx] = __float2half_rn(v);
    }
}

// ---------------- big masked GEMM on HMMA (mma.sync m16n8k16 fp16) ----------------
// deg[b][m][n] = sum_k Amask[b][m][k] * W[k][n],  A = Ahi + Alo (fp16 hi/lo split)
// CTA tile 128x128, K-chunk 16, 3-stage cp.async pipeline, 8 warps (2m x 4n).
#define TKC 16
#define NSTG 3
__global__ void __launch_bounds__(256, 2) k_biggemm_mma(int branch) {
    __shared__ __align__(16) __half sAh[NSTG][128*TKC];
    __shared__ __align__(16) __half sAl[NSTG][128*TKC];
    __shared__ __align__(16) __half sW [NSTG][128*TKC];

    const int tid = threadIdx.x;
    const int b  = blockIdx.z;
    const int m0 = blockIdx.y*128;
    const int n0 = blockIdx.x*128;

    const __half* Ahi = ((branch == 0) ? g_ac_hi : g_ad_hi) + (size_t)b*NN*NN;
    const __half* Alo = ((branch == 0) ? g_ac_lo : g_ad_lo) + (size_t)b*NN*NN;
    const __half* Wt  = (branch == 0) ? g_wc : g_wd;

    const int lrow = tid >> 1;        // 0..127
    const int lhalf = tid & 1;        // 16B half of a 32B row
    const size_t aRow = (size_t)(m0 + lrow)*NN + lhalf*8;
    const size_t wRow = (size_t)(n0 + lrow)*NN + lhalf*8;
    const uint32_t sOff = (uint32_t)(lrow*TKC + lhalf*8);

    auto issue = [&](int c, int s) {
        uint32_t dA = (uint32_t)__cvta_generic_to_shared(&sAh[s][sOff]);
        uint32_t dL = (uint32_t)__cvta_generic_to_shared(&sAl[s][sOff]);
        uint32_t dW = (uint32_t)__cvta_generic_to_shared(&sW [s][sOff]);
        const __half* gA = Ahi + aRow + (size_t)c*TKC;
        const __half* gL = Alo + aRow + (size_t)c*TKC;
        const __half* gW = Wt  + wRow + (size_t)c*TKC;
        asm volatile("cp.async.cg.shared.global [%0], [%1], 16;" :: "r"(dA), "l"(gA));
        asm volatile("cp.async.cg.shared.global [%0], [%1], 16;" :: "r"(dL), "l"(gL));
        asm volatile("cp.async.cg.shared.global [%0], [%1], 16;" :: "r"(dW), "l"(gW));
        asm volatile("cp.async.commit_group;");
    };

    const int lane = tid & 31, wid = tid >> 5;
    const int wm = (wid & 1)*64;      // warp row base
    const int wn = (wid >> 1)*32;     // warp col base
    const int qr = lane >> 2;         // 0..7
    const int qk = (lane & 3)*2;      // 0,2,4,6

    float acc[4][4][4];
#pragma unroll
    for (int i = 0; i < 4; i++)
#pragma unroll
        for (int j = 0; j < 4; j++)
#pragma unroll
            for (int q = 0; q < 4; q++) acc[i][j][q] = 0.f;

    issue(0, 0);
    issue(1, 1);

    const int NC = NN/TKC;  // 128
    for (int c = 0; c < NC; c++) {
        int s = c % NSTG;
        if (c + 2 < NC) asm volatile("cp.async.wait_group 1;" ::: "memory");
        else            asm volatile("cp.async.wait_group 0;" ::: "memory");
        __syncthreads();
        if (c + 2 < NC) issue(c + 2, (c + 2) % NSTG);

        // B fragments (shared by both passes)
        uint32_t bf[4][2];
#pragma unroll
        for (int j = 0; j < 4; j++) {
            const __half* bp = &sW[s][(wn + j*8 + qr)*TKC + qk];
            bf[j][0] = *(const uint32_t*)bp;
            bf[j][1] = *(const uint32_t*)(bp + 8);
        }
        // pass over hi then lo A tiles
#pragma unroll
        for (int p = 0; p < 2; p++) {
            const __half* At = p ? &sAl[s][0] : &sAh[s][0];
            uint32_t af[4][4];
#pragma unroll
            for (int i = 0; i < 4; i++) {
                const __half* ap = At + (wm + i*16 + qr)*TKC + qk;
                af[i][0] = *(const uint32_t*)ap;
                af[i][1] = *(const uint32_t*)(ap + 8*TKC);
                af[i][2] = *(const uint32_t*)(ap + 8);
                af[i][3] = *(const uint32_t*)(ap + 8*TKC + 8);
            }
#pragma unroll
            for (int i = 0; i < 4; i++)
#pragma unroll
                for (int j = 0; j < 4; j++) {
                    asm volatile(
                        "mma.sync.aligned.m16n8k16.row.col.f32.f16.f16.f32 "
                        "{%0,%1,%2,%3}, {%4,%5,%6,%7}, {%8,%9}, {%0,%1,%2,%3};"
                        : "+f"(acc[i][j][0]), "+f"(acc[i][j][1]),
                          "+f"(acc[i][j][2]), "+f"(acc[i][j][3])
                        : "r"(af[i][0]), "r"(af[i][1]), "r"(af[i][2]), "r"(af[i][3]),
                          "r"(bf[j][0]), "r"(bf[j][1]));
                }
        }
        __syncthreads();
    }

    // epilogue
    float* C = g_deg + (size_t)b*NN*NN;
#pragma unroll
    for (int i = 0; i < 4; i++) {
        int r0 = m0 + wm + i*16 + qr;
#pragma unroll
        for (int j = 0; j < 4; j++) {
            int cc = n0 + wn + j*8 + qk;
            *(float2*)&C[(size_t)r0*NN + cc]     = make_float2(acc[i][j][0], acc[i][j][1]);
            *(float2*)&C[(size_t)(r0+8)*NN + cc] = make_float2(acc[i][j][2], acc[i][j][3]);
        }
    }
}

// ---------------- out = (mode0: 0.8h) + alpha * deg @ h ----------------
__global__ void k_deg_h(float* __restrict__ out, float alpha, int mode) {
    int b = blockIdx.z;
    const float* A  = g_deg + (size_t)b*NN*NN;
    const float* Hh = g_h   + (size_t)b*NN*DD;
    __shared__ __align__(16) float As[16][128];
    __shared__ __align__(16) float Bs[16][64];
    int tid = threadIdx.x;
    int m0 = blockIdx.y*128;
    int row0 = (tid/16)*8, col0 = (tid%16)*4;
    float acc[8][4] = {};
    int arow = tid >> 1, acs = (tid & 1)*8;
    int brow = tid >> 4, bcs = (tid & 15)*4;
    for (int k0 = 0; k0 < NN; k0 += 16) {
        float4 a0 = *(const float4*)&A[(size_t)(m0+arow)*NN + k0 + acs];
        float4 a1 = *(const float4*)&A[(size_t)(m0+arow)*NN + k0 + acs + 4];
        As[acs+0][arow]=a0.x; As[acs+1][arow]=a0.y; As[acs+2][arow]=a0.z; As[acs+3][arow]=a0.w;
        As[acs+4][arow]=a1.x; As[acs+5][arow]=a1.y; As[acs+6][arow]=a1.z; As[acs+7][arow]=a1.w;
        float4 bv = *(const float4*)&Hh[(size_t)(k0+brow)*DD + bcs];
        *(float4*)&Bs[brow][bcs] = bv;
        __syncthreads();
#pragma unroll
        for (int k = 0; k < 16; k++) {
            float av[8], bw[4];
            float4 t;
            t = *(const float4*)&As[k][row0];   av[0]=t.x; av[1]=t.y; av[2]=t.z; av[3]=t.w;
            t = *(const float4*)&As[k][row0+4]; av[4]=t.x; av[5]=t.y; av[6]=t.z; av[7]=t.w;
            t = *(const float4*)&Bs[k][col0];   bw[0]=t.x; bw[1]=t.y; bw[2]=t.z; bw[3]=t.w;
#pragma unroll
            for (int i = 0; i < 8; i++)
#pragma unroll
                for (int j = 0; j < 4; j++) acc[i][j] += av[i]*bw[j];
        }
        __syncthreads();
    }
#pragma unroll
    for (int i = 0; i < 8; i++)
#pragma unroll
        for (int j = 0; j < 4; j++) {
            size_t ix = ((size_t)b*NN + m0 + row0 + i)*DD + col0 + j;
            float v = alpha * acc[i][j];
            if (mode == 0) v += 0.8f * g_h[ix];
            else           v += out[ix];
            out[ix] = v;
        }
}

// ---------------- launch ----------------
extern "C" void kernel_launch(void* const* d_in, const int* in_sizes, int n_in,
                              void* d_out, int out_size) {
    const float* x       = (const float*)d_in[0];
    const float* state   = (const float*)d_in[1];
    const float* E       = (const float*)d_in[2];
    const float* Wc      = (const float*)d_in[3];
    const float* Wd      = (const float*)d_in[4];
    const float* gate_w  = (const float*)d_in[5];
    const float* gate_b  = (const float*)d_in[6];
    const float* upd_w   = (const float*)d_in[7];
    const float* upd_b   = (const float*)d_in[8];
    float* out = (float*)d_out;

    // adjacency + supports + sign mask
    k_embed_outer<<<dim3(128,128), dim3(16,16)>>>(E);
    k_rowsoftmax<<<dim3(NN,1), 256>>>(0);

    // per-node weights
    k_mkW<<<dim3((2*DIN*OG)/256, NN), 256>>>(E, gate_w, 2*DIN*OG, 0);
    k_mkW<<<dim3((2*DIN*OU)/256, NN), 256>>>(E, upd_w,  2*DIN*OU, 1);

    // weight transposes to fp16 (independent; early)
    k_convW<<<dim3(64,64), dim3(32,8)>>>(Wc, 0);
    k_convW<<<dim3(64,64), dim3(32,8)>>>(Wd, 1);

    // gate path
    k_concat<<<(NN*XCOLS + 255)/256, 256>>>(x, state);
    k_sgemm_SX<<<dim3((XCOLS + 127)/128, NN/128), 256>>>(0);
    k_gate_apply<<<NN, 128>>>(E, gate_b, state);

    // update path
    k_sgemm_SX<<<dim3((XCOLS + 127)/128, NN/128), 256>>>(1);
    k_upd_apply<<<NN, 64>>>(E, upd_b, state);

    // H H^T -> masked fp16 hi/lo (both branches)
    k_hht<<<dim3(16,16,16), 256>>>();

    // connect branch
    k_biggemm_mma<<<dim3(16,16,16), 256>>>(0);
    k_rowsoftmax<<<dim3(NN,16), 256>>>(1);
    k_deg_h<<<dim3(1,16,16), 256>>>(out, -0.1f, 0);

    // disconnect branch
    k_biggemm_mma<<<dim3(16,16,16), 256>>>(1);
    k_rowsoftmax<<<dim3(NN,16), 256>>>(1);
    k_deg_h<<<dim3(1,16,16), 256>>>(out, +0.1f, 1);
}

// round 4
// speedup vs baseline: 3.1558x; 1.2992x over previous
#include <cuda_runtime.h>
#include <cuda_fp16.h>
#include <cstdint>
#include <math.h>

// ---------------- problem constants ----------------
#define NN   2048      // nodes
#define BB   16        // batch
#define DD   64        // dim_out
#define DIN  66        // dim_in + dim_out
#define EMB  16        // embed dim
#define OG   128       // gate out (2*D)
#define OU   64        // update out
#define XCOLS (BB*DIN) // 1056

// ---------------- device scratch ----------------
__device__ float g_A   [(size_t)NN*NN];
__device__ float g_S   [(size_t)NN*NN];
__device__ unsigned char g_mask[(size_t)NN*NN];        // 1: A>0, 2: A<0, 0: A==0
__device__ float g_Wg  [(size_t)NN*2*DIN*OG];
__device__ float g_Wu  [(size_t)NN*2*DIN*OU];
__device__ float g_inpT[(size_t)NN*XCOLS];
__device__ float g_xg1T[(size_t)NN*XCOLS];
__device__ float g_candT[(size_t)NN*XCOLS];
__device__ float g_xg2T[(size_t)NN*XCOLS];
__device__ float g_r   [(size_t)BB*NN*DD];
__device__ float g_h   [(size_t)BB*NN*DD];
// pre-masked HHT in fp16 (hi only), per branch
__device__ __half g_ac[(size_t)BB*NN*NN];
__device__ __half g_ad[(size_t)BB*NN*NN];
// transposed fp16 weights Wt[n][k]
__device__ __half g_wc[(size_t)NN*NN];
__device__ __half g_wd[(size_t)NN*NN];
__device__ float g_deg [(size_t)BB*NN*NN];             // GEMM out -> softmax in place

// ---------------- A = E E^T + sign mask ----------------
__global__ void k_embed_outer(const float* __restrict__ E) {
    __shared__ float En[16][17], Em[16][17];
    int tx = threadIdx.x, ty = threadIdx.y;
    En[ty][tx] = E[((size_t)blockIdx.y*16 + ty)*EMB + tx];
    Em[ty][tx] = E[((size_t)blockIdx.x*16 + ty)*EMB + tx];
    __syncthreads();
    float s = 0.f;
#pragma unroll
    for (int e = 0; e < 16; e++) s += En[ty][e] * Em[tx][e];
    size_t idx = ((size_t)blockIdx.y*16 + ty)*NN + blockIdx.x*16 + tx;
    g_A[idx] = s;
    g_mask[idx] = (s > 0.f) ? 1 : ((s < 0.f) ? 2 : 0);
}

// ---------------- row softmax ----------------
__global__ void k_rowsoftmax(int mode) {
    __shared__ float buf[NN];
    __shared__ float red[256];
    int row = blockIdx.x;
    int tid = threadIdx.x;
    const float* in;
    float* out;
    if (mode == 0) { in = g_A + (size_t)row*NN; out = g_S + (size_t)row*NN; }
    else {
        size_t off = ((size_t)blockIdx.y*NN + row)*NN;
        in = g_deg + off; out = g_deg + off;
    }
    float mx = -1e30f;
    for (int i = tid; i < NN; i += 256) {
        float v = in[i];
        if (mode == 0) v = v > 0.f ? v : 0.f;
        buf[i] = v;
        mx = fmaxf(mx, v);
    }
    red[tid] = mx; __syncthreads();
    for (int s = 128; s > 0; s >>= 1) {
        if (tid < s) red[tid] = fmaxf(red[tid], red[tid+s]);
        __syncthreads();
    }
    mx = red[0];
    __syncthreads();
    float sum = 0.f;
    for (int i = tid; i < NN; i += 256) {
        float e = __expf(buf[i] - mx);
        buf[i] = e;
        sum += e;
    }
    red[tid] = sum; __syncthreads();
    for (int s = 128; s > 0; s >>= 1) {
        if (tid < s) red[tid] += red[tid+s];
        __syncthreads();
    }
    float inv = 1.0f / red[0];
    for (int i = tid; i < NN; i += 256) out[i] = buf[i] * inv;
}

// ---------------- per-node weights ----------------
__global__ void k_mkW(const float* __restrict__ E, const float* __restrict__ pool,
                      int per_e, int which) {
    __shared__ float Es[16];
    int n = blockIdx.y;
    int j = blockIdx.x*256 + threadIdx.x;
    if (threadIdx.x < 16) Es[threadIdx.x] = E[(size_t)n*EMB + threadIdx.x];
    __syncthreads();
    float s = 0.f;
#pragma unroll
    for (int e = 0; e < 16; e++) s += Es[e] * pool[(size_t)e*per_e + j];
    float* W = (which == 0) ? g_Wg : g_Wu;
    W[(size_t)n*per_e + j] = s;
}

// ---------------- concat ----------------
__global__ void k_concat(const float* __restrict__ x, const float* __restrict__ state) {
    int idx = blockIdx.x*256 + threadIdx.x;
    if (idx >= NN*XCOLS) return;
    int n = idx / XCOLS;
    int rem = idx % XCOLS;
    int b = rem / DIN, i = rem % DIN;
    float v;
    if (i < 2) v = x[((size_t)b*NN + n)*2 + i];
    else       v = state[((size_t)b*NN + n)*DD + (i-2)];
    g_inpT[idx] = v;
    if (i < 2) g_candT[idx] = v;
}

// ---------------- xg = S @ X ----------------
__global__ void k_sgemm_SX(int which) {
    const float* Bm = (which == 0) ? g_inpT : g_candT;
    float*       C  = (which == 0) ? g_xg1T : g_xg2T;
    __shared__ __align__(16) float As[16][128];
    __shared__ __align__(16) float Bs[16][128];
    int tid = threadIdx.x;
    int n0 = blockIdx.x*128;
    int m0 = blockIdx.y*128;
    int row0 = (tid/16)*8, col0 = (tid%16)*8;
    float acc[8][8] = {};
    int arow = tid >> 1, acs = (tid & 1)*8;
    int brow = tid >> 4, bcs = (tid & 15)*8;
    for (int k0 = 0; k0 < NN; k0 += 16) {
        float4 a0 = *(const float4*)&g_S[(size_t)(m0+arow)*NN + k0 + acs];
        float4 a1 = *(const float4*)&g_S[(size_t)(m0+arow)*NN + k0 + acs + 4];
        As[acs+0][arow]=a0.x; As[acs+1][arow]=a0.y; As[acs+2][arow]=a0.z; As[acs+3][arow]=a0.w;
        As[acs+4][arow]=a1.x; As[acs+5][arow]=a1.y; As[acs+6][arow]=a1.z; As[acs+7][arow]=a1.w;
        float4 b0 = make_float4(0,0,0,0), b1 = make_float4(0,0,0,0);
        int bc = n0 + bcs;
        if (bc < XCOLS) {
            b0 = *(const float4*)&Bm[(size_t)(k0+brow)*XCOLS + bc];
            b1 = *(const float4*)&Bm[(size_t)(k0+brow)*XCOLS + bc + 4];
        }
        *(float4*)&Bs[brow][bcs]   = b0;
        *(float4*)&Bs[brow][bcs+4] = b1;
        __syncthreads();
#pragma unroll
        for (int k = 0; k < 16; k++) {
            float av[8], bv[8];
            float4 t;
            t = *(const float4*)&As[k][row0];   av[0]=t.x; av[1]=t.y; av[2]=t.z; av[3]=t.w;
            t = *(const float4*)&As[k][row0+4]; av[4]=t.x; av[5]=t.y; av[6]=t.z; av[7]=t.w;
            t = *(const float4*)&Bs[k][col0];   bv[0]=t.x; bv[1]=t.y; bv[2]=t.z; bv[3]=t.w;
            t = *(const float4*)&Bs[k][col0+4]; bv[4]=t.x; bv[5]=t.y; bv[6]=t.z; bv[7]=t.w;
#pragma unroll
            for (int i = 0; i < 8; i++)
#pragma unroll
                for (int j = 0; j < 8; j++) acc[i][j] += av[i]*bv[j];
        }
        __syncthreads();
    }
#pragma unroll
    for (int i = 0; i < 8; i++) {
        int row = m0 + row0 + i;
#pragma unroll
        for (int j = 0; j < 8; j++) {
            int col = n0 + col0 + j;
            if (col < XCOLS) C[(size_t)row*XCOLS + col] = acc[i][j];
        }
    }
}

// ---------------- gate apply ----------------
__global__ void k_gate_apply(const float* __restrict__ E, const float* __restrict__ gate_b,
                             const float* __restrict__ state) {
    int n = blockIdx.x;
    int o = threadIdx.x;
    __shared__ float Xs[BB][2*DIN];
    __shared__ float Es[16];
    if (o < 16) Es[o] = E[(size_t)n*EMB + o];
    for (int idx = o; idx < BB*2*DIN; idx += 128) {
        int bb = idx / (2*DIN), i = idx % (2*DIN);
        float v = (i < DIN) ? g_inpT[(size_t)n*XCOLS + bb*DIN + i]
                            : g_xg1T[(size_t)n*XCOLS + bb*DIN + (i - DIN)];
        Xs[bb][i] = v;
    }
    __syncthreads();
    float bias = 0.f;
#pragma unroll
    for (int e = 0; e < 16; e++) bias += Es[e] * gate_b[e*OG + o];
    float acc[BB];
#pragma unroll
    for (int bb = 0; bb < BB; bb++) acc[bb] = bias;
    const float* Wn = g_Wg + (size_t)n*(2*DIN*OG);
    for (int i = 0; i < 2*DIN; i++) {
        float w = Wn[(size_t)i*OG + o];
#pragma unroll
        for (int bb = 0; bb < BB; bb++) acc[bb] += Xs[bb][i] * w;
    }
#pragma unroll
    for (int bb = 0; bb < BB; bb++) {
        float v = 1.0f / (1.0f + __expf(-acc[bb]));
        if (o < DD) {
            float st = state[((size_t)bb*NN + n)*DD + o];
            g_candT[(size_t)n*XCOLS + bb*DIN + 2 + o] = v * st;
        } else {
            g_r[((size_t)bb*NN + n)*DD + (o - DD)] = v;
        }
    }
}

// ---------------- update apply ----------------
__global__ void k_upd_apply(const float* __restrict__ E, const float* __restrict__ upd_b,
                            const float* __restrict__ state) {
    int n = blockIdx.x;
    int o = threadIdx.x;
    __shared__ float Xs[BB][2*DIN];
    __shared__ float Es[16];
    if (o < 16) Es[o] = E[(size_t)n*EMB + o];
    for (int idx = o; idx < BB*2*DIN; idx += 64) {
        int bb = idx / (2*DIN), i = idx % (2*DIN);
        Xs[bb][i] = (i < DIN) ? g_candT[(size_t)n*XCOLS + bb*DIN + i]
                              : g_xg2T[(size_t)n*XCOLS + bb*DIN + (i - DIN)];
    }
    __syncthreads();
    float bias = 0.f;
#pragma unroll
    for (int e = 0; e < 16; e++) bias += Es[e] * upd_b[e*OU + o];
    float acc[BB];
#pragma unroll
    for (int bb = 0; bb < BB; bb++) acc[bb] = bias;
    const float* Wn = g_Wu + (size_t)n*(2*DIN*OU);
    for (int i = 0; i < 2*DIN; i++) {
        float w = Wn[(size_t)i*OU + o];
#pragma unroll
        for (int bb = 0; bb < BB; bb++) acc[bb] += Xs[bb][i] * w;
    }
#pragma unroll
    for (int bb = 0; bb < BB; bb++) {
        float hc = tanhf(acc[bb]);
        size_t ix = ((size_t)bb*NN + n)*DD + o;
        float r = g_r[ix];
        g_h[ix] = r * state[ix] + (1.0f - r) * hc;
    }
}

// ---------------- HHT[b] = H[b] @ H[b]^T -> masked fp16 per branch ----------------
__global__ void k_hht() {
    int b = blockIdx.z;
    const float* H = g_h + (size_t)b*NN*DD;
    const size_t bofs = (size_t)b*NN*NN;
    __shared__ __align__(16) float As[32][132];
    __shared__ __align__(16) float Bs[32][132];
    int tid = threadIdx.x;
    int n0 = blockIdx.y*128;
    int m0 = blockIdx.x*128;
    int row0 = (tid/16)*8, col0 = (tid%16)*8;
    float acc[8][8] = {};
    int lr = tid >> 1;
    int lh = (tid & 1)*16;
    for (int k0 = 0; k0 < DD; k0 += 32) {
#pragma unroll
        for (int v = 0; v < 4; v++) {
            float4 t = *(const float4*)&H[(size_t)(n0+lr)*DD + k0 + lh + v*4];
            As[lh+v*4+0][lr]=t.x; As[lh+v*4+1][lr]=t.y; As[lh+v*4+2][lr]=t.z; As[lh+v*4+3][lr]=t.w;
            float4 u = *(const float4*)&H[(size_t)(m0+lr)*DD + k0 + lh + v*4];
            Bs[lh+v*4+0][lr]=u.x; Bs[lh+v*4+1][lr]=u.y; Bs[lh+v*4+2][lr]=u.z; Bs[lh+v*4+3][lr]=u.w;
        }
        __syncthreads();
#pragma unroll
        for (int k = 0; k < 32; k++) {
            float av[8], bv[8];
            float4 t;
            t = *(const float4*)&As[k][row0];   av[0]=t.x; av[1]=t.y; av[2]=t.z; av[3]=t.w;
            t = *(const float4*)&As[k][row0+4]; av[4]=t.x; av[5]=t.y; av[6]=t.z; av[7]=t.w;
            t = *(const float4*)&Bs[k][col0];   bv[0]=t.x; bv[1]=t.y; bv[2]=t.z; bv[3]=t.w;
            t = *(const float4*)&Bs[k][col0+4]; bv[4]=t.x; bv[5]=t.y; bv[6]=t.z; bv[7]=t.w;
#pragma unroll
            for (int i = 0; i < 8; i++)
#pragma unroll
                for (int j = 0; j < 8; j++) acc[i][j] += av[i]*bv[j];
        }
        __syncthreads();
    }
#pragma unroll
    for (int i = 0; i < 8; i++) {
        size_t rofs = (size_t)(n0 + row0 + i)*NN + m0 + col0;
        unsigned char mk[8];
        *(uint2*)mk = *(const uint2*)&g_mask[rofs];
        __half ch[8], dh[8];
#pragma unroll
        for (int j = 0; j < 8; j++) {
            float v = acc[i][j];
            ch[j] = __float2half_rn((mk[j] == 1) ? v : 0.f);
            dh[j] = __float2half_rn((mk[j] == 2) ? v : 0.f);
        }
        *(uint4*)&g_ac[bofs + rofs] = *(uint4*)ch;
        *(uint4*)&g_ad[bofs + rofs] = *(uint4*)dh;
    }
}

// ---------------- W (fp32 [k][n]) -> transposed fp16 Wt[n][k] ----------------
__global__ void k_convW(const float* __restrict__ W, int which) {
    __shared__ float t[32][33];
    int tx = threadIdx.x, ty = threadIdx.y;    // 32 x 8
    int bx = blockIdx.x*32, by = blockIdx.y*32;
    for (int j = 0; j < 32; j += 8)
        t[ty+j][tx] = W[(size_t)(by+ty+j)*NN + bx+tx];
    __syncthreads();
    __half* Wt = (which == 0) ? g_wc : g_wd;
    for (int j = 0; j < 32; j += 8) {
        float v = t[tx][ty+j];                 // = W[by+tx][bx+ty+j]
        Wt[(size_t)(bx+ty+j)*NN + by+tx] = __float2half_rn(v);
    }
}

// ---------------- big masked GEMM on HMMA (mma.sync m16n8k16 fp16) ----------------
// deg[b][m][n] = sum_k Amask[b][m][k] * W[k][n]  (A fp16, W fp16, fp32 accum)
// CTA tile 128x128, K-chunk 16, 4-stage cp.async pipeline, 8 warps (2m x 4n).
#define TKC 16
#define NSTG 4
__global__ void __launch_bounds__(256, 2) k_biggemm_mma(int branch) {
    __shared__ __align__(16) __half sA[NSTG][128*TKC];
    __shared__ __align__(16) __half sW[NSTG][128*TKC];

    const int tid = threadIdx.x;
    const int b  = blockIdx.z;
    const int m0 = blockIdx.y*128;
    const int n0 = blockIdx.x*128;

    const __half* Am = ((branch == 0) ? g_ac : g_ad) + (size_t)b*NN*NN;
    const __half* Wt = (branch == 0) ? g_wc : g_wd;

    const int lrow = tid >> 1;        // 0..127
    const int lhalf = tid & 1;        // 16B half of a 32B row
    const size_t aRow = (size_t)(m0 + lrow)*NN + lhalf*8;
    const size_t wRow = (size_t)(n0 + lrow)*NN + lhalf*8;
    const uint32_t sOff = (uint32_t)(lrow*TKC + lhalf*8);

    auto issue = [&](int c, int s) {
        uint32_t dA = (uint32_t)__cvta_generic_to_shared(&sA[s][sOff]);
        uint32_t dW = (uint32_t)__cvta_generic_to_shared(&sW[s][sOff]);
        const __half* gA = Am + aRow + (size_t)c*TKC;
        const __half* gW = Wt + wRow + (size_t)c*TKC;
        asm volatile("cp.async.cg.shared.global [%0], [%1], 16;" :: "r"(dA), "l"(gA));
        asm volatile("cp.async.cg.shared.global [%0], [%1], 16;" :: "r"(dW), "l"(gW));
        asm volatile("cp.async.commit_group;");
    };

    const int lane = tid & 31, wid = tid >> 5;
    const int wm = (wid & 1)*64;      // warp row base
    const int wn = (wid >> 1)*32;     // warp col base
    const int qr = lane >> 2;         // 0..7
    const int qk = (lane & 3)*2;      // 0,2,4,6

    float acc[4][4][4];
#pragma unroll
    for (int i = 0; i < 4; i++)
#pragma unroll
        for (int j = 0; j < 4; j++)
#pragma unroll
            for (int q = 0; q < 4; q++) acc[i][j][q] = 0.f;

    issue(0, 0);
    issue(1, 1);
    issue(2, 2);

    const int NC = NN/TKC;  // 128
    for (int c = 0; c < NC; c++) {
        int s = c % NSTG;
        if (c < NC-3)      asm volatile("cp.async.wait_group 2;" ::: "memory");
        else if (c == NC-3) asm volatile("cp.async.wait_group 2;" ::: "memory");
        else if (c == NC-2) asm volatile("cp.async.wait_group 1;" ::: "memory");
        else               asm volatile("cp.async.wait_group 0;" ::: "memory");
        __syncthreads();
        if (c + 3 < NC) issue(c + 3, (c + 3) % NSTG);

        // B fragments
        uint32_t bf[4][2];
#pragma unroll
        for (int j = 0; j < 4; j++) {
            const __half* bp = &sW[s][(wn + j*8 + qr)*TKC + qk];
            bf[j][0] = *(const uint32_t*)bp;
            bf[j][1] = *(const uint32_t*)(bp + 8);
        }
        // A fragments
        uint32_t af[4][4];
#pragma unroll
        for (int i = 0; i < 4; i++) {
            const __half* ap = &sA[s][(wm + i*16 + qr)*TKC + qk];
            af[i][0] = *(const uint32_t*)ap;
            af[i][1] = *(const uint32_t*)(ap + 8*TKC);
            af[i][2] = *(const uint32_t*)(ap + 8);
            af[i][3] = *(const uint32_t*)(ap + 8*TKC + 8);
        }
#pragma unroll
        for (int i = 0; i < 4; i++)
#pragma unroll
            for (int j = 0; j < 4; j++) {
                asm volatile(
                    "mma.sync.aligned.m16n8k16.row.col.f32.f16.f16.f32 "
                    "{%0,%1,%2,%3}, {%4,%5,%6,%7}, {%8,%9}, {%0,%1,%2,%3};"
                    : "+f"(acc[i][j][0]), "+f"(acc[i][j][1]),
                      "+f"(acc[i][j][2]), "+f"(acc[i][j][3])
                    : "r"(af[i][0]), "r"(af[i][1]), "r"(af[i][2]), "r"(af[i][3]),
                      "r"(bf[j][0]), "r"(bf[j][1]));
            }
        __syncthreads();
    }

    // epilogue
    float* C = g_deg + (size_t)b*NN*NN;
#pragma unroll
    for (int i = 0; i < 4; i++) {
        int r0 = m0 + wm + i*16 + qr;
#pragma unroll
        for (int j = 0; j < 4; j++) {
            int cc = n0 + wn + j*8 + qk;
            *(float2*)&C[(size_t)r0*NN + cc]     = make_float2(acc[i][j][0], acc[i][j][1]);
            *(float2*)&C[(size_t)(r0+8)*NN + cc] = make_float2(acc[i][j][2], acc[i][j][3]);
        }
    }
}

// ---------------- out = (mode0: 0.8h) + alpha * deg @ h ----------------
__global__ void k_deg_h(float* __restrict__ out, float alpha, int mode) {
    int b = blockIdx.z;
    const float* A  = g_deg + (size_t)b*NN*NN;
    const float* Hh = g_h   + (size_t)b*NN*DD;
    __shared__ __align__(16) float As[16][128];
    __shared__ __align__(16) float Bs[16][64];
    int tid = threadIdx.x;
    int m0 = blockIdx.y*128;
    int row0 = (tid/16)*8, col0 = (tid%16)*4;
    float acc[8][4] = {};
    int arow = tid >> 1, acs = (tid & 1)*8;
    int brow = tid >> 4, bcs = (tid & 15)*4;
    for (int k0 = 0; k0 < NN; k0 += 16) {
        float4 a0 = *(const float4*)&A[(size_t)(m0+arow)*NN + k0 + acs];
        float4 a1 = *(const float4*)&A[(size_t)(m0+arow)*NN + k0 + acs + 4];
        As[acs+0][arow]=a0.x; As[acs+1][arow]=a0.y; As[acs+2][arow]=a0.z; As[acs+3][arow]=a0.w;
        As[acs+4][arow]=a1.x; As[acs+5][arow]=a1.y; As[acs+6][arow]=a1.z; As[acs+7][arow]=a1.w;
        float4 bv = *(const float4*)&Hh[(size_t)(k0+brow)*DD + bcs];
        *(float4*)&Bs[brow][bcs] = bv;
        __syncthreads();
#pragma unroll
        for (int k = 0; k < 16; k++) {
            float av[8], bw[4];
            float4 t;
            t = *(const float4*)&As[k][row0];   av[0]=t.x; av[1]=t.y; av[2]=t.z; av[3]=t.w;
            t = *(const float4*)&As[k][row0+4]; av[4]=t.x; av[5]=t.y; av[6]=t.z; av[7]=t.w;
            t = *(const float4*)&Bs[k][col0];   bw[0]=t.x; bw[1]=t.y; bw[2]=t.z; bw[3]=t.w;
#pragma unroll
            for (int i = 0; i < 8; i++)
#pragma unroll
                for (int j = 0; j < 4; j++) acc[i][j] += av[i]*bw[j];
        }
        __syncthreads();
    }
#pragma unroll
    for (int i = 0; i < 8; i++)
#pragma unroll
        for (int j = 0; j < 4; j++) {
            size_t ix = ((size_t)b*NN + m0 + row0 + i)*DD + col0 + j;
            float v = alpha * acc[i][j];
            if (mode == 0) v += 0.8f * g_h[ix];
            else           v += out[ix];
            out[ix] = v;
        }
}

// ---------------- launch ----------------
extern "C" void kernel_launch(void* const* d_in, const int* in_sizes, int n_in,
                              void* d_out, int out_size) {
    const float* x       = (const float*)d_in[0];
    const float* state   = (const float*)d_in[1];
    const float* E       = (const float*)d_in[2];
    const float* Wc      = (const float*)d_in[3];
    const float* Wd      = (const float*)d_in[4];
    const float* gate_w  = (const float*)d_in[5];
    const float* gate_b  = (const float*)d_in[6];
    const float* upd_w   = (const float*)d_in[7];
    const float* upd_b   = (const float*)d_in[8];
    float* out = (float*)d_out;

    // adjacency + supports + sign mask
    k_embed_outer<<<dim3(128,128), dim3(16,16)>>>(E);
    k_rowsoftmax<<<dim3(NN,1), 256>>>(0);

    // per-node weights
    k_mkW<<<dim3((2*DIN*OG)/256, NN), 256>>>(E, gate_w, 2*DIN*OG, 0);
    k_mkW<<<dim3((2*DIN*OU)/256, NN), 256>>>(E, upd_w,  2*DIN*OU, 1);

    // weight transposes to fp16 (independent; early)
    k_convW<<<dim3(64,64), dim3(32,8)>>>(Wc, 0);
    k_convW<<<dim3(64,64), dim3(32,8)>>>(Wd, 1);

    // gate path
    k_concat<<<(NN*XCOLS + 255)/256, 256>>>(x, state);
    k_sgemm_SX<<<dim3((XCOLS + 127)/128, NN/128), 256>>>(0);
    k_gate_apply<<<NN, 128>>>(E, gate_b, state);

    // update path
    k_sgemm_SX<<<dim3((XCOLS + 127)/128, NN/128), 256>>>(1);
    k_upd_apply<<<NN, 64>>>(E, upd_b, state);

    // H H^T -> masked fp16 (both branches)
    k_hht<<<dim3(16,16,16), 256>>>();

    // connect branch
    k_biggemm_mma<<<dim3(16,16,16), 256>>>(0);
    k_rowsoftmax<<<dim3(NN,16), 256>>>(1);
    k_deg_h<<<dim3(1,16,16), 256>>>(out, -0.1f, 0);

    // disconnect branch
    k_biggemm_mma<<<dim3(16,16,16), 256>>>(1);
    k_rowsoftmax<<<dim3(NN,16), 256>>>(1);
    k_deg_h<<<dim3(1,16,16), 256>>>(out, +0.1f, 1);
}

// round 5
// speedup vs baseline: 4.1116x; 1.3029x over previous
#include <cuda_runtime.h>
#include <cuda_fp16.h>
#include <cstdint>
#include <math.h>

// ---------------- problem constants ----------------
#define NN   2048
#define BB   16
#define DD   64
#define DIN  66
#define EMB  16
#define OG   128
#define OU   64
#define XCOLS (BB*DIN)   // 1056
#define XPAD  1152       // padded cols (9 tiles of 128)

// ---------------- device scratch ----------------
__device__ float g_A   [(size_t)NN*NN];
__device__ unsigned char g_mask[(size_t)NN*NN];        // 1: A>0, 2: A<0, 0: A==0
__device__ float g_Wg  [(size_t)NN*2*DIN*OG];
__device__ float g_Wu  [(size_t)NN*2*DIN*OU];
__device__ float g_inpT[(size_t)NN*XCOLS];             // fp32 [node][b*66+i]
__device__ float g_candT[(size_t)NN*XCOLS];
__device__ float g_xg1T[(size_t)NN*XPAD];              // S @ inp  (padded)
__device__ float g_xg2T[(size_t)NN*XPAD];              // S @ cand (padded)
__device__ float g_r   [(size_t)BB*NN*DD];
__device__ float g_h   [(size_t)BB*NN*DD];
__device__ __half g_h16 [(size_t)BB*NN*DD];            // h in fp16
__device__ __half g_shi[(size_t)NN*NN];                // softmax S hi
__device__ __half g_slo[(size_t)NN*NN];                // softmax S lo
__device__ __half g_xinhi[(size_t)NN*XPAD];            // X=concat(x,state) hi (padded)
__device__ __half g_xinlo[(size_t)NN*XPAD];
__device__ __half g_xcahi[(size_t)NN*XPAD];            // cand hi (padded)
__device__ __half g_xcalo[(size_t)NN*XPAD];
__device__ __half g_ac[(size_t)BB*NN*NN];              // masked HHT (connect)
__device__ __half g_ad[(size_t)BB*NN*NN];              // masked HHT (disconnect)
__device__ __half g_wc[(size_t)NN*NN];                 // Wt[n][k] fp16
__device__ __half g_wd[(size_t)NN*NN];
__device__ float g_deg [(size_t)BB*NN*NN];

// ---------------- asm helpers ----------------
__device__ __forceinline__ uint32_t s2u(const void* p) {
    return (uint32_t)__cvta_generic_to_shared(p);
}
__device__ __forceinline__ void cp16(uint32_t dst, const void* src) {
    asm volatile("cp.async.cg.shared.global [%0], [%1], 16;" :: "r"(dst), "l"(src));
}
__device__ __forceinline__ void cpcommit() { asm volatile("cp.async.commit_group;"); }
__device__ __forceinline__ void ldsm4(uint32_t* r, uint32_t addr) {
    asm volatile("ldmatrix.sync.aligned.m8n8.x4.shared.b16 {%0,%1,%2,%3}, [%4];"
        : "=r"(r[0]), "=r"(r[1]), "=r"(r[2]), "=r"(r[3]) : "r"(addr));
}
__device__ __forceinline__ void ldsm4t(uint32_t* r, uint32_t addr) {
    asm volatile("ldmatrix.sync.aligned.m8n8.x4.trans.shared.b16 {%0,%1,%2,%3}, [%4];"
        : "=r"(r[0]), "=r"(r[1]), "=r"(r[2]), "=r"(r[3]) : "r"(addr));
}
__device__ __forceinline__ void mma16816(float* c, const uint32_t* a, uint32_t b0, uint32_t b1) {
    asm volatile(
        "mma.sync.aligned.m16n8k16.row.col.f32.f16.f16.f32 "
        "{%0,%1,%2,%3}, {%4,%5,%6,%7}, {%8,%9}, {%0,%1,%2,%3};"
        : "+f"(c[0]), "+f"(c[1]), "+f"(c[2]), "+f"(c[3])
        : "r"(a[0]), "r"(a[1]), "r"(a[2]), "r"(a[3]), "r"(b0), "r"(b1));
}

// ---------------- A = E E^T + sign mask ----------------
__global__ void k_embed_outer(const float* __restrict__ E) {
    __shared__ float En[16][17], Em[16][17];
    int tx = threadIdx.x, ty = threadIdx.y;
    En[ty][tx] = E[((size_t)blockIdx.y*16 + ty)*EMB + tx];
    Em[ty][tx] = E[((size_t)blockIdx.x*16 + ty)*EMB + tx];
    __syncthreads();
    float s = 0.f;
#pragma unroll
    for (int e = 0; e < 16; e++) s += En[ty][e] * Em[tx][e];
    size_t idx = ((size_t)blockIdx.y*16 + ty)*NN + blockIdx.x*16 + tx;
    g_A[idx] = s;
    g_mask[idx] = (s > 0.f) ? 1 : ((s < 0.f) ? 2 : 0);
}

// ---------------- row softmax (mode0: relu(A)->S16 hi/lo; mode1: deg in place) ----------------
__global__ void k_rowsoftmax(int mode) {
    __shared__ float buf[NN];
    __shared__ float red[256];
    int row = blockIdx.x;
    int tid = threadIdx.x;
    const float* in;
    float* out = nullptr;
    if (mode == 0) { in = g_A + (size_t)row*NN; }
    else {
        size_t off = ((size_t)blockIdx.y*NN + row)*NN;
        in = g_deg + off; out = g_deg + off;
    }
    float mx = -1e30f;
    for (int i = tid; i < NN; i += 256) {
        float v = in[i];
        if (mode == 0) v = v > 0.f ? v : 0.f;
        buf[i] = v;
        mx = fmaxf(mx, v);
    }
    red[tid] = mx; __syncthreads();
    for (int s = 128; s > 0; s >>= 1) {
        if (tid < s) red[tid] = fmaxf(red[tid], red[tid+s]);
        __syncthreads();
    }
    mx = red[0];
    __syncthreads();
    float sum = 0.f;
    for (int i = tid; i < NN; i += 256) {
        float e = __expf(buf[i] - mx);
        buf[i] = e;
        sum += e;
    }
    red[tid] = sum; __syncthreads();
    for (int s = 128; s > 0; s >>= 1) {
        if (tid < s) red[tid] += red[tid+s];
        __syncthreads();
    }
    float inv = 1.0f / red[0];
    if (mode == 0) {
        for (int i = tid; i < NN; i += 256) {
            float v = buf[i] * inv;
            __half hi = __float2half_rn(v);
            g_shi[(size_t)row*NN + i] = hi;
            g_slo[(size_t)row*NN + i] = __float2half_rn(v - __half2float(hi));
        }
    } else {
        for (int i = tid; i < NN; i += 256) out[i] = buf[i] * inv;
    }
}

// ---------------- per-node weights ----------------
__global__ void k_mkW(const float* __restrict__ E, const float* __restrict__ pool,
                      int per_e, int which) {
    __shared__ float Es[16];
    int n = blockIdx.y;
    int j = blockIdx.x*256 + threadIdx.x;
    if (threadIdx.x < 16) Es[threadIdx.x] = E[(size_t)n*EMB + threadIdx.x];
    __syncthreads();
    float s = 0.f;
#pragma unroll
    for (int e = 0; e < 16; e++) s += Es[e] * pool[(size_t)e*per_e + j];
    float* W = (which == 0) ? g_Wg : g_Wu;
    W[(size_t)n*per_e + j] = s;
}

// ---------------- concat: fp32 + fp16 hi/lo ----------------
__global__ void k_concat(const float* __restrict__ x, const float* __restrict__ state) {
    int idx = blockIdx.x*256 + threadIdx.x;
    if (idx >= NN*XCOLS) return;
    int n = idx / XCOLS;
    int rem = idx % XCOLS;
    int b = rem / DIN, i = rem % DIN;
    float v;
    if (i < 2) v = x[((size_t)b*NN + n)*2 + i];
    else       v = state[((size_t)b*NN + n)*DD + (i-2)];
    g_inpT[idx] = v;
    __half hi = __float2half_rn(v);
    __half lo = __float2half_rn(v - __half2float(hi));
    size_t pidx = (size_t)n*XPAD + rem;
    g_xinhi[pidx] = hi; g_xinlo[pidx] = lo;
    if (i < 2) {
        g_candT[idx] = v;
        g_xcahi[pidx] = hi; g_xcalo[pidx] = lo;
    }
}

// ---------------- xg = S @ X on HMMA (3 passes: Shi*Xhi + Shi*Xlo + Slo*Xhi) ----------------
// A = S [m][k] fp16 row-major; B = X [k][col] fp16 row-major (trans ldmatrix).
#define SX_NSTG 3
__global__ void __launch_bounds__(256, 2) k_sx_mma(int which) {
    extern __shared__ __align__(16) __half dsm[];
    const __half* Bhi = which ? g_xcahi : g_xinhi;
    const __half* Blo = which ? g_xcalo : g_xinlo;
    float* C = which ? g_xg2T : g_xg1T;

    const int tid = threadIdx.x;
    const int n0 = blockIdx.x*128;
    const int m0 = blockIdx.y*128;
    uint32_t su = s2u(dsm);

    // loader mappings
    const int rowA = tid >> 1, ap0 = (tid & 1)*2;   // A: 128 rows x 4 chunks
    const int rowB = tid >> 3, bp0 = (tid & 7)*2;   // B: 32 rows x 16 chunks
    const size_t aRow = (size_t)(m0 + rowA)*NN;
    uint32_t dA[2], dB[2];
#pragma unroll
    for (int t = 0; t < 2; t++) {
        int ch = ap0 + t;
        dA[t] = rowA*64 + ((ch ^ ((rowA>>1)&3)) << 4);
        int cb = bp0 + t;
        dB[t] = 16384 + rowB*256 + ((cb ^ (rowB&7)) << 4);
    }

    auto issue = [&](int c, int s) {
        uint32_t base = su + s*32768;   // stage: Ahi 0 | Alo 8192 | Bhi 16384 | Blo 24576 (bytes)
#pragma unroll
        for (int t = 0; t < 2; t++) {
            int ch = ap0 + t;
            cp16(base + dA[t],        g_shi + aRow + c*32 + ch*8);
            cp16(base + 8192 + dA[t], g_slo + aRow + c*32 + ch*8);
        }
#pragma unroll
        for (int t = 0; t < 2; t++) {
            int cb = bp0 + t;
            size_t bo = (size_t)(c*32 + rowB)*XPAD + n0 + cb*8;
            cp16(base + dB[t],        Bhi + bo);
            cp16(base + 8192 + dB[t], Blo + bo);
        }
        cpcommit();
    };

    const int lane = tid & 31, wid = tid >> 5;
    const int wm = (wid & 1)*64, wn = (wid >> 1)*32;
    const int frow = ((lane>>3)&1)*8 + (lane&7);
    const int fch  = lane >> 4;

    float acc[4][4][4] = {};
    issue(0, 0); issue(1, 1);
    const int NC = NN/32;  // 64
    for (int c = 0; c < NC; c++) {
        int s = c % SX_NSTG;
        if (c + 1 < NC) asm volatile("cp.async.wait_group 1;" ::: "memory");
        else            asm volatile("cp.async.wait_group 0;" ::: "memory");
        __syncthreads();
        if (c + 2 < NC) issue(c + 2, (c + 2) % SX_NSTG);
        uint32_t base = su + s*32768;
#pragma unroll
        for (int ks = 0; ks < 2; ks++) {
            uint32_t af[4][4], bh[2][4], bl[2][4];
            // A hi frags
#pragma unroll
            for (int i = 0; i < 4; i++) {
                int row = wm + i*16 + frow;
                int ch = 2*ks + fch;
                ldsm4(af[i], base + row*64 + ((ch ^ ((row>>1)&3)) << 4));
            }
            // B hi frags (trans)
#pragma unroll
            for (int jj = 0; jj < 2; jj++) {
                int krow = ks*16 + frow;
                int ch = (wn >> 3) + jj*2 + fch;
                ldsm4t(bh[jj], base + 16384 + krow*256 + ((ch ^ (krow&7)) << 4));
            }
            // pass 0: Shi * Xhi
#pragma unroll
            for (int i = 0; i < 4; i++)
#pragma unroll
                for (int j = 0; j < 4; j++) {
                    int jj = j >> 1, sb = (j & 1)*2;
                    mma16816(acc[i][j], af[i], bh[jj][sb], bh[jj][sb+1]);
                }
            // B lo frags, pass 1: Shi * Xlo
#pragma unroll
            for (int jj = 0; jj < 2; jj++) {
                int krow = ks*16 + frow;
                int ch = (wn >> 3) + jj*2 + fch;
                ldsm4t(bl[jj], base + 24576 + krow*256 + ((ch ^ (krow&7)) << 4));
            }
#pragma unroll
            for (int i = 0; i < 4; i++)
#pragma unroll
                for (int j = 0; j < 4; j++) {
                    int jj = j >> 1, sb = (j & 1)*2;
                    mma16816(acc[i][j], af[i], bl[jj][sb], bl[jj][sb+1]);
                }
            // A lo frags (reuse af), pass 2: Slo * Xhi
#pragma unroll
            for (int i = 0; i < 4; i++) {
                int row = wm + i*16 + frow;
                int ch = 2*ks + fch;
                ldsm4(af[i], base + 8192 + row*64 + ((ch ^ ((row>>1)&3)) << 4));
            }
#pragma unroll
            for (int i = 0; i < 4; i++)
#pragma unroll
                for (int j = 0; j < 4; j++) {
                    int jj = j >> 1, sb = (j & 1)*2;
                    mma16816(acc[i][j], af[i], bh[jj][sb], bh[jj][sb+1]);
                }
        }
    }
    // epilogue
    const int r = lane >> 2, cq = (lane & 3)*2;
#pragma unroll
    for (int i = 0; i < 4; i++) {
        int r0 = m0 + wm + i*16 + r;
#pragma unroll
        for (int j = 0; j < 4; j++) {
            int cc = n0 + wn + j*8 + cq;
            *(float2*)&C[(size_t)r0*XPAD + cc]     = make_float2(acc[i][j][0], acc[i][j][1]);
            *(float2*)&C[(size_t)(r0+8)*XPAD + cc] = make_float2(acc[i][j][2], acc[i][j][3]);
        }
    }
}

// ---------------- gate apply ----------------
__global__ void k_gate_apply(const float* __restrict__ E, const float* __restrict__ gate_b,
                             const float* __restrict__ state) {
    int n = blockIdx.x;
    int o = threadIdx.x;
    __shared__ float Xs[BB][2*DIN];
    __shared__ float Es[16];
    if (o < 16) Es[o] = E[(size_t)n*EMB + o];
    for (int idx = o; idx < BB*2*DIN; idx += 128) {
        int bb = idx / (2*DIN), i = idx % (2*DIN);
        float v = (i < DIN) ? g_inpT[(size_t)n*XCOLS + bb*DIN + i]
                            : g_xg1T[(size_t)n*XPAD + bb*DIN + (i - DIN)];
        Xs[bb][i] = v;
    }
    __syncthreads();
    float bias = 0.f;
#pragma unroll
    for (int e = 0; e < 16; e++) bias += Es[e] * gate_b[e*OG + o];
    float acc[BB];
#pragma unroll
    for (int bb = 0; bb < BB; bb++) acc[bb] = bias;
    const float* Wn = g_Wg + (size_t)n*(2*DIN*OG);
    for (int i = 0; i < 2*DIN; i++) {
        float w = Wn[(size_t)i*OG + o];
#pragma unroll
        for (int bb = 0; bb < BB; bb++) acc[bb] += Xs[bb][i] * w;
    }
#pragma unroll
    for (int bb = 0; bb < BB; bb++) {
        float v = 1.0f / (1.0f + __expf(-acc[bb]));
        if (o < DD) { // z
            float st = state[((size_t)bb*NN + n)*DD + o];
            float zs = v * st;
            g_candT[(size_t)n*XCOLS + bb*DIN + 2 + o] = zs;
            __half hi = __float2half_rn(zs);
            size_t pidx = (size_t)n*XPAD + bb*DIN + 2 + o;
            g_xcahi[pidx] = hi;
            g_xcalo[pidx] = __float2half_rn(zs - __half2float(hi));
        } else {      // r
            g_r[((size_t)bb*NN + n)*DD + (o - DD)] = v;
        }
    }
}

// ---------------- update apply: h + h16 ----------------
__global__ void k_upd_apply(const float* __restrict__ E, const float* __restrict__ upd_b,
                            const float* __restrict__ state) {
    int n = blockIdx.x;
    int o = threadIdx.x;
    __shared__ float Xs[BB][2*DIN];
    __shared__ float Es[16];
    if (o < 16) Es[o] = E[(size_t)n*EMB + o];
    for (int idx = o; idx < BB*2*DIN; idx += 64) {
        int bb = idx / (2*DIN), i = idx % (2*DIN);
        Xs[bb][i] = (i < DIN) ? g_candT[(size_t)n*XCOLS + bb*DIN + i]
                              : g_xg2T[(size_t)n*XPAD + bb*DIN + (i - DIN)];
    }
    __syncthreads();
    float bias = 0.f;
#pragma unroll
    for (int e = 0; e < 16; e++) bias += Es[e] * upd_b[e*OU + o];
    float acc[BB];
#pragma unroll
    for (int bb = 0; bb < BB; bb++) acc[bb] = bias;
    const float* Wn = g_Wu + (size_t)n*(2*DIN*OU);
    for (int i = 0; i < 2*DIN; i++) {
        float w = Wn[(size_t)i*OU + o];
#pragma unroll
        for (int bb = 0; bb < BB; bb++) acc[bb] += Xs[bb][i] * w;
    }
#pragma unroll
    for (int bb = 0; bb < BB; bb++) {
        float hc = tanhf(acc[bb]);
        size_t ix = ((size_t)bb*NN + n)*DD + o;
        float r = g_r[ix];
        float hv = r * state[ix] + (1.0f - r) * hc;
        g_h[ix] = hv;
        g_h16[ix] = __float2half_rn(hv);
    }
}

// ---------------- HHT on HMMA: g_ac/g_ad = mask(.) * (h16 @ h16^T) ----------------
__global__ void __launch_bounds__(256, 2) k_hht_mma() {
    __shared__ __align__(16) __half sA[128*64];
    __shared__ __align__(16) __half sB[128*64];
    const int tid = threadIdx.x;
    const int b = blockIdx.z, m0 = blockIdx.y*128, n0 = blockIdx.x*128;
    uint32_t aU = s2u(sA), bU = s2u(sB);

    const int row = tid >> 1, c0 = (tid & 1)*4;
#pragma unroll
    for (int t = 0; t < 4; t++) {
        int ch = c0 + t;
        uint32_t off = row*128 + ((ch ^ (row&7)) << 4);
        cp16(aU + off, g_h16 + ((size_t)b*NN + m0 + row)*64 + ch*8);
        cp16(bU + off, g_h16 + ((size_t)b*NN + n0 + row)*64 + ch*8);
    }
    cpcommit();
    asm volatile("cp.async.wait_group 0;" ::: "memory");
    __syncthreads();

    const int lane = tid & 31, wid = tid >> 5;
    const int wm = (wid & 1)*64, wn = (wid >> 1)*32;
    const int frow = ((lane>>3)&1)*8 + (lane&7);
    const int fch  = lane >> 4;

    float acc[4][4][4] = {};
#pragma unroll
    for (int ks = 0; ks < 4; ks++) {
        uint32_t af[4][4], bf[2][4];
#pragma unroll
        for (int i = 0; i < 4; i++) {
            int rr = wm + i*16 + frow;
            int ch = 2*ks + fch;
            ldsm4(af[i], aU + rr*128 + ((ch ^ (rr&7)) << 4));
        }
#pragma unroll
        for (int jj = 0; jj < 2; jj++) {
            int rr = wn + jj*16 + frow;
            int ch = 2*ks + fch;
            ldsm4(bf[jj], bU + rr*128 + ((ch ^ (rr&7)) << 4));
        }
#pragma unroll
        for (int i = 0; i < 4; i++)
#pragma unroll
            for (int j = 0; j < 4; j++) {
                int jj = j >> 1, sb = j & 1;
                mma16816(acc[i][j], af[i], bf[jj][sb], bf[jj][sb+2]);
            }
    }
    // epilogue: mask + fp16 store (both branches)
    const int r = lane >> 2, cq = (lane & 3)*2;
#pragma unroll
    for (int i = 0; i < 4; i++) {
        int rbase = m0 + wm + i*16 + r;
#pragma unroll
        for (int j = 0; j < 4; j++) {
            int cc = n0 + wn + j*8 + cq;
#pragma unroll
            for (int hh = 0; hh < 2; hh++) {
                int rr = rbase + hh*8;
                uchar2 mk = *(const uchar2*)&g_mask[(size_t)rr*NN + cc];
                float v0 = acc[i][j][hh*2+0], v1 = acc[i][j][hh*2+1];
                __half2 hc = __floats2half2_rn(mk.x == 1 ? v0 : 0.f, mk.y == 1 ? v1 : 0.f);
                __half2 hd = __floats2half2_rn(mk.x == 2 ? v0 : 0.f, mk.y == 2 ? v1 : 0.f);
                *(__half2*)&g_ac[((size_t)b*NN + rr)*NN + cc] = hc;
                *(__half2*)&g_ad[((size_t)b*NN + rr)*NN + cc] = hd;
            }
        }
    }
}

// ---------------- W (fp32 [k][n]) -> transposed fp16 Wt[n][k] ----------------
__global__ void k_convW(const float* __restrict__ W, int which) {
    __shared__ float t[32][33];
    int tx = threadIdx.x, ty = threadIdx.y;    // 32 x 8
    int bx = blockIdx.x*32, by = blockIdx.y*32;
    for (int j = 0; j < 32; j += 8)
        t[ty+j][tx] = W[(size_t)(by+ty+j)*NN + bx+tx];
    __syncthreads();
    __half* Wt = (which == 0) ? g_wc : g_wd;
    for (int j = 0; j < 32; j += 8) {
        float v = t[tx][ty+j];
        Wt[(size_t)(bx+ty+j)*NN + by+tx] = __float2half_rn(v);
    }
}

// ---------------- big GEMM: deg[b] = Amask[b] @ W  (ldmatrix + swizzle, TKC=32) ----------------
#define BG_NSTG 3
__global__ void __launch_bounds__(256, 2) k_biggemm_mma(int branch) {
    __shared__ __align__(16) __half sA[BG_NSTG][4096];
    __shared__ __align__(16) __half sW[BG_NSTG][4096];
    const int tid = threadIdx.x;
    const int b = blockIdx.z, m0 = blockIdx.y*128, n0 = blockIdx.x*128;
    const __half* Am = ((branch == 0) ? g_ac : g_ad) + (size_t)b*NN*NN;
    const __half* Wt = (branch == 0) ? g_wc : g_wd;
    uint32_t aU = s2u(sA), wU = s2u(sW);

    const int lrow = tid >> 1, cp0 = (tid & 1)*2;
    const size_t aRow = (size_t)(m0 + lrow)*NN;
    const size_t wRow = (size_t)(n0 + lrow)*NN;
    uint32_t dOff[2];
#pragma unroll
    for (int t = 0; t < 2; t++) {
        int ch = cp0 + t;
        dOff[t] = lrow*64 + ((ch ^ ((lrow>>1)&3)) << 4);
    }
    auto issue = [&](int c, int s) {
#pragma unroll
        for (int t = 0; t < 2; t++) {
            int ch = cp0 + t;
            cp16(aU + s*8192 + dOff[t], Am + aRow + c*32 + ch*8);
            cp16(wU + s*8192 + dOff[t], Wt + wRow + c*32 + ch*8);
        }
        cpcommit();
    };

    const int lane = tid & 31, wid = tid >> 5;
    const int wm = (wid & 1)*64, wn = (wid >> 1)*32;
    const int frow = ((lane>>3)&1)*8 + (lane&7);
    const int fch  = lane >> 4;

    float acc[4][4][4] = {};
    issue(0, 0); issue(1, 1);
    const int NC = NN/32;  // 64
    for (int c = 0; c < NC; c++) {
        int s = c % BG_NSTG;
        if (c + 1 < NC) asm volatile("cp.async.wait_group 1;" ::: "memory");
        else            asm volatile("cp.async.wait_group 0;" ::: "memory");
        __syncthreads();
        if (c + 2 < NC) issue(c + 2, (c + 2) % BG_NSTG);
        uint32_t aB = aU + s*8192, wB = wU + s*8192;
#pragma unroll
        for (int ks = 0; ks < 2; ks++) {
            uint32_t af[4][4], bf[2][4];
#pragma unroll
            for (int i = 0; i < 4; i++) {
                int row = wm + i*16 + frow;
                int ch = 2*ks + fch;
                ldsm4(af[i], aB + row*64 + ((ch ^ ((row>>1)&3)) << 4));
            }
#pragma unroll
            for (int jj = 0; jj < 2; jj++) {
                int row = wn + jj*16 + frow;
                int ch = 2*ks + fch;
                ldsm4(bf[jj], wB + row*64 + ((ch ^ ((row>>1)&3)) << 4));
            }
#pragma unroll
            for (int i = 0; i < 4; i++)
#pragma unroll
                for (int j = 0; j < 4; j++) {
                    int jj = j >> 1, sb = j & 1;
                    mma16816(acc[i][j], af[i], bf[jj][sb], bf[jj][sb+2]);
                }
        }
    }
    // epilogue
    float* C = g_deg + (size_t)b*NN*NN;
    const int r = lane >> 2, cq = (lane & 3)*2;
#pragma unroll
    for (int i = 0; i < 4; i++) {
        int r0 = m0 + wm + i*16 + r;
#pragma unroll
        for (int j = 0; j < 4; j++) {
            int cc = n0 + wn + j*8 + cq;
            *(float2*)&C[(size_t)r0*NN + cc]     = make_float2(acc[i][j][0], acc[i][j][1]);
            *(float2*)&C[(size_t)(r0+8)*NN + cc] = make_float2(acc[i][j][2], acc[i][j][3]);
        }
    }
}

// ---------------- out = (mode0: 0.8h) + alpha * deg @ h ----------------
__global__ void k_deg_h(float* __restrict__ out, float alpha, int mode) {
    int b = blockIdx.z;
    const float* A  = g_deg + (size_t)b*NN*NN;
    const float* Hh = g_h   + (size_t)b*NN*DD;
    __shared__ __align__(16) float As[16][128];
    __shared__ __align__(16) float Bs[16][64];
    int tid = threadIdx.x;
    int m0 = blockIdx.y*128;
    int row0 = (tid/16)*8, col0 = (tid%16)*4;
    float acc[8][4] = {};
    int arow = tid >> 1, acs = (tid & 1)*8;
    int brow = tid >> 4, bcs = (tid & 15)*4;
    for (int k0 = 0; k0 < NN; k0 += 16) {
        float4 a0 = *(const float4*)&A[(size_t)(m0+arow)*NN + k0 + acs];
        float4 a1 = *(const float4*)&A[(size_t)(m0+arow)*NN + k0 + acs + 4];
        As[acs+0][arow]=a0.x; As[acs+1][arow]=a0.y; As[acs+2][arow]=a0.z; As[acs+3][arow]=a0.w;
        As[acs+4][arow]=a1.x; As[acs+5][arow]=a1.y; As[acs+6][arow]=a1.z; As[acs+7][arow]=a1.w;
        float4 bv = *(const float4*)&Hh[(size_t)(k0+brow)*DD + bcs];
        *(float4*)&Bs[brow][bcs] = bv;
        __syncthreads();
#pragma unroll
        for (int k = 0; k < 16; k++) {
            float av[8], bw[4];
            float4 t;
            t = *(const float4*)&As[k][row0];   av[0]=t.x; av[1]=t.y; av[2]=t.z; av[3]=t.w;
            t = *(const float4*)&As[k][row0+4]; av[4]=t.x; av[5]=t.y; av[6]=t.z; av[7]=t.w;
            t = *(const float4*)&Bs[k][col0];   bw[0]=t.x; bw[1]=t.y; bw[2]=t.z; bw[3]=t.w;
#pragma unroll
            for (int i = 0; i < 8; i++)
#pragma unroll
                for (int j = 0; j < 4; j++) acc[i][j] += av[i]*bw[j];
        }
        __syncthreads();
    }
#pragma unroll
    for (int i = 0; i < 8; i++)
#pragma unroll
        for (int j = 0; j < 4; j++) {
            size_t ix = ((size_t)b*NN + m0 + row0 + i)*DD + col0 + j;
            float v = alpha * acc[i][j];
            if (mode == 0) v += 0.8f * g_h[ix];
            else           v += out[ix];
            out[ix] = v;
        }
}

// ---------------- launch ----------------
extern "C" void kernel_launch(void* const* d_in, const int* in_sizes, int n_in,
                              void* d_out, int out_size) {
    const float* x       = (const float*)d_in[0];
    const float* state   = (const float*)d_in[1];
    const float* E       = (const float*)d_in[2];
    const float* Wc      = (const float*)d_in[3];
    const float* Wd      = (const float*)d_in[4];
    const float* gate_w  = (const float*)d_in[5];
    const float* gate_b  = (const float*)d_in[6];
    const float* upd_w   = (const float*)d_in[7];
    const float* upd_b   = (const float*)d_in[8];
    float* out = (float*)d_out;

    const int SX_SMEM = SX_NSTG * 32768;  // 96KB dynamic
    cudaFuncSetAttribute(k_sx_mma, cudaFuncAttributeMaxDynamicSharedMemorySize, SX_SMEM);

    // adjacency + supports + sign mask
    k_embed_outer<<<dim3(128,128), dim3(16,16)>>>(E);
    k_rowsoftmax<<<dim3(NN,1), 256>>>(0);

    // per-node weights + weight transposes
    k_mkW<<<dim3((2*DIN*OG)/256, NN), 256>>>(E, gate_w, 2*DIN*OG, 0);
    k_mkW<<<dim3((2*DIN*OU)/256, NN), 256>>>(E, upd_w,  2*DIN*OU, 1);
    k_convW<<<dim3(64,64), dim3(32,8)>>>(Wc, 0);
    k_convW<<<dim3(64,64), dim3(32,8)>>>(Wd, 1);

    // gate path
    k_concat<<<(NN*XCOLS + 255)/256, 256>>>(x, state);
    k_sx_mma<<<dim3(XPAD/128, NN/128), 256, SX_SMEM>>>(0);
    k_gate_apply<<<NN, 128>>>(E, gate_b, state);

    // update path
    k_sx_mma<<<dim3(XPAD/128, NN/128), 256, SX_SMEM>>>(1);
    k_upd_apply<<<NN, 64>>>(E, upd_b, state);

    // HHT on tensor cores -> masked fp16 (both branches)
    k_hht_mma<<<dim3(16,16,16), 256>>>();

    // connect branch
    k_biggemm_mma<<<dim3(16,16,16), 256>>>(0);
    k_rowsoftmax<<<dim3(NN,16), 256>>>(1);
    k_deg_h<<<dim3(1,16,16), 256>>>(out, -0.1f, 0);

    // disconnect branch
    k_biggemm_mma<<<dim3(16,16,16), 256>>>(1);
    k_rowsoftmax<<<dim3(NN,16), 256>>>(1);
    k_deg_h<<<dim3(1,16,16), 256>>>(out, +0.1f, 1);
}

// round 6
// speedup vs baseline: 5.0954x; 1.2393x over previous
#include <cuda_runtime.h>
#include <cuda_fp16.h>
#include <cstdint>
#include <math.h>

// ---------------- problem constants ----------------
#define NN   2048
#define BB   16
#define DD   64
#define DIN  66
#define EMB  16
#define OG   128
#define OU   64
#define XCOLS (BB*DIN)   // 1056
#define XPAD  1152       // padded cols (9 tiles of 128)

// ---------------- device scratch ----------------
__device__ float g_A   [(size_t)NN*NN];
__device__ unsigned char g_mask[(size_t)NN*NN];        // 1: A>0, 2: A<0, 0: A==0
__device__ float g_Wg  [(size_t)NN*2*DIN*OG];
__device__ float g_Wu  [(size_t)NN*2*DIN*OU];
__device__ float g_inpT[(size_t)NN*XCOLS];
__device__ float g_candT[(size_t)NN*XCOLS];
__device__ float g_xg1T[(size_t)NN*XPAD];
__device__ float g_xg2T[(size_t)NN*XPAD];
__device__ float g_r   [(size_t)BB*NN*DD];
__device__ float g_h   [(size_t)BB*NN*DD];
__device__ __half g_h16 [(size_t)BB*NN*DD];
__device__ __half g_shi[(size_t)NN*NN];
__device__ __half g_slo[(size_t)NN*NN];
__device__ __half g_xinhi[(size_t)NN*XPAD];
__device__ __half g_xinlo[(size_t)NN*XPAD];
__device__ __half g_xcahi[(size_t)NN*XPAD];
__device__ __half g_xcalo[(size_t)NN*XPAD];
__device__ __half g_ac[(size_t)BB*NN*NN];              // masked HHT (connect)
__device__ __half g_ad[(size_t)BB*NN*NN];              // masked HHT (disconnect)
__device__ __half g_wc[(size_t)NN*NN];
__device__ __half g_wd[(size_t)NN*NN];
__device__ float g_deg [(size_t)BB*NN*NN];             // fp32 logits
__device__ __half g_p16 [(size_t)BB*NN*NN];            // exp(v - rowmax), unnormalized
__device__ float g_invsum[(size_t)BB*NN];              // 1 / rowsum

// ---------------- asm helpers ----------------
__device__ __forceinline__ uint32_t s2u(const void* p) {
    return (uint32_t)__cvta_generic_to_shared(p);
}
__device__ __forceinline__ void cp16(uint32_t dst, const void* src) {
    asm volatile("cp.async.cg.shared.global [%0], [%1], 16;" :: "r"(dst), "l"(src));
}
__device__ __forceinline__ void cpcommit() { asm volatile("cp.async.commit_group;"); }
__device__ __forceinline__ void ldsm4(uint32_t* r, uint32_t addr) {
    asm volatile("ldmatrix.sync.aligned.m8n8.x4.shared.b16 {%0,%1,%2,%3}, [%4];"
        : "=r"(r[0]), "=r"(r[1]), "=r"(r[2]), "=r"(r[3]) : "r"(addr));
}
__device__ __forceinline__ void ldsm4t(uint32_t* r, uint32_t addr) {
    asm volatile("ldmatrix.sync.aligned.m8n8.x4.trans.shared.b16 {%0,%1,%2,%3}, [%4];"
        : "=r"(r[0]), "=r"(r[1]), "=r"(r[2]), "=r"(r[3]) : "r"(addr));
}
__device__ __forceinline__ void mma16816(float* c, const uint32_t* a, uint32_t b0, uint32_t b1) {
    asm volatile(
        "mma.sync.aligned.m16n8k16.row.col.f32.f16.f16.f32 "
        "{%0,%1,%2,%3}, {%4,%5,%6,%7}, {%8,%9}, {%0,%1,%2,%3};"
        : "+f"(c[0]), "+f"(c[1]), "+f"(c[2]), "+f"(c[3])
        : "r"(a[0]), "r"(a[1]), "r"(a[2]), "r"(a[3]), "r"(b0), "r"(b1));
}
// fast exp on the FMA pipe: exp(x) for x <= 0
__device__ __forceinline__ float fexp(float x) {
    float t = fmaxf(x * 1.4426950408889634f, -125.f);
    int   ni = __float2int_rn(t);
    float f  = t - (float)ni;
    float p = 0.00133335581f;
    p = fmaf(p, f, 0.00961812910f);
    p = fmaf(p, f, 0.05550410866f);
    p = fmaf(p, f, 0.24022650696f);
    p = fmaf(p, f, 0.69314718056f);
    p = fmaf(p, f, 1.0f);
    return p * __int_as_float((ni + 127) << 23);
}

// ---------------- A = E E^T + sign mask ----------------
__global__ void k_embed_outer(const float* __restrict__ E) {
    __shared__ float En[16][17], Em[16][17];
    int tx = threadIdx.x, ty = threadIdx.y;
    En[ty][tx] = E[((size_t)blockIdx.y*16 + ty)*EMB + tx];
    Em[ty][tx] = E[((size_t)blockIdx.x*16 + ty)*EMB + tx];
    __syncthreads();
    float s = 0.f;
#pragma unroll
    for (int e = 0; e < 16; e++) s += En[ty][e] * Em[tx][e];
    size_t idx = ((size_t)blockIdx.y*16 + ty)*NN + blockIdx.x*16 + tx;
    g_A[idx] = s;
    g_mask[idx] = (s > 0.f) ? 1 : ((s < 0.f) ? 2 : 0);
}

// ---------------- S softmax: relu(A) -> fp16 hi/lo ----------------
__global__ void k_srowsoftmax() {
    __shared__ float buf[NN];
    __shared__ float red[256];
    int row = blockIdx.x;
    int tid = threadIdx.x;
    const float* in = g_A + (size_t)row*NN;
    float mx = -1e30f;
    for (int i = tid; i < NN; i += 256) {
        float v = in[i];
        v = v > 0.f ? v : 0.f;
        buf[i] = v;
        mx = fmaxf(mx, v);
    }
    red[tid] = mx; __syncthreads();
    for (int s = 128; s > 0; s >>= 1) {
        if (tid < s) red[tid] = fmaxf(red[tid], red[tid+s]);
        __syncthreads();
    }
    mx = red[0];
    __syncthreads();
    float sum = 0.f;
    for (int i = tid; i < NN; i += 256) {
        float e = fexp(buf[i] - mx);
        buf[i] = e;
        sum += e;
    }
    red[tid] = sum; __syncthreads();
    for (int s = 128; s > 0; s >>= 1) {
        if (tid < s) red[tid] += red[tid+s];
        __syncthreads();
    }
    float inv = 1.0f / red[0];
    for (int i = tid; i < NN; i += 256) {
        float v = buf[i] * inv;
        __half hi = __float2half_rn(v);
        g_shi[(size_t)row*NN + i] = hi;
        g_slo[(size_t)row*NN + i] = __float2half_rn(v - __half2float(hi));
    }
}

// ---------------- exp + rowsum: deg (fp32 logits) -> p16 + invsum ----------------
__global__ void __launch_bounds__(256) k_expsum() {
    int row = blockIdx.x, b = blockIdx.y, tid = threadIdx.x;
    const float2* in = (const float2*)(g_deg + ((size_t)b*NN + row)*NN);
    __half2* outp = (__half2*)(g_p16 + ((size_t)b*NN + row)*NN);
    __shared__ float red[256];
    float2 v[4];
    float mx = -1e30f;
#pragma unroll
    for (int t = 0; t < 4; t++) {
        v[t] = in[tid + t*256];
        mx = fmaxf(mx, fmaxf(v[t].x, v[t].y));
    }
    red[tid] = mx; __syncthreads();
    for (int s = 128; s > 0; s >>= 1) {
        if (tid < s) red[tid] = fmaxf(red[tid], red[tid+s]);
        __syncthreads();
    }
    mx = red[0];
    __syncthreads();
    float sum = 0.f;
#pragma unroll
    for (int t = 0; t < 4; t++) {
        v[t].x = fexp(v[t].x - mx);
        v[t].y = fexp(v[t].y - mx);
        sum += v[t].x + v[t].y;
    }
    red[tid] = sum; __syncthreads();
    for (int s = 128; s > 0; s >>= 1) {
        if (tid < s) red[tid] += red[tid+s];
        __syncthreads();
    }
    if (tid == 0) g_invsum[(size_t)b*NN + row] = 1.0f / red[0];
#pragma unroll
    for (int t = 0; t < 4; t++)
        outp[tid + t*256] = __floats2half2_rn(v[t].x, v[t].y);
}

// ---------------- per-node weights ----------------
__global__ void k_mkW(const float* __restrict__ E, const float* __restrict__ pool,
                      int per_e, int which) {
    __shared__ float Es[16];
    int n = blockIdx.y;
    int j = blockIdx.x*256 + threadIdx.x;
    if (threadIdx.x < 16) Es[threadIdx.x] = E[(size_t)n*EMB + threadIdx.x];
    __syncthreads();
    float s = 0.f;
#pragma unroll
    for (int e = 0; e < 16; e++) s += Es[e] * pool[(size_t)e*per_e + j];
    float* W = (which == 0) ? g_Wg : g_Wu;
    W[(size_t)n*per_e + j] = s;
}

// ---------------- concat: fp32 + fp16 hi/lo ----------------
__global__ void k_concat(const float* __restrict__ x, const float* __restrict__ state) {
    int idx = blockIdx.x*256 + threadIdx.x;
    if (idx >= NN*XCOLS) return;
    int n = idx / XCOLS;
    int rem = idx % XCOLS;
    int b = rem / DIN, i = rem % DIN;
    float v;
    if (i < 2) v = x[((size_t)b*NN + n)*2 + i];
    else       v = state[((size_t)b*NN + n)*DD + (i-2)];
    g_inpT[idx] = v;
    __half hi = __float2half_rn(v);
    __half lo = __float2half_rn(v - __half2float(hi));
    size_t pidx = (size_t)n*XPAD + rem;
    g_xinhi[pidx] = hi; g_xinlo[pidx] = lo;
    if (i < 2) {
        g_candT[idx] = v;
        g_xcahi[pidx] = hi; g_xcalo[pidx] = lo;
    }
}

// ---------------- xg = S @ X on HMMA (3 passes) ----------------
#define SX_NSTG 3
__global__ void __launch_bounds__(256, 2) k_sx_mma(int which) {
    extern __shared__ __align__(16) __half dsm[];
    const __half* Bhi = which ? g_xcahi : g_xinhi;
    const __half* Blo = which ? g_xcalo : g_xinlo;
    float* C = which ? g_xg2T : g_xg1T;

    const int tid = threadIdx.x;
    const int n0 = blockIdx.x*128;
    const int m0 = blockIdx.y*128;
    uint32_t su = s2u(dsm);

    const int rowA = tid >> 1, ap0 = (tid & 1)*2;
    const int rowB = tid >> 3, bp0 = (tid & 7)*2;
    const size_t aRow = (size_t)(m0 + rowA)*NN;
    uint32_t dA[2], dB[2];
#pragma unroll
    for (int t = 0; t < 2; t++) {
        int ch = ap0 + t;
        dA[t] = rowA*64 + ((ch ^ ((rowA>>1)&3)) << 4);
        int cb = bp0 + t;
        dB[t] = 16384 + rowB*256 + ((cb ^ (rowB&7)) << 4);
    }

    auto issue = [&](int c, int s) {
        uint32_t base = su + s*32768;
#pragma unroll
        for (int t = 0; t < 2; t++) {
            int ch = ap0 + t;
            cp16(base + dA[t],        g_shi + aRow + c*32 + ch*8);
            cp16(base + 8192 + dA[t], g_slo + aRow + c*32 + ch*8);
        }
#pragma unroll
        for (int t = 0; t < 2; t++) {
            int cb = bp0 + t;
            size_t bo = (size_t)(c*32 + rowB)*XPAD + n0 + cb*8;
            cp16(base + dB[t],        Bhi + bo);
            cp16(base + 8192 + dB[t], Blo + bo);
        }
        cpcommit();
    };

    const int lane = tid & 31, wid = tid >> 5;
    const int wm = (wid & 1)*64, wn = (wid >> 1)*32;
    const int frow = ((lane>>3)&1)*8 + (lane&7);
    const int fch  = lane >> 4;

    float acc[4][4][4] = {};
    issue(0, 0); issue(1, 1);
    const int NC = NN/32;
    for (int c = 0; c < NC; c++) {
        int s = c % SX_NSTG;
        if (c + 1 < NC) asm volatile("cp.async.wait_group 1;" ::: "memory");
        else            asm volatile("cp.async.wait_group 0;" ::: "memory");
        __syncthreads();
        if (c + 2 < NC) issue(c + 2, (c + 2) % SX_NSTG);
        uint32_t base = su + s*32768;
#pragma unroll
        for (int ks = 0; ks < 2; ks++) {
            uint32_t af[4][4], bh[2][4], bl[2][4];
#pragma unroll
            for (int i = 0; i < 4; i++) {
                int row = wm + i*16 + frow;
                int ch = 2*ks + fch;
                ldsm4(af[i], base + row*64 + ((ch ^ ((row>>1)&3)) << 4));
            }
#pragma unroll
            for (int jj = 0; jj < 2; jj++) {
                int krow = ks*16 + frow;
                int ch = (wn >> 3) + jj*2 + fch;
                ldsm4t(bh[jj], base + 16384 + krow*256 + ((ch ^ (krow&7)) << 4));
            }
#pragma unroll
            for (int i = 0; i < 4; i++)
#pragma unroll
                for (int j = 0; j < 4; j++) {
                    int jj = j >> 1, sb = (j & 1)*2;
                    mma16816(acc[i][j], af[i], bh[jj][sb], bh[jj][sb+1]);
                }
#pragma unroll
            for (int jj = 0; jj < 2; jj++) {
                int krow = ks*16 + frow;
                int ch = (wn >> 3) + jj*2 + fch;
                ldsm4t(bl[jj], base + 24576 + krow*256 + ((ch ^ (krow&7)) << 4));
            }
#pragma unroll
            for (int i = 0; i < 4; i++)
#pragma unroll
                for (int j = 0; j < 4; j++) {
                    int jj = j >> 1, sb = (j & 1)*2;
                    mma16816(acc[i][j], af[i], bl[jj][sb], bl[jj][sb+1]);
                }
#pragma unroll
            for (int i = 0; i < 4; i++) {
                int row = wm + i*16 + frow;
                int ch = 2*ks + fch;
                ldsm4(af[i], base + 8192 + row*64 + ((ch ^ ((row>>1)&3)) << 4));
            }
#pragma unroll
            for (int i = 0; i < 4; i++)
#pragma unroll
                for (int j = 0; j < 4; j++) {
                    int jj = j >> 1, sb = (j & 1)*2;
                    mma16816(acc[i][j], af[i], bh[jj][sb], bh[jj][sb+1]);
                }
        }
    }
    const int r = lane >> 2, cq = (lane & 3)*2;
#pragma unroll
    for (int i = 0; i < 4; i++) {
        int r0 = m0 + wm + i*16 + r;
#pragma unroll
        for (int j = 0; j < 4; j++) {
            int cc = n0 + wn + j*8 + cq;
            *(float2*)&C[(size_t)r0*XPAD + cc]     = make_float2(acc[i][j][0], acc[i][j][1]);
            *(float2*)&C[(size_t)(r0+8)*XPAD + cc] = make_float2(acc[i][j][2], acc[i][j][3]);
        }
    }
}

// ---------------- gate apply ----------------
__global__ void k_gate_apply(const float* __restrict__ E, const float* __restrict__ gate_b,
                             const float* __restrict__ state) {
    int n = blockIdx.x;
    int o = threadIdx.x;
    __shared__ float Xs[BB][2*DIN];
    __shared__ float Es[16];
    if (o < 16) Es[o] = E[(size_t)n*EMB + o];
    for (int idx = o; idx < BB*2*DIN; idx += 128) {
        int bb = idx / (2*DIN), i = idx % (2*DIN);
        float v = (i < DIN) ? g_inpT[(size_t)n*XCOLS + bb*DIN + i]
                            : g_xg1T[(size_t)n*XPAD + bb*DIN + (i - DIN)];
        Xs[bb][i] = v;
    }
    __syncthreads();
    float bias = 0.f;
#pragma unroll
    for (int e = 0; e < 16; e++) bias += Es[e] * gate_b[e*OG + o];
    float acc[BB];
#pragma unroll
    for (int bb = 0; bb < BB; bb++) acc[bb] = bias;
    const float* Wn = g_Wg + (size_t)n*(2*DIN*OG);
    for (int i = 0; i < 2*DIN; i++) {
        float w = Wn[(size_t)i*OG + o];
#pragma unroll
        for (int bb = 0; bb < BB; bb++) acc[bb] += Xs[bb][i] * w;
    }
#pragma unroll
    for (int bb = 0; bb < BB; bb++) {
        float v = 1.0f / (1.0f + __expf(-acc[bb]));
        if (o < DD) {
            float st = state[((size_t)bb*NN + n)*DD + o];
            float zs = v * st;
            g_candT[(size_t)n*XCOLS + bb*DIN + 2 + o] = zs;
            __half hi = __float2half_rn(zs);
            size_t pidx = (size_t)n*XPAD + bb*DIN + 2 + o;
            g_xcahi[pidx] = hi;
            g_xcalo[pidx] = __float2half_rn(zs - __half2float(hi));
        } else {
            g_r[((size_t)bb*NN + n)*DD + (o - DD)] = v;
        }
    }
}

// ---------------- update apply: h + h16 ----------------
__global__ void k_upd_apply(const float* __restrict__ E, const float* __restrict__ upd_b,
                            const float* __restrict__ state) {
    int n = blockIdx.x;
    int o = threadIdx.x;
    __shared__ float Xs[BB][2*DIN];
    __shared__ float Es[16];
    if (o < 16) Es[o] = E[(size_t)n*EMB + o];
    for (int idx = o; idx < BB*2*DIN; idx += 64) {
        int bb = idx / (2*DIN), i = idx % (2*DIN);
        Xs[bb][i] = (i < DIN) ? g_candT[(size_t)n*XCOLS + bb*DIN + i]
                              : g_xg2T[(size_t)n*XPAD + bb*DIN + (i - DIN)];
    }
    __syncthreads();
    float bias = 0.f;
#pragma unroll
    for (int e = 0; e < 16; e++) bias += Es[e] * upd_b[e*OU + o];
    float acc[BB];
#pragma unroll
    for (int bb = 0; bb < BB; bb++) acc[bb] = bias;
    const float* Wn = g_Wu + (size_t)n*(2*DIN*OU);
    for (int i = 0; i < 2*DIN; i++) {
        float w = Wn[(size_t)i*OU + o];
#pragma unroll
        for (int bb = 0; bb < BB; bb++) acc[bb] += Xs[bb][i] * w;
    }
#pragma unroll
    for (int bb = 0; bb < BB; bb++) {
        float hc = tanhf(acc[bb]);
        size_t ix = ((size_t)bb*NN + n)*DD + o;
        float r = g_r[ix];
        float hv = r * state[ix] + (1.0f - r) * hc;
        g_h[ix] = hv;
        g_h16[ix] = __float2half_rn(hv);
    }
}

// ---------------- HHT on HMMA: g_ac/g_ad = mask(.) * (h16 @ h16^T) ----------------
__global__ void __launch_bounds__(256, 2) k_hht_mma() {
    __shared__ __align__(16) __half sA[128*64];
    __shared__ __align__(16) __half sB[128*64];
    const int tid = threadIdx.x;
    const int b = blockIdx.z, m0 = blockIdx.y*128, n0 = blockIdx.x*128;
    uint32_t aU = s2u(sA), bU = s2u(sB);

    const int row = tid >> 1, c0 = (tid & 1)*4;
#pragma unroll
    for (int t = 0; t < 4; t++) {
        int ch = c0 + t;
        uint32_t off = row*128 + ((ch ^ (row&7)) << 4);
        cp16(aU + off, g_h16 + ((size_t)b*NN + m0 + row)*64 + ch*8);
        cp16(bU + off, g_h16 + ((size_t)b*NN + n0 + row)*64 + ch*8);
    }
    cpcommit();
    asm volatile("cp.async.wait_group 0;" ::: "memory");
    __syncthreads();

    const int lane = tid & 31, wid = tid >> 5;
    const int wm = (wid & 1)*64, wn = (wid >> 1)*32;
    const int frow = ((lane>>3)&1)*8 + (lane&7);
    const int fch  = lane >> 4;

    float acc[4][4][4] = {};
#pragma unroll
    for (int ks = 0; ks < 4; ks++) {
        uint32_t af[4][4], bf[2][4];
#pragma unroll
        for (int i = 0; i < 4; i++) {
            int rr = wm + i*16 + frow;
            int ch = 2*ks + fch;
            ldsm4(af[i], aU + rr*128 + ((ch ^ (rr&7)) << 4));
        }
#pragma unroll
        for (int jj = 0; jj < 2; jj++) {
            int rr = wn + jj*16 + frow;
            int ch = 2*ks + fch;
            ldsm4(bf[jj], bU + rr*128 + ((ch ^ (rr&7)) << 4));
        }
#pragma unroll
        for (int i = 0; i < 4; i++)
#pragma unroll
            for (int j = 0; j < 4; j++) {
                int jj = j >> 1, sb = j & 1;
                mma16816(acc[i][j], af[i], bf[jj][sb], bf[jj][sb+2]);
            }
    }
    const int r = lane >> 2, cq = (lane & 3)*2;
#pragma unroll
    for (int i = 0; i < 4; i++) {
        int rbase = m0 + wm + i*16 + r;
#pragma unroll
        for (int j = 0; j < 4; j++) {
            int cc = n0 + wn + j*8 + cq;
#pragma unroll
            for (int hh = 0; hh < 2; hh++) {
                int rr = rbase + hh*8;
                uchar2 mk = *(const uchar2*)&g_mask[(size_t)rr*NN + cc];
                float v0 = acc[i][j][hh*2+0], v1 = acc[i][j][hh*2+1];
                __half2 hc = __floats2half2_rn(mk.x == 1 ? v0 : 0.f, mk.y == 1 ? v1 : 0.f);
                __half2 hd = __floats2half2_rn(mk.x == 2 ? v0 : 0.f, mk.y == 2 ? v1 : 0.f);
                *(__half2*)&g_ac[((size_t)b*NN + rr)*NN + cc] = hc;
                *(__half2*)&g_ad[((size_t)b*NN + rr)*NN + cc] = hd;
            }
        }
    }
}

// ---------------- W (fp32 [k][n]) -> transposed fp16 Wt[n][k] ----------------
__global__ void k_convW(const float* __restrict__ W, int which) {
    __shared__ float t[32][33];
    int tx = threadIdx.x, ty = threadIdx.y;
    int bx = blockIdx.x*32, by = blockIdx.y*32;
    for (int j = 0; j < 32; j += 8)
        t[ty+j][tx] = W[(size_t)(by+ty+j)*NN + bx+tx];
    __syncthreads();
    __half* Wt = (which == 0) ? g_wc : g_wd;
    for (int j = 0; j < 32; j += 8) {
        float v = t[tx][ty+j];
        Wt[(size_t)(bx+ty+j)*NN + by+tx] = __float2half_rn(v);
    }
}

// ---------------- big GEMM: deg[b] = Amask[b] @ W ----------------
#define BG_NSTG 4
__global__ void __launch_bounds__(256, 2) k_biggemm_mma(int branch) {
    __shared__ __align__(16) __half sA[BG_NSTG][4096];
    __shared__ __align__(16) __half sW[BG_NSTG][4096];
    const int tid = threadIdx.x;
    const int b = blockIdx.z, m0 = blockIdx.y*128, n0 = blockIdx.x*128;
    const __half* Am = ((branch == 0) ? g_ac : g_ad) + (size_t)b*NN*NN;
    const __half* Wt = (branch == 0) ? g_wc : g_wd;
    uint32_t aU = s2u(sA), wU = s2u(sW);

    const int lrow = tid >> 1, cp0 = (tid & 1)*2;
    const size_t aRow = (size_t)(m0 + lrow)*NN;
    const size_t wRow = (size_t)(n0 + lrow)*NN;
    uint32_t dOff[2];
#pragma unroll
    for (int t = 0; t < 2; t++) {
        int ch = cp0 + t;
        dOff[t] = lrow*64 + ((ch ^ ((lrow>>1)&3)) << 4);
    }
    auto issue = [&](int c, int s) {
#pragma unroll
        for (int t = 0; t < 2; t++) {
            int ch = cp0 + t;
            cp16(aU + s*8192 + dOff[t], Am + aRow + c*32 + ch*8);
            cp16(wU + s*8192 + dOff[t], Wt + wRow + c*32 + ch*8);
        }
        cpcommit();
    };

    const int lane = tid & 31, wid = tid >> 5;
    const int wm = (wid & 1)*64, wn = (wid >> 1)*32;
    const int frow = ((lane>>3)&1)*8 + (lane&7);
    const int fch  = lane >> 4;

    float acc[4][4][4] = {};
    issue(0, 0); issue(1, 1); issue(2, 2);
    const int NC = NN/32;
    for (int c = 0; c < NC; c++) {
        int s = c % BG_NSTG;
        if (c + 2 < NC)      asm volatile("cp.async.wait_group 2;" ::: "memory");
        else if (c + 1 < NC) asm volatile("cp.async.wait_group 1;" ::: "memory");
        else                 asm volatile("cp.async.wait_group 0;" ::: "memory");
        __syncthreads();
        if (c + 3 < NC) issue(c + 3, (c + 3) % BG_NSTG);
        uint32_t aB = aU + s*8192, wB = wU + s*8192;
#pragma unroll
        for (int ks = 0; ks < 2; ks++) {
            uint32_t af[4][4], bf[2][4];
#pragma unroll
            for (int i = 0; i < 4; i++) {
                int row = wm + i*16 + frow;
                int ch = 2*ks + fch;
                ldsm4(af[i], aB + row*64 + ((ch ^ ((row>>1)&3)) << 4));
            }
#pragma unroll
            for (int jj = 0; jj < 2; jj++) {
                int row = wn + jj*16 + frow;
                int ch = 2*ks + fch;
                ldsm4(bf[jj], wB + row*64 + ((ch ^ ((row>>1)&3)) << 4));
            }
#pragma unroll
            for (int i = 0; i < 4; i++)
#pragma unroll
                for (int j = 0; j < 4; j++) {
                    int jj = j >> 1, sb = j & 1;
                    mma16816(acc[i][j], af[i], bf[jj][sb], bf[jj][sb+2]);
                }
        }
    }
    float* C = g_deg + (size_t)b*NN*NN;
    const int r = lane >> 2, cq = (lane & 3)*2;
#pragma unroll
    for (int i = 0; i < 4; i++) {
        int r0 = m0 + wm + i*16 + r;
#pragma unroll
        for (int j = 0; j < 4; j++) {
            int cc = n0 + wn + j*8 + cq;
            *(float2*)&C[(size_t)r0*NN + cc]     = make_float2(acc[i][j][0], acc[i][j][1]);
            *(float2*)&C[(size_t)(r0+8)*NN + cc] = make_float2(acc[i][j][2], acc[i][j][3]);
        }
    }
}

// ---------------- deg @ h on HMMA: out = base + alpha*invsum[row]*(p16 @ h16) ----------------
#define DH_NSTG 3
__global__ void __launch_bounds__(256, 2) k_deg_h_mma(float* __restrict__ out,
                                                      float alpha, int mode) {
    __shared__ __align__(16) __half sA[DH_NSTG][128*32];  // 8KB / stage
    __shared__ __align__(16) __half sB[DH_NSTG][32*64];   // 4KB / stage
    const int tid = threadIdx.x;
    const int b = blockIdx.z, m0 = blockIdx.y*128;
    const __half* Ap = g_p16 + (size_t)b*NN*NN;
    const __half* Hp = g_h16 + (size_t)b*NN*DD;
    uint32_t aU = s2u(sA), bU = s2u(sB);

    // A loader: 128 rows x 4 chunks, 2 per thread
    const int rowA = tid >> 1, ap0 = (tid & 1)*2;
    const size_t aRow = (size_t)(m0 + rowA)*NN;
    // B loader: 32 rows x 8 chunks, 1 per thread
    const int rowB = tid >> 3, chB = tid & 7;
    const uint32_t dB = rowB*128 + ((chB ^ (rowB&7)) << 4);

    auto issue = [&](int c, int s) {
#pragma unroll
        for (int t = 0; t < 2; t++) {
            int ch = ap0 + t;
            cp16(aU + s*8192 + rowA*64 + ((ch ^ ((rowA>>1)&3)) << 4),
                 Ap + aRow + c*32 + ch*8);
        }
        cp16(bU + s*4096 + dB, Hp + (size_t)(c*32 + rowB)*DD + chB*8);
        cpcommit();
    };

    const int lane = tid & 31, wid = tid >> 5;
    const int wm = (wid & 3)*32;       // 4 m-warps x 32 rows
    const int wn = (wid >> 2)*32;      // 2 n-warps x 32 cols
    const int frow = ((lane>>3)&1)*8 + (lane&7);
    const int fch  = lane >> 4;

    float acc[2][4][4] = {};
    issue(0, 0); issue(1, 1);
    const int NC = NN/32;  // 64
    for (int c = 0; c < NC; c++) {
        int s = c % DH_NSTG;
        if (c + 1 < NC) asm volatile("cp.async.wait_group 1;" ::: "memory");
        else            asm volatile("cp.async.wait_group 0;" ::: "memory");
        __syncthreads();
        if (c + 2 < NC) issue(c + 2, (c + 2) % DH_NSTG);
        uint32_t aB = aU + s*8192, bBs = bU + s*4096;
#pragma unroll
        for (int ks = 0; ks < 2; ks++) {
            uint32_t af[2][4], bt[2][4];
#pragma unroll
            for (int i = 0; i < 2; i++) {
                int row = wm + i*16 + frow;
                int ch = 2*ks + fch;
                ldsm4(af[i], aB + row*64 + ((ch ^ ((row>>1)&3)) << 4));
            }
#pragma unroll
            for (int jj = 0; jj < 2; jj++) {
                int krow = ks*16 + frow;
                int ch = (wn >> 3) + jj*2 + fch;
                ldsm4t(bt[jj], bBs + krow*128 + ((ch ^ (krow&7)) << 4));
            }
#pragma unroll
            for (int i = 0; i < 2; i++)
#pragma unroll
                for (int j = 0; j < 4; j++) {
                    int jj = j >> 1, sb = (j & 1)*2;
                    mma16816(acc[i][j], af[i], bt[jj][sb], bt[jj][sb+1]);
                }
        }
    }
    // epilogue with invsum scaling
    const int r = lane >> 2, cq = (lane & 3)*2;
#pragma unroll
    for (int i = 0; i < 2; i++) {
#pragma unroll
        for (int hh = 0; hh < 2; hh++) {
            int r0 = m0 + wm + i*16 + hh*8 + r;
            float sc = alpha * g_invsum[(size_t)b*NN + r0];
#pragma unroll
            for (int j = 0; j < 4; j++) {
                int cc = wn + j*8 + cq;
                size_t ix = ((size_t)b*NN + r0)*DD + cc;
                float v0 = sc * acc[i][j][hh*2+0];
                float v1 = sc * acc[i][j][hh*2+1];
                if (mode == 0) {
                    v0 += 0.8f * g_h[ix];
                    v1 += 0.8f * g_h[ix+1];
                } else {
                    v0 += out[ix];
                    v1 += out[ix+1];
                }
                *(float2*)&out[ix] = make_float2(v0, v1);
            }
        }
    }
}

// ---------------- launch ----------------
extern "C" void kernel_launch(void* const* d_in, const int* in_sizes, int n_in,
                              void* d_out, int out_size) {
    const float* x       = (const float*)d_in[0];
    const float* state   = (const float*)d_in[1];
    const float* E       = (const float*)d_in[2];
    const float* Wc      = (const float*)d_in[3];
    const float* Wd      = (const float*)d_in[4];
    const float* gate_w  = (const float*)d_in[5];
    const float* gate_b  = (const float*)d_in[6];
    const float* upd_w   = (const float*)d_in[7];
    const float* upd_b   = (const float*)d_in[8];
    float* out = (float*)d_out;

    const int SX_SMEM = SX_NSTG * 32768;
    cudaFuncSetAttribute(k_sx_mma, cudaFuncAttributeMaxDynamicSharedMemorySize, SX_SMEM);

    // adjacency + supports + sign mask
    k_embed_outer<<<dim3(128,128), dim3(16,16)>>>(E);
    k_srowsoftmax<<<NN, 256>>>();

    // per-node weights + weight transposes
    k_mkW<<<dim3((2*DIN*OG)/256, NN), 256>>>(E, gate_w, 2*DIN*OG, 0);
    k_mkW<<<dim3((2*DIN*OU)/256, NN), 256>>>(E, upd_w,  2*DIN*OU, 1);
    k_convW<<<dim3(64,64), dim3(32,8)>>>(Wc, 0);
    k_convW<<<dim3(64,64), dim3(32,8)>>>(Wd, 1);

    // gate path
    k_concat<<<(NN*XCOLS + 255)/256, 256>>>(x, state);
    k_sx_mma<<<dim3(XPAD/128, NN/128), 256, SX_SMEM>>>(0);
    k_gate_apply<<<NN, 128>>>(E, gate_b, state);

    // update path
    k_sx_mma<<<dim3(XPAD/128, NN/128), 256, SX_SMEM>>>(1);
    k_upd_apply<<<NN, 64>>>(E, upd_b, state);

    // HHT -> masked fp16 (both branches)
    k_hht_mma<<<dim3(16,16,16), 256>>>();

    // connect branch
    k_biggemm_mma<<<dim3(16,16,16), 256>>>(0);
    k_expsum<<<dim3(NN, BB), 256>>>();
    k_deg_h_mma<<<dim3(1,16,16), 256>>>(out, -0.1f, 0);

    // disconnect branch
    k_biggemm_mma<<<dim3(16,16,16), 256>>>(1);
    k_expsum<<<dim3(NN, BB), 256>>>();
    k_deg_h_mma<<<dim3(1,16,16), 256>>>(out, +0.1f, 1);
}

// round 7
// speedup vs baseline: 5.1548x; 1.0116x over previous
#include <cuda_runtime.h>
#include <cuda_fp16.h>
#include <cstdint>
#include <math.h>

// ---------------- problem constants ----------------
#define NN   2048
#define BB   16
#define DD   64
#define DIN  66
#define EMB  16
#define OG   128
#define OU   64
#define XCOLS (BB*DIN)   // 1056
#define XPAD  1152       // padded cols (9 tiles of 128)

// ---------------- device scratch ----------------
__device__ float g_A   [(size_t)NN*NN];
__device__ unsigned char g_mask[(size_t)NN*NN];        // 1: A>0, 2: A<0, 0: A==0
__device__ float g_Wg  [(size_t)NN*2*DIN*OG];
__device__ float g_Wu  [(size_t)NN*2*DIN*OU];
__device__ float g_inpT[(size_t)NN*XCOLS];
__device__ float g_candT[(size_t)NN*XCOLS];
__device__ float g_xg1T[(size_t)NN*XPAD];
__device__ float g_xg2T[(size_t)NN*XPAD];
__device__ float g_r   [(size_t)BB*NN*DD];
__device__ float g_h   [(size_t)BB*NN*DD];
__device__ __half g_h16 [(size_t)BB*NN*DD];
__device__ __half g_shi[(size_t)NN*NN];
__device__ __half g_slo[(size_t)NN*NN];
__device__ __half g_xinhi[(size_t)NN*XPAD];
__device__ __half g_xinlo[(size_t)NN*XPAD];
__device__ __half g_xcahi[(size_t)NN*XPAD];
__device__ __half g_xcalo[(size_t)NN*XPAD];
__device__ __half g_ac[(size_t)BB*NN*NN];              // masked HHT (connect)
__device__ __half g_ad[(size_t)BB*NN*NN];              // masked HHT (disconnect)
__device__ __half g_wc[(size_t)NN*NN];
__device__ __half g_wd[(size_t)NN*NN];
__device__ __half g_deg16[(size_t)BB*NN*NN];           // fp16 logits
__device__ float g_pmax[(size_t)BB*16*NN];             // per-(b, ntile) row max
__device__ __half g_p16 [(size_t)BB*NN*NN];            // exp(v - rowmax), unnormalized
__device__ float g_invsum[(size_t)BB*NN];              // 1 / rowsum

// ---------------- asm helpers ----------------
__device__ __forceinline__ uint32_t s2u(const void* p) {
    return (uint32_t)__cvta_generic_to_shared(p);
}
__device__ __forceinline__ void cp16(uint32_t dst, const void* src) {
    asm volatile("cp.async.cg.shared.global [%0], [%1], 16;" :: "r"(dst), "l"(src));
}
__device__ __forceinline__ void cpcommit() { asm volatile("cp.async.commit_group;"); }
__device__ __forceinline__ void ldsm4(uint32_t* r, uint32_t addr) {
    asm volatile("ldmatrix.sync.aligned.m8n8.x4.shared.b16 {%0,%1,%2,%3}, [%4];"
        : "=r"(r[0]), "=r"(r[1]), "=r"(r[2]), "=r"(r[3]) : "r"(addr));
}
__device__ __forceinline__ void ldsm4t(uint32_t* r, uint32_t addr) {
    asm volatile("ldmatrix.sync.aligned.m8n8.x4.trans.shared.b16 {%0,%1,%2,%3}, [%4];"
        : "=r"(r[0]), "=r"(r[1]), "=r"(r[2]), "=r"(r[3]) : "r"(addr));
}
__device__ __forceinline__ void mma16816(float* c, const uint32_t* a, uint32_t b0, uint32_t b1) {
    asm volatile(
        "mma.sync.aligned.m16n8k16.row.col.f32.f16.f16.f32 "
        "{%0,%1,%2,%3}, {%4,%5,%6,%7}, {%8,%9}, {%0,%1,%2,%3};"
        : "+f"(c[0]), "+f"(c[1]), "+f"(c[2]), "+f"(c[3])
        : "r"(a[0]), "r"(a[1]), "r"(a[2]), "r"(a[3]), "r"(b0), "r"(b1));
}
// fast exp on the FMA pipe
__device__ __forceinline__ float fexp(float x) {
    float t = fmaxf(x * 1.4426950408889634f, -125.f);
    int   ni = __float2int_rn(t);
    float f  = t - (float)ni;
    float p = 0.00133335581f;
    p = fmaf(p, f, 0.00961812910f);
    p = fmaf(p, f, 0.05550410866f);
    p = fmaf(p, f, 0.24022650696f);
    p = fmaf(p, f, 0.69314718056f);
    p = fmaf(p, f, 1.0f);
    return p * __int_as_float((ni + 127) << 23);
}

// ---------------- A = E E^T + sign mask ----------------
__global__ void k_embed_outer(const float* __restrict__ E) {
    __shared__ float En[16][17], Em[16][17];
    int tx = threadIdx.x, ty = threadIdx.y;
    En[ty][tx] = E[((size_t)blockIdx.y*16 + ty)*EMB + tx];
    Em[ty][tx] = E[((size_t)blockIdx.x*16 + ty)*EMB + tx];
    __syncthreads();
    float s = 0.f;
#pragma unroll
    for (int e = 0; e < 16; e++) s += En[ty][e] * Em[tx][e];
    size_t idx = ((size_t)blockIdx.y*16 + ty)*NN + blockIdx.x*16 + tx;
    g_A[idx] = s;
    g_mask[idx] = (s > 0.f) ? 1 : ((s < 0.f) ? 2 : 0);
}

// ---------------- S softmax: relu(A) -> fp16 hi/lo ----------------
__global__ void k_srowsoftmax() {
    __shared__ float buf[NN];
    __shared__ float red[256];
    int row = blockIdx.x;
    int tid = threadIdx.x;
    const float* in = g_A + (size_t)row*NN;
    float mx = -1e30f;
    for (int i = tid; i < NN; i += 256) {
        float v = in[i];
        v = v > 0.f ? v : 0.f;
        buf[i] = v;
        mx = fmaxf(mx, v);
    }
    red[tid] = mx; __syncthreads();
    for (int s = 128; s > 0; s >>= 1) {
        if (tid < s) red[tid] = fmaxf(red[tid], red[tid+s]);
        __syncthreads();
    }
    mx = red[0];
    __syncthreads();
    float sum = 0.f;
    for (int i = tid; i < NN; i += 256) {
        float e = fexp(buf[i] - mx);
        buf[i] = e;
        sum += e;
    }
    red[tid] = sum; __syncthreads();
    for (int s = 128; s > 0; s >>= 1) {
        if (tid < s) red[tid] += red[tid+s];
        __syncthreads();
    }
    float inv = 1.0f / red[0];
    for (int i = tid; i < NN; i += 256) {
        float v = buf[i] * inv;
        __half hi = __float2half_rn(v);
        g_shi[(size_t)row*NN + i] = hi;
        g_slo[(size_t)row*NN + i] = __float2half_rn(v - __half2float(hi));
    }
}

// ---------------- exp + rowsum: deg16 + pmax -> p16 + invsum (single pass) ----------------
__global__ void __launch_bounds__(256) k_expsum() {
    int row = blockIdx.x, b = blockIdx.y, tid = threadIdx.x;
    const __half2* in = (const __half2*)(g_deg16 + ((size_t)b*NN + row)*NN);
    __half2* outp = (__half2*)(g_p16 + ((size_t)b*NN + row)*NN);
    __shared__ float red[256];
    float mx = -1e30f;
#pragma unroll
    for (int nt = 0; nt < 16; nt++)
        mx = fmaxf(mx, g_pmax[((size_t)b*16 + nt)*NN + row]);
    float2 e[4];
    float sum = 0.f;
#pragma unroll
    for (int t = 0; t < 4; t++) {
        float2 f = __half22float2(in[tid + t*256]);
        e[t].x = fexp(f.x - mx);
        e[t].y = fexp(f.y - mx);
        sum += e[t].x + e[t].y;
    }
    red[tid] = sum; __syncthreads();
    for (int s = 128; s > 0; s >>= 1) {
        if (tid < s) red[tid] += red[tid+s];
        __syncthreads();
    }
    if (tid == 0) g_invsum[(size_t)b*NN + row] = 1.0f / red[0];
#pragma unroll
    for (int t = 0; t < 4; t++)
        outp[tid + t*256] = __floats2half2_rn(e[t].x, e[t].y);
}

// ---------------- per-node weights ----------------
__global__ void k_mkW(const float* __restrict__ E, const float* __restrict__ pool,
                      int per_e, int which) {
    __shared__ float Es[16];
    int n = blockIdx.y;
    int j = blockIdx.x*256 + threadIdx.x;
    if (threadIdx.x < 16) Es[threadIdx.x] = E[(size_t)n*EMB + threadIdx.x];
    __syncthreads();
    float s = 0.f;
#pragma unroll
    for (int e = 0; e < 16; e++) s += Es[e] * pool[(size_t)e*per_e + j];
    float* W = (which == 0) ? g_Wg : g_Wu;
    W[(size_t)n*per_e + j] = s;
}

// ---------------- concat: fp32 + fp16 hi/lo ----------------
__global__ void k_concat(const float* __restrict__ x, const float* __restrict__ state) {
    int idx = blockIdx.x*256 + threadIdx.x;
    if (idx >= NN*XCOLS) return;
    int n = idx / XCOLS;
    int rem = idx % XCOLS;
    int b = rem / DIN, i = rem % DIN;
    float v;
    if (i < 2) v = x[((size_t)b*NN + n)*2 + i];
    else       v = state[((size_t)b*NN + n)*DD + (i-2)];
    g_inpT[idx] = v;
    __half hi = __float2half_rn(v);
    __half lo = __float2half_rn(v - __half2float(hi));
    size_t pidx = (size_t)n*XPAD + rem;
    g_xinhi[pidx] = hi; g_xinlo[pidx] = lo;
    if (i < 2) {
        g_candT[idx] = v;
        g_xcahi[pidx] = hi; g_xcalo[pidx] = lo;
    }
}

// ---------------- xg = S @ X on HMMA (3 passes) ----------------
#define SX_NSTG 3
__global__ void __launch_bounds__(256, 2) k_sx_mma(int which) {
    extern __shared__ __align__(16) __half dsm[];
    const __half* Bhi = which ? g_xcahi : g_xinhi;
    const __half* Blo = which ? g_xcalo : g_xinlo;
    float* C = which ? g_xg2T : g_xg1T;

    const int tid = threadIdx.x;
    const int n0 = blockIdx.x*128;
    const int m0 = blockIdx.y*128;
    uint32_t su = s2u(dsm);

    const int rowA = tid >> 1, ap0 = (tid & 1)*2;
    const int rowB = tid >> 3, bp0 = (tid & 7)*2;
    const size_t aRow = (size_t)(m0 + rowA)*NN;
    uint32_t dA[2], dB[2];
#pragma unroll
    for (int t = 0; t < 2; t++) {
        int ch = ap0 + t;
        dA[t] = rowA*64 + ((ch ^ ((rowA>>1)&3)) << 4);
        int cb = bp0 + t;
        dB[t] = 16384 + rowB*256 + ((cb ^ (rowB&7)) << 4);
    }

    auto issue = [&](int c, int s) {
        uint32_t base = su + s*32768;
#pragma unroll
        for (int t = 0; t < 2; t++) {
            int ch = ap0 + t;
            cp16(base + dA[t],        g_shi + aRow + c*32 + ch*8);
            cp16(base + 8192 + dA[t], g_slo + aRow + c*32 + ch*8);
        }
#pragma unroll
        for (int t = 0; t < 2; t++) {
            int cb = bp0 + t;
            size_t bo = (size_t)(c*32 + rowB)*XPAD + n0 + cb*8;
            cp16(base + dB[t],        Bhi + bo);
            cp16(base + 8192 + dB[t], Blo + bo);
        }
        cpcommit();
    };

    const int lane = tid & 31, wid = tid >> 5;
    const int wm = (wid & 1)*64, wn = (wid >> 1)*32;
    const int frow = ((lane>>3)&1)*8 + (lane&7);
    const int fch  = lane >> 4;

    float acc[4][4][4] = {};
    issue(0, 0); issue(1, 1);
    const int NC = NN/32;
    for (int c = 0; c < NC; c++) {
        int s = c % SX_NSTG;
        if (c + 1 < NC) asm volatile("cp.async.wait_group 1;" ::: "memory");
        else            asm volatile("cp.async.wait_group 0;" ::: "memory");
        __syncthreads();
        if (c + 2 < NC) issue(c + 2, (c + 2) % SX_NSTG);
        uint32_t base = su + s*32768;
#pragma unroll
        for (int ks = 0; ks < 2; ks++) {
            uint32_t af[4][4], bh[2][4], bl[2][4];
#pragma unroll
            for (int i = 0; i < 4; i++) {
                int row = wm + i*16 + frow;
                int ch = 2*ks + fch;
                ldsm4(af[i], base + row*64 + ((ch ^ ((row>>1)&3)) << 4));
            }
#pragma unroll
            for (int jj = 0; jj < 2; jj++) {
                int krow = ks*16 + frow;
                int ch = (wn >> 3) + jj*2 + fch;
                ldsm4t(bh[jj], base + 16384 + krow*256 + ((ch ^ (krow&7)) << 4));
            }
#pragma unroll
            for (int i = 0; i < 4; i++)
#pragma unroll
                for (int j = 0; j < 4; j++) {
                    int jj = j >> 1, sb = (j & 1)*2;
                    mma16816(acc[i][j], af[i], bh[jj][sb], bh[jj][sb+1]);
                }
#pragma unroll
            for (int jj = 0; jj < 2; jj++) {
                int krow = ks*16 + frow;
                int ch = (wn >> 3) + jj*2 + fch;
                ldsm4t(bl[jj], base + 24576 + krow*256 + ((ch ^ (krow&7)) << 4));
            }
#pragma unroll
            for (int i = 0; i < 4; i++)
#pragma unroll
                for (int j = 0; j < 4; j++) {
                    int jj = j >> 1, sb = (j & 1)*2;
                    mma16816(acc[i][j], af[i], bl[jj][sb], bl[jj][sb+1]);
                }
#pragma unroll
            for (int i = 0; i < 4; i++) {
                int row = wm + i*16 + frow;
                int ch = 2*ks + fch;
                ldsm4(af[i], base + 8192 + row*64 + ((ch ^ ((row>>1)&3)) << 4));
            }
#pragma unroll
            for (int i = 0; i < 4; i++)
#pragma unroll
                for (int j = 0; j < 4; j++) {
                    int jj = j >> 1, sb = (j & 1)*2;
                    mma16816(acc[i][j], af[i], bh[jj][sb], bh[jj][sb+1]);
                }
        }
    }
    const int r = lane >> 2, cq = (lane & 3)*2;
#pragma unroll
    for (int i = 0; i < 4; i++) {
        int r0 = m0 + wm + i*16 + r;
#pragma unroll
        for (int j = 0; j < 4; j++) {
            int cc = n0 + wn + j*8 + cq;
            *(float2*)&C[(size_t)r0*XPAD + cc]     = make_float2(acc[i][j][0], acc[i][j][1]);
            *(float2*)&C[(size_t)(r0+8)*XPAD + cc] = make_float2(acc[i][j][2], acc[i][j][3]);
        }
    }
}

// ---------------- gate apply ----------------
__global__ void k_gate_apply(const float* __restrict__ E, const float* __restrict__ gate_b,
                             const float* __restrict__ state) {
    int n = blockIdx.x;
    int o = threadIdx.x;
    __shared__ float Xs[BB][2*DIN];
    __shared__ float Es[16];
    if (o < 16) Es[o] = E[(size_t)n*EMB + o];
    for (int idx = o; idx < BB*2*DIN; idx += 128) {
        int bb = idx / (2*DIN), i = idx % (2*DIN);
        float v = (i < DIN) ? g_inpT[(size_t)n*XCOLS + bb*DIN + i]
                            : g_xg1T[(size_t)n*XPAD + bb*DIN + (i - DIN)];
        Xs[bb][i] = v;
    }
    __syncthreads();
    float bias = 0.f;
#pragma unroll
    for (int e = 0; e < 16; e++) bias += Es[e] * gate_b[e*OG + o];
    float acc[BB];
#pragma unroll
    for (int bb = 0; bb < BB; bb++) acc[bb] = bias;
    const float* Wn = g_Wg + (size_t)n*(2*DIN*OG);
    for (int i = 0; i < 2*DIN; i++) {
        float w = Wn[(size_t)i*OG + o];
#pragma unroll
        for (int bb = 0; bb < BB; bb++) acc[bb] += Xs[bb][i] * w;
    }
#pragma unroll
    for (int bb = 0; bb < BB; bb++) {
        float v = 1.0f / (1.0f + __expf(-acc[bb]));
        if (o < DD) {
            float st = state[((size_t)bb*NN + n)*DD + o];
            float zs = v * st;
            g_candT[(size_t)n*XCOLS + bb*DIN + 2 + o] = zs;
            __half hi = __float2half_rn(zs);
            size_t pidx = (size_t)n*XPAD + bb*DIN + 2 + o;
            g_xcahi[pidx] = hi;
            g_xcalo[pidx] = __float2half_rn(zs - __half2float(hi));
        } else {
            g_r[((size_t)bb*NN + n)*DD + (o - DD)] = v;
        }
    }
}

// ---------------- update apply: h + h16 ----------------
__global__ void k_upd_apply(const float* __restrict__ E, const float* __restrict__ upd_b,
                            const float* __restrict__ state) {
    int n = blockIdx.x;
    int o = threadIdx.x;
    __shared__ float Xs[BB][2*DIN];
    __shared__ float Es[16];
    if (o < 16) Es[o] = E[(size_t)n*EMB + o];
    for (int idx = o; idx < BB*2*DIN; idx += 64) {
        int bb = idx / (2*DIN), i = idx % (2*DIN);
        Xs[bb][i] = (i < DIN) ? g_candT[(size_t)n*XCOLS + bb*DIN + i]
                              : g_xg2T[(size_t)n*XPAD + bb*DIN + (i - DIN)];
    }
    __syncthreads();
    float bias = 0.f;
#pragma unroll
    for (int e = 0; e < 16; e++) bias += Es[e] * upd_b[e*OU + o];
    float acc[BB];
#pragma unroll
    for (int bb = 0; bb < BB; bb++) acc[bb] = bias;
    const float* Wn = g_Wu + (size_t)n*(2*DIN*OU);
    for (int i = 0; i < 2*DIN; i++) {
        float w = Wn[(size_t)i*OU + o];
#pragma unroll
        for (int bb = 0; bb < BB; bb++) acc[bb] += Xs[bb][i] * w;
    }
#pragma unroll
    for (int bb = 0; bb < BB; bb++) {
        float hc = tanhf(acc[bb]);
        size_t ix = ((size_t)bb*NN + n)*DD + o;
        float r = g_r[ix];
        float hv = r * state[ix] + (1.0f - r) * hc;
        g_h[ix] = hv;
        g_h16[ix] = __float2half_rn(hv);
    }
}

// ---------------- HHT on HMMA: g_ac/g_ad = mask(.) * (h16 @ h16^T) ----------------
__global__ void __launch_bounds__(256, 2) k_hht_mma() {
    __shared__ __align__(16) __half sA[128*64];
    __shared__ __align__(16) __half sB[128*64];
    const int tid = threadIdx.x;
    const int b = blockIdx.z, m0 = blockIdx.y*128, n0 = blockIdx.x*128;
    uint32_t aU = s2u(sA), bU = s2u(sB);

    const int row = tid >> 1, c0 = (tid & 1)*4;
#pragma unroll
    for (int t = 0; t < 4; t++) {
        int ch = c0 + t;
        uint32_t off = row*128 + ((ch ^ (row&7)) << 4);
        cp16(aU + off, g_h16 + ((size_t)b*NN + m0 + row)*64 + ch*8);
        cp16(bU + off, g_h16 + ((size_t)b*NN + n0 + row)*64 + ch*8);
    }
    cpcommit();
    asm volatile("cp.async.wait_group 0;" ::: "memory");
    __syncthreads();

    const int lane = tid & 31, wid = tid >> 5;
    const int wm = (wid & 1)*64, wn = (wid >> 1)*32;
    const int frow = ((lane>>3)&1)*8 + (lane&7);
    const int fch  = lane >> 4;

    float acc[4][4][4] = {};
#pragma unroll
    for (int ks = 0; ks < 4; ks++) {
        uint32_t af[4][4], bf[2][4];
#pragma unroll
        for (int i = 0; i < 4; i++) {
            int rr = wm + i*16 + frow;
            int ch = 2*ks + fch;
            ldsm4(af[i], aU + rr*128 + ((ch ^ (rr&7)) << 4));
        }
#pragma unroll
        for (int jj = 0; jj < 2; jj++) {
            int rr = wn + jj*16 + frow;
            int ch = 2*ks + fch;
            ldsm4(bf[jj], bU + rr*128 + ((ch ^ (rr&7)) << 4));
        }
#pragma unroll
        for (int i = 0; i < 4; i++)
#pragma unroll
            for (int j = 0; j < 4; j++) {
                int jj = j >> 1, sb = j & 1;
                mma16816(acc[i][j], af[i], bf[jj][sb], bf[jj][sb+2]);
            }
    }
    const int r = lane >> 2, cq = (lane & 3)*2;
#pragma unroll
    for (int i = 0; i < 4; i++) {
        int rbase = m0 + wm + i*16 + r;
#pragma unroll
        for (int j = 0; j < 4; j++) {
            int cc = n0 + wn + j*8 + cq;
#pragma unroll
            for (int hh = 0; hh < 2; hh++) {
                int rr = rbase + hh*8;
                uchar2 mk = *(const uchar2*)&g_mask[(size_t)rr*NN + cc];
                float v0 = acc[i][j][hh*2+0], v1 = acc[i][j][hh*2+1];
                __half2 hc = __floats2half2_rn(mk.x == 1 ? v0 : 0.f, mk.y == 1 ? v1 : 0.f);
                __half2 hd = __floats2half2_rn(mk.x == 2 ? v0 : 0.f, mk.y == 2 ? v1 : 0.f);
                *(__half2*)&g_ac[((size_t)b*NN + rr)*NN + cc] = hc;
                *(__half2*)&g_ad[((size_t)b*NN + rr)*NN + cc] = hd;
            }
        }
    }
}

// ---------------- W (fp32 [k][n]) -> transposed fp16 Wt[n][k] ----------------
__global__ void k_convW(const float* __restrict__ W, int which) {
    __shared__ float t[32][33];
    int tx = threadIdx.x, ty = threadIdx.y;
    int bx = blockIdx.x*32, by = blockIdx.y*32;
    for (int j = 0; j < 32; j += 8)
        t[ty+j][tx] = W[(size_t)(by+ty+j)*NN + bx+tx];
    __syncthreads();
    __half* Wt = (which == 0) ? g_wc : g_wd;
    for (int j = 0; j < 32; j += 8) {
        float v = t[tx][ty+j];
        Wt[(size_t)(bx+ty+j)*NN + by+tx] = __float2half_rn(v);
    }
}

// ---------------- big GEMM: deg16[b] = Amask[b] @ W, 256x128 tile, 512 thr ----------------
#define BG_NSTG 4
__global__ void __launch_bounds__(512, 1) k_biggemm_mma(int branch) {
    __shared__ __align__(16) __half sA[BG_NSTG][256*32];   // 16KB / stage
    __shared__ __align__(16) __half sW[BG_NSTG][128*32];   // 8KB / stage
    __shared__ float smax[4][256];
    const int tid = threadIdx.x;
    const int b = blockIdx.z, m0 = blockIdx.y*256, n0 = blockIdx.x*128;
    const __half* Am = ((branch == 0) ? g_ac : g_ad) + (size_t)b*NN*NN;
    const __half* Wt = (branch == 0) ? g_wc : g_wd;
    uint32_t aU = s2u(sA), wU = s2u(sW);

    // loaders: A 256 rows x 4 chunks (2/thread); W 128 rows x 4 chunks (1/thread)
    const int rowA = tid >> 1, ap0 = (tid & 1)*2;
    const int rowW = tid >> 2, chW = tid & 3;
    const size_t aRow = (size_t)(m0 + rowA)*NN;
    const size_t wRow = (size_t)(n0 + rowW)*NN;
    const uint32_t dW = rowW*64 + ((chW ^ ((rowW>>1)&3)) << 4);
    uint32_t dA[2];
#pragma unroll
    for (int t = 0; t < 2; t++) {
        int ch = ap0 + t;
        dA[t] = rowA*64 + ((ch ^ ((rowA>>1)&3)) << 4);
    }
    auto issue = [&](int c, int s) {
#pragma unroll
        for (int t = 0; t < 2; t++)
            cp16(aU + s*16384 + dA[t], Am + aRow + c*32 + (ap0 + t)*8);
        cp16(wU + s*8192 + dW, Wt + wRow + c*32 + chW*8);
        cpcommit();
    };

    const int lane = tid & 31, wid = tid >> 5;
    const int wm = (wid & 3)*64, wn = (wid >> 2)*32;
    const int frow = ((lane>>3)&1)*8 + (lane&7);
    const int fch  = lane >> 4;

    float acc[4][4][4] = {};
    issue(0, 0); issue(1, 1); issue(2, 2);
    const int NC = NN/32;
    for (int c = 0; c < NC; c++) {
        int s = c % BG_NSTG;
        if (c + 2 < NC)      asm volatile("cp.async.wait_group 2;" ::: "memory");
        else if (c + 1 < NC) asm volatile("cp.async.wait_group 1;" ::: "memory");
        else                 asm volatile("cp.async.wait_group 0;" ::: "memory");
        __syncthreads();
        if (c + 3 < NC) issue(c + 3, (c + 3) % BG_NSTG);
        uint32_t aB = aU + s*16384, wB = wU + s*8192;
#pragma unroll
        for (int ks = 0; ks < 2; ks++) {
            uint32_t af[4][4], bf[2][4];
#pragma unroll
            for (int i = 0; i < 4; i++) {
                int row = wm + i*16 + frow;
                int ch = 2*ks + fch;
                ldsm4(af[i], aB + row*64 + ((ch ^ ((row>>1)&3)) << 4));
            }
#pragma unroll
            for (int jj = 0; jj < 2; jj++) {
                int row = wn + jj*16 + frow;
                int ch = 2*ks + fch;
                ldsm4(bf[jj], wB + row*64 + ((ch ^ ((row>>1)&3)) << 4));
            }
#pragma unroll
            for (int i = 0; i < 4; i++)
#pragma unroll
                for (int j = 0; j < 4; j++) {
                    int jj = j >> 1, sb = j & 1;
                    mma16816(acc[i][j], af[i], bf[jj][sb], bf[jj][sb+2]);
                }
        }
    }
    // epilogue: fp16 store + per-CTA row max
    __half* C = g_deg16 + (size_t)b*NN*NN;
    const int r = lane >> 2, cq = (lane & 3)*2;
#pragma unroll
    for (int i = 0; i < 4; i++) {
#pragma unroll
        for (int hh = 0; hh < 2; hh++) {
            int r0 = m0 + wm + i*16 + hh*8 + r;
            float m = -1e30f;
#pragma unroll
            for (int j = 0; j < 4; j++) {
                float v0 = acc[i][j][hh*2+0], v1 = acc[i][j][hh*2+1];
                m = fmaxf(m, fmaxf(v0, v1));
                int cc = n0 + wn + j*8 + cq;
                *(__half2*)&C[(size_t)r0*NN + cc] = __floats2half2_rn(v0, v1);
            }
            m = fmaxf(m, __shfl_xor_sync(0xffffffff, m, 1));
            m = fmaxf(m, __shfl_xor_sync(0xffffffff, m, 2));
            if ((lane & 3) == 0) smax[wid >> 2][wm + i*16 + hh*8 + r] = m;
        }
    }
    __syncthreads();
    if (tid < 256) {
        float m4 = fmaxf(fmaxf(smax[0][tid], smax[1][tid]),
                         fmaxf(smax[2][tid], smax[3][tid]));
        g_pmax[((size_t)b*16 + blockIdx.x)*NN + m0 + tid] = m4;
    }
}

// ---------------- deg @ h on HMMA: out = base + alpha*invsum[row]*(p16 @ h16) ----------------
#define DH_NSTG 3
__global__ void __launch_bounds__(256, 2) k_deg_h_mma(float* __restrict__ out,
                                                      float alpha, int mode) {
    __shared__ __align__(16) __half sA[DH_NSTG][128*32];
    __shared__ __align__(16) __half sB[DH_NSTG][32*64];
    const int tid = threadIdx.x;
    const int b = blockIdx.z, m0 = blockIdx.y*128;
    const __half* Ap = g_p16 + (size_t)b*NN*NN;
    const __half* Hp = g_h16 + (size_t)b*NN*DD;
    uint32_t aU = s2u(sA), bU = s2u(sB);

    const int rowA = tid >> 1, ap0 = (tid & 1)*2;
    const size_t aRow = (size_t)(m0 + rowA)*NN;
    const int rowB = tid >> 3, chB = tid & 7;
    const uint32_t dB = rowB*128 + ((chB ^ (rowB&7)) << 4);

    auto issue = [&](int c, int s) {
#pragma unroll
        for (int t = 0; t < 2; t++) {
            int ch = ap0 + t;
            cp16(aU + s*8192 + rowA*64 + ((ch ^ ((rowA>>1)&3)) << 4),
                 Ap + aRow + c*32 + ch*8);
        }
        cp16(bU + s*4096 + dB, Hp + (size_t)(c*32 + rowB)*DD + chB*8);
        cpcommit();
    };

    const int lane = tid & 31, wid = tid >> 5;
    const int wm = (wid & 3)*32;
    const int wn = (wid >> 2)*32;
    const int frow = ((lane>>3)&1)*8 + (lane&7);
    const int fch  = lane >> 4;

    float acc[2][4][4] = {};
    issue(0, 0); issue(1, 1);
    const int NC = NN/32;
    for (int c = 0; c < NC; c++) {
        int s = c % DH_NSTG;
        if (c + 1 < NC) asm volatile("cp.async.wait_group 1;" ::: "memory");
        else            asm volatile("cp.async.wait_group 0;" ::: "memory");
        __syncthreads();
        if (c + 2 < NC) issue(c + 2, (c + 2) % DH_NSTG);
        uint32_t aB = aU + s*8192, bBs = bU + s*4096;
#pragma unroll
        for (int ks = 0; ks < 2; ks++) {
            uint32_t af[2][4], bt[2][4];
#pragma unroll
            for (int i = 0; i < 2; i++) {
                int row = wm + i*16 + frow;
                int ch = 2*ks + fch;
                ldsm4(af[i], aB + row*64 + ((ch ^ ((row>>1)&3)) << 4));
            }
#pragma unroll
            for (int jj = 0; jj < 2; jj++) {
                int krow = ks*16 + frow;
                int ch = (wn >> 3) + jj*2 + fch;
                ldsm4t(bt[jj], bBs + krow*128 + ((ch ^ (krow&7)) << 4));
            }
#pragma unroll
            for (int i = 0; i < 2; i++)
#pragma unroll
                for (int j = 0; j < 4; j++) {
                    int jj = j >> 1, sb = (j & 1)*2;
                    mma16816(acc[i][j], af[i], bt[jj][sb], bt[jj][sb+1]);
                }
        }
    }
    const int r = lane >> 2, cq = (lane & 3)*2;
#pragma unroll
    for (int i = 0; i < 2; i++) {
#pragma unroll
        for (int hh = 0; hh < 2; hh++) {
            int r0 = m0 + wm + i*16 + hh*8 + r;
            float sc = alpha * g_invsum[(size_t)b*NN + r0];
#pragma unroll
            for (int j = 0; j < 4; j++) {
                int cc = wn + j*8 + cq;
                size_t ix = ((size_t)b*NN + r0)*DD + cc;
                float v0 = sc * acc[i][j][hh*2+0];
                float v1 = sc * acc[i][j][hh*2+1];
                if (mode == 0) {
                    v0 += 0.8f * g_h[ix];
                    v1 += 0.8f * g_h[ix+1];
                } else {
                    v0 += out[ix];
                    v1 += out[ix+1];
                }
                *(float2*)&out[ix] = make_float2(v0, v1);
            }
        }
    }
}

// ---------------- launch ----------------
extern "C" void kernel_launch(void* const* d_in, const int* in_sizes, int n_in,
                              void* d_out, int out_size) {
    const float* x       = (const float*)d_in[0];
    const float* state   = (const float*)d_in[1];
    const float* E       = (const float*)d_in[2];
    const float* Wc      = (const float*)d_in[3];
    const float* Wd      = (const float*)d_in[4];
    const float* gate_w  = (const float*)d_in[5];
    const float* gate_b  = (const float*)d_in[6];
    const float* upd_w   = (const float*)d_in[7];
    const float* upd_b   = (const float*)d_in[8];
    float* out = (float*)d_out;

    const int SX_SMEM = SX_NSTG * 32768;
    cudaFuncSetAttribute(k_sx_mma, cudaFuncAttributeMaxDynamicSharedMemorySize, SX_SMEM);

    // adjacency + supports + sign mask
    k_embed_outer<<<dim3(128,128), dim3(16,16)>>>(E);
    k_srowsoftmax<<<NN, 256>>>();

    // per-node weights + weight transposes
    k_mkW<<<dim3((2*DIN*OG)/256, NN), 256>>>(E, gate_w, 2*DIN*OG, 0);
    k_mkW<<<dim3((2*DIN*OU)/256, NN), 256>>>(E, upd_w,  2*DIN*OU, 1);
    k_convW<<<dim3(64,64), dim3(32,8)>>>(Wc, 0);
    k_convW<<<dim3(64,64), dim3(32,8)>>>(Wd, 1);

    // gate path
    k_concat<<<(NN*XCOLS + 255)/256, 256>>>(x, state);
    k_sx_mma<<<dim3(XPAD/128, NN/128), 256, SX_SMEM>>>(0);
    k_gate_apply<<<NN, 128>>>(E, gate_b, state);

    // update path
    k_sx_mma<<<dim3(XPAD/128, NN/128), 256, SX_SMEM>>>(1);
    k_upd_apply<<<NN, 64>>>(E, upd_b, state);

    // HHT -> masked fp16 (both branches)
    k_hht_mma<<<dim3(16,16,16), 256>>>();

    // connect branch
    k_biggemm_mma<<<dim3(16,8,16), 512>>>(0);
    k_expsum<<<dim3(NN, BB), 256>>>();
    k_deg_h_mma<<<dim3(1,16,16), 256>>>(out, -0.1f, 0);

    // disconnect branch
    k_biggemm_mma<<<dim3(16,8,16), 512>>>(1);
    k_expsum<<<dim3(NN, BB), 256>>>();
    k_deg_h_mma<<<dim3(1,16,16), 256>>>(out, +0.1f, 1);
}

// round 8
// speedup vs baseline: 5.2988x; 1.0279x over previous
#include <cuda_runtime.h>
#include <cuda_fp16.h>
#include <cstdint>
#include <math.h>

// ---------------- problem constants ----------------
#define NN   2048
#define BB   16
#define DD   64
#define DIN  66
#define EMB  16
#define OG   128
#define OU   64
#define XCOLS (BB*DIN)   // 1056
#define XPAD  1152

// ---------------- device scratch ----------------
__device__ float g_A   [(size_t)NN*NN];
__device__ unsigned char g_mask[(size_t)NN*NN];
__device__ float g_Wg  [(size_t)NN*2*DIN*OG];
__device__ float g_Wu  [(size_t)NN*2*DIN*OU];
__device__ float g_inpT[(size_t)NN*XCOLS];
__device__ float g_candT[(size_t)NN*XCOLS];
__device__ float g_xg1T[(size_t)NN*XPAD];
__device__ float g_xg2T[(size_t)NN*XPAD];
__device__ float g_r   [(size_t)BB*NN*DD];
__device__ float g_h   [(size_t)BB*NN*DD];
__device__ __half g_h16 [(size_t)BB*NN*DD];
__device__ __half g_shi[(size_t)NN*NN];
__device__ __half g_slo[(size_t)NN*NN];
__device__ __half g_xinhi[(size_t)NN*XPAD];
__device__ __half g_xinlo[(size_t)NN*XPAD];
__device__ __half g_xcahi[(size_t)NN*XPAD];
__device__ __half g_xcalo[(size_t)NN*XPAD];
__device__ __half g_ac[(size_t)BB*NN*NN];
__device__ __half g_ad[(size_t)BB*NN*NN];
__device__ __half g_wc[(size_t)NN*NN];
__device__ __half g_wd[(size_t)NN*NN];
__device__ __half g_deg16[(size_t)2*BB*NN*NN];   // logits -> exp in place (per branch)
__device__ float g_pmax[(size_t)2*BB*16*NN];
__device__ float g_invsum[(size_t)2*BB*NN];

// ---------------- asm helpers ----------------
__device__ __forceinline__ uint32_t s2u(const void* p) {
    return (uint32_t)__cvta_generic_to_shared(p);
}
__device__ __forceinline__ void cp16(uint32_t dst, const void* src) {
    asm volatile("cp.async.cg.shared.global [%0], [%1], 16;" :: "r"(dst), "l"(src));
}
__device__ __forceinline__ void cpcommit() { asm volatile("cp.async.commit_group;"); }
__device__ __forceinline__ void ldsm4(uint32_t* r, uint32_t addr) {
    asm volatile("ldmatrix.sync.aligned.m8n8.x4.shared.b16 {%0,%1,%2,%3}, [%4];"
        : "=r"(r[0]), "=r"(r[1]), "=r"(r[2]), "=r"(r[3]) : "r"(addr));
}
__device__ __forceinline__ void ldsm4t(uint32_t* r, uint32_t addr) {
    asm volatile("ldmatrix.sync.aligned.m8n8.x4.trans.shared.b16 {%0,%1,%2,%3}, [%4];"
        : "=r"(r[0]), "=r"(r[1]), "=r"(r[2]), "=r"(r[3]) : "r"(addr));
}
__device__ __forceinline__ void mma16816(float* c, const uint32_t* a, uint32_t b0, uint32_t b1) {
    asm volatile(
        "mma.sync.aligned.m16n8k16.row.col.f32.f16.f16.f32 "
        "{%0,%1,%2,%3}, {%4,%5,%6,%7}, {%8,%9}, {%0,%1,%2,%3};"
        : "+f"(c[0]), "+f"(c[1]), "+f"(c[2]), "+f"(c[3])
        : "r"(a[0]), "r"(a[1]), "r"(a[2]), "r"(a[3]), "r"(b0), "r"(b1));
}
__device__ __forceinline__ float fexp(float x) {
    float t = fmaxf(x * 1.4426950408889634f, -125.f);
    int   ni = __float2int_rn(t);
    float f  = t - (float)ni;
    float p = 0.00133335581f;
    p = fmaf(p, f, 0.00961812910f);
    p = fmaf(p, f, 0.05550410866f);
    p = fmaf(p, f, 0.24022650696f);
    p = fmaf(p, f, 0.69314718056f);
    p = fmaf(p, f, 1.0f);
    return p * __int_as_float((ni + 127) << 23);
}

// ---------------- A = E E^T + sign mask ----------------
__global__ void k_embed_outer(const float* __restrict__ E) {
    __shared__ float En[16][17], Em[16][17];
    int tx = threadIdx.x, ty = threadIdx.y;
    En[ty][tx] = E[((size_t)blockIdx.y*16 + ty)*EMB + tx];
    Em[ty][tx] = E[((size_t)blockIdx.x*16 + ty)*EMB + tx];
    __syncthreads();
    float s = 0.f;
#pragma unroll
    for (int e = 0; e < 16; e++) s += En[ty][e] * Em[tx][e];
    size_t idx = ((size_t)blockIdx.y*16 + ty)*NN + blockIdx.x*16 + tx;
    g_A[idx] = s;
    g_mask[idx] = (s > 0.f) ? 1 : ((s < 0.f) ? 2 : 0);
}

// ---------------- S softmax: relu(A) -> fp16 hi/lo ----------------
__global__ void k_srowsoftmax() {
    __shared__ float buf[NN];
    __shared__ float red[256];
    int row = blockIdx.x;
    int tid = threadIdx.x;
    const float* in = g_A + (size_t)row*NN;
    float mx = -1e30f;
    for (int i = tid; i < NN; i += 256) {
        float v = in[i];
        v = v > 0.f ? v : 0.f;
        buf[i] = v;
        mx = fmaxf(mx, v);
    }
    red[tid] = mx; __syncthreads();
    for (int s = 128; s > 0; s >>= 1) {
        if (tid < s) red[tid] = fmaxf(red[tid], red[tid+s]);
        __syncthreads();
    }
    mx = red[0];
    __syncthreads();
    float sum = 0.f;
    for (int i = tid; i < NN; i += 256) {
        float e = fexp(buf[i] - mx);
        buf[i] = e;
        sum += e;
    }
    red[tid] = sum; __syncthreads();
    for (int s = 128; s > 0; s >>= 1) {
        if (tid < s) red[tid] += red[tid+s];
        __syncthreads();
    }
    float inv = 1.0f / red[0];
    for (int i = tid; i < NN; i += 256) {
        float v = buf[i] * inv;
        __half hi = __float2half_rn(v);
        g_shi[(size_t)row*NN + i] = hi;
        g_slo[(size_t)row*NN + i] = __float2half_rn(v - __half2float(hi));
    }
}

// ---------------- exp + rowsum (in place), both branches ----------------
__global__ void __launch_bounds__(256) k_expsum() {
    int row = blockIdx.x, b2 = blockIdx.y, tid = threadIdx.x;
    int b = b2 & 15, br = b2 >> 4;
    __half2* io = (__half2*)(g_deg16 + (((size_t)br*BB + b)*NN + row)*NN);
    __shared__ float red[256];
    float mx = -1e30f;
#pragma unroll
    for (int nt = 0; nt < 16; nt++)
        mx = fmaxf(mx, g_pmax[(((size_t)br*BB + b)*16 + nt)*NN + row]);
    float2 e[4];
    float sum = 0.f;
#pragma unroll
    for (int t = 0; t < 4; t++) {
        float2 f = __half22float2(io[tid + t*256]);
        e[t].x = fexp(f.x - mx);
        e[t].y = fexp(f.y - mx);
        sum += e[t].x + e[t].y;
    }
    red[tid] = sum; __syncthreads();
    for (int s = 128; s > 0; s >>= 1) {
        if (tid < s) red[tid] += red[tid+s];
        __syncthreads();
    }
    if (tid == 0) g_invsum[((size_t)br*BB + b)*NN + row] = 1.0f / red[0];
#pragma unroll
    for (int t = 0; t < 4; t++)
        io[tid + t*256] = __floats2half2_rn(e[t].x, e[t].y);
}

// ---------------- per-node weights, tiled (pool reused from smem) ----------------
__global__ void __launch_bounds__(256) k_mkW2(const float* __restrict__ E,
                                              const float* __restrict__ pool,
                                              int per_e, float* __restrict__ W) {
    __shared__ __align__(16) float Es[16][128];
    __shared__ __align__(16) float Ps[16][128];
    int tid = threadIdx.x;
    int j0 = blockIdx.x*128, m0 = blockIdx.y*128;
    // load E tile: rows m0..m0+127, 16 cols
    {
        int r = tid >> 1, e0 = (tid & 1)*8;
        float4 a = *(const float4*)&E[(size_t)(m0+r)*EMB + e0];
        float4 b = *(const float4*)&E[(size_t)(m0+r)*EMB + e0 + 4];
        Es[e0+0][r]=a.x; Es[e0+1][r]=a.y; Es[e0+2][r]=a.z; Es[e0+3][r]=a.w;
        Es[e0+4][r]=b.x; Es[e0+5][r]=b.y; Es[e0+6][r]=b.z; Es[e0+7][r]=b.w;
    }
    // load pool tile: 16 e x 128 j
    {
        int e = tid >> 4, c0 = (tid & 15)*8;
        float4 a = *(const float4*)&pool[(size_t)e*per_e + j0 + c0];
        float4 b = *(const float4*)&pool[(size_t)e*per_e + j0 + c0 + 4];
        *(float4*)&Ps[e][c0]   = a;
        *(float4*)&Ps[e][c0+4] = b;
    }
    __syncthreads();
    int row0 = (tid/16)*8, col0 = (tid%16)*8;
    float acc[8][8] = {};
#pragma unroll
    for (int k = 0; k < 16; k++) {
        float av[8], bv[8];
        float4 t;
        t = *(const float4*)&Es[k][row0];   av[0]=t.x; av[1]=t.y; av[2]=t.z; av[3]=t.w;
        t = *(const float4*)&Es[k][row0+4]; av[4]=t.x; av[5]=t.y; av[6]=t.z; av[7]=t.w;
        t = *(const float4*)&Ps[k][col0];   bv[0]=t.x; bv[1]=t.y; bv[2]=t.z; bv[3]=t.w;
        t = *(const float4*)&Ps[k][col0+4]; bv[4]=t.x; bv[5]=t.y; bv[6]=t.z; bv[7]=t.w;
#pragma unroll
        for (int i = 0; i < 8; i++)
#pragma unroll
            for (int j = 0; j < 8; j++) acc[i][j] += av[i]*bv[j];
    }
#pragma unroll
    for (int i = 0; i < 8; i++) {
        size_t ro = (size_t)(m0 + row0 + i)*per_e + j0 + col0;
        *(float4*)&W[ro]   = make_float4(acc[i][0], acc[i][1], acc[i][2], acc[i][3]);
        *(float4*)&W[ro+4] = make_float4(acc[i][4], acc[i][5], acc[i][6], acc[i][7]);
    }
}

// ---------------- concat ----------------
__global__ void k_concat(const float* __restrict__ x, const float* __restrict__ state) {
    int idx = blockIdx.x*256 + threadIdx.x;
    if (idx >= NN*XCOLS) return;
    int n = idx / XCOLS;
    int rem = idx % XCOLS;
    int b = rem / DIN, i = rem % DIN;
    float v;
    if (i < 2) v = x[((size_t)b*NN + n)*2 + i];
    else       v = state[((size_t)b*NN + n)*DD + (i-2)];
    g_inpT[idx] = v;
    __half hi = __float2half_rn(v);
    __half lo = __float2half_rn(v - __half2float(hi));
    size_t pidx = (size_t)n*XPAD + rem;
    g_xinhi[pidx] = hi; g_xinlo[pidx] = lo;
    if (i < 2) {
        g_candT[idx] = v;
        g_xcahi[pidx] = hi; g_xcalo[pidx] = lo;
    }
}

// ---------------- xg = S @ X on HMMA (3 passes) ----------------
#define SX_NSTG 3
__global__ void __launch_bounds__(256, 2) k_sx_mma(int which) {
    extern __shared__ __align__(16) __half dsm[];
    const __half* Bhi = which ? g_xcahi : g_xinhi;
    const __half* Blo = which ? g_xcalo : g_xinlo;
    float* C = which ? g_xg2T : g_xg1T;

    const int tid = threadIdx.x;
    const int n0 = blockIdx.x*128;
    const int m0 = blockIdx.y*128;
    uint32_t su = s2u(dsm);

    const int rowA = tid >> 1, ap0 = (tid & 1)*2;
    const int rowB = tid >> 3, bp0 = (tid & 7)*2;
    const size_t aRow = (size_t)(m0 + rowA)*NN;
    uint32_t dA[2], dB[2];
#pragma unroll
    for (int t = 0; t < 2; t++) {
        int ch = ap0 + t;
        dA[t] = rowA*64 + ((ch ^ ((rowA>>1)&3)) << 4);
        int cb = bp0 + t;
        dB[t] = 16384 + rowB*256 + ((cb ^ (rowB&7)) << 4);
    }

    auto issue = [&](int c, int s) {
        uint32_t base = su + s*32768;
#pragma unroll
        for (int t = 0; t < 2; t++) {
            int ch = ap0 + t;
            cp16(base + dA[t],        g_shi + aRow + c*32 + ch*8);
            cp16(base + 8192 + dA[t], g_slo + aRow + c*32 + ch*8);
        }
#pragma unroll
        for (int t = 0; t < 2; t++) {
            int cb = bp0 + t;
            size_t bo = (size_t)(c*32 + rowB)*XPAD + n0 + cb*8;
            cp16(base + dB[t],        Bhi + bo);
            cp16(base + 8192 + dB[t], Blo + bo);
        }
        cpcommit();
    };

    const int lane = tid & 31, wid = tid >> 5;
    const int wm = (wid & 1)*64, wn = (wid >> 1)*32;
    const int frow = ((lane>>3)&1)*8 + (lane&7);
    const int fch  = lane >> 4;

    float acc[4][4][4] = {};
    issue(0, 0); issue(1, 1);
    const int NC = NN/32;
    for (int c = 0; c < NC; c++) {
        int s = c % SX_NSTG;
        if (c + 1 < NC) asm volatile("cp.async.wait_group 1;" ::: "memory");
        else            asm volatile("cp.async.wait_group 0;" ::: "memory");
        __syncthreads();
        if (c + 2 < NC) issue(c + 2, (c + 2) % SX_NSTG);
        uint32_t base = su + s*32768;
#pragma unroll
        for (int ks = 0; ks < 2; ks++) {
            uint32_t af[4][4], bh[2][4], bl[2][4];
#pragma unroll
            for (int i = 0; i < 4; i++) {
                int row = wm + i*16 + frow;
                int ch = 2*ks + fch;
                ldsm4(af[i], base + row*64 + ((ch ^ ((row>>1)&3)) << 4));
            }
#pragma unroll
            for (int jj = 0; jj < 2; jj++) {
                int krow = ks*16 + frow;
                int ch = (wn >> 3) + jj*2 + fch;
                ldsm4t(bh[jj], base + 16384 + krow*256 + ((ch ^ (krow&7)) << 4));
            }
#pragma unroll
            for (int i = 0; i < 4; i++)
#pragma unroll
                for (int j = 0; j < 4; j++) {
                    int jj = j >> 1, sb = (j & 1)*2;
                    mma16816(acc[i][j], af[i], bh[jj][sb], bh[jj][sb+1]);
                }
#pragma unroll
            for (int jj = 0; jj < 2; jj++) {
                int krow = ks*16 + frow;
                int ch = (wn >> 3) + jj*2 + fch;
                ldsm4t(bl[jj], base + 24576 + krow*256 + ((ch ^ (krow&7)) << 4));
            }
#pragma unroll
            for (int i = 0; i < 4; i++)
#pragma unroll
                for (int j = 0; j < 4; j++) {
                    int jj = j >> 1, sb = (j & 1)*2;
                    mma16816(acc[i][j], af[i], bl[jj][sb], bl[jj][sb+1]);
                }
#pragma unroll
            for (int i = 0; i < 4; i++) {
                int row = wm + i*16 + frow;
                int ch = 2*ks + fch;
                ldsm4(af[i], base + 8192 + row*64 + ((ch ^ ((row>>1)&3)) << 4));
            }
#pragma unroll
            for (int i = 0; i < 4; i++)
#pragma unroll
                for (int j = 0; j < 4; j++) {
                    int jj = j >> 1, sb = (j & 1)*2;
                    mma16816(acc[i][j], af[i], bh[jj][sb], bh[jj][sb+1]);
                }
        }
    }
    const int r = lane >> 2, cq = (lane & 3)*2;
#pragma unroll
    for (int i = 0; i < 4; i++) {
        int r0 = m0 + wm + i*16 + r;
#pragma unroll
        for (int j = 0; j < 4; j++) {
            int cc = n0 + wn + j*8 + cq;
            *(float2*)&C[(size_t)r0*XPAD + cc]     = make_float2(acc[i][j][0], acc[i][j][1]);
            *(float2*)&C[(size_t)(r0+8)*XPAD + cc] = make_float2(acc[i][j][2], acc[i][j][3]);
        }
    }
}

// ---------------- gate apply ----------------
__global__ void k_gate_apply(const float* __restrict__ E, const float* __restrict__ gate_b,
                             const float* __restrict__ state) {
    int n = blockIdx.x;
    int o = threadIdx.x;
    __shared__ float Xs[BB][2*DIN];
    __shared__ float Es[16];
    if (o < 16) Es[o] = E[(size_t)n*EMB + o];
    for (int idx = o; idx < BB*2*DIN; idx += 128) {
        int bb = idx / (2*DIN), i = idx % (2*DIN);
        float v = (i < DIN) ? g_inpT[(size_t)n*XCOLS + bb*DIN + i]
                            : g_xg1T[(size_t)n*XPAD + bb*DIN + (i - DIN)];
        Xs[bb][i] = v;
    }
    __syncthreads();
    float bias = 0.f;
#pragma unroll
    for (int e = 0; e < 16; e++) bias += Es[e] * gate_b[e*OG + o];
    float acc[BB];
#pragma unroll
    for (int bb = 0; bb < BB; bb++) acc[bb] = bias;
    const float* Wn = g_Wg + (size_t)n*(2*DIN*OG);
    for (int i = 0; i < 2*DIN; i++) {
        float w = Wn[(size_t)i*OG + o];
#pragma unroll
        for (int bb = 0; bb < BB; bb++) acc[bb] += Xs[bb][i] * w;
    }
#pragma unroll
    for (int bb = 0; bb < BB; bb++) {
        float v = 1.0f / (1.0f + __expf(-acc[bb]));
        if (o < DD) {
            float st = state[((size_t)bb*NN + n)*DD + o];
            float zs = v * st;
            g_candT[(size_t)n*XCOLS + bb*DIN + 2 + o] = zs;
            __half hi = __float2half_rn(zs);
            size_t pidx = (size_t)n*XPAD + bb*DIN + 2 + o;
            g_xcahi[pidx] = hi;
            g_xcalo[pidx] = __float2half_rn(zs - __half2float(hi));
        } else {
            g_r[((size_t)bb*NN + n)*DD + (o - DD)] = v;
        }
    }
}

// ---------------- update apply: h + h16 ----------------
__global__ void k_upd_apply(const float* __restrict__ E, const float* __restrict__ upd_b,
                            const float* __restrict__ state) {
    int n = blockIdx.x;
    int o = threadIdx.x;
    __shared__ float Xs[BB][2*DIN];
    __shared__ float Es[16];
    if (o < 16) Es[o] = E[(size_t)n*EMB + o];
    for (int idx = o; idx < BB*2*DIN; idx += 64) {
        int bb = idx / (2*DIN), i = idx % (2*DIN);
        Xs[bb][i] = (i < DIN) ? g_candT[(size_t)n*XCOLS + bb*DIN + i]
                              : g_xg2T[(size_t)n*XPAD + bb*DIN + (i - DIN)];
    }
    __syncthreads();
    float bias = 0.f;
#pragma unroll
    for (int e = 0; e < 16; e++) bias += Es[e] * upd_b[e*OU + o];
    float acc[BB];
#pragma unroll
    for (int bb = 0; bb < BB; bb++) acc[bb] = bias;
    const float* Wn = g_Wu + (size_t)n*(2*DIN*OU);
    for (int i = 0; i < 2*DIN; i++) {
        float w = Wn[(size_t)i*OU + o];
#pragma unroll
        for (int bb = 0; bb < BB; bb++) acc[bb] += Xs[bb][i] * w;
    }
#pragma unroll
    for (int bb = 0; bb < BB; bb++) {
        float hc = tanhf(acc[bb]);
        size_t ix = ((size_t)bb*NN + n)*DD + o;
        float r = g_r[ix];
        float hv = r * state[ix] + (1.0f - r) * hc;
        g_h[ix] = hv;
        g_h16[ix] = __float2half_rn(hv);
    }
}

// ---------------- HHT on HMMA: g_ac/g_ad = mask(.) * (h16 @ h16^T) ----------------
__global__ void __launch_bounds__(256, 2) k_hht_mma() {
    __shared__ __align__(16) __half sA[128*64];
    __shared__ __align__(16) __half sB[128*64];
    const int tid = threadIdx.x;
    const int b = blockIdx.z, m0 = blockIdx.y*128, n0 = blockIdx.x*128;
    uint32_t aU = s2u(sA), bU = s2u(sB);

    const int row = tid >> 1, c0 = (tid & 1)*4;
#pragma unroll
    for (int t = 0; t < 4; t++) {
        int ch = c0 + t;
        uint32_t off = row*128 + ((ch ^ (row&7)) << 4);
        cp16(aU + off, g_h16 + ((size_t)b*NN + m0 + row)*64 + ch*8);
        cp16(bU + off, g_h16 + ((size_t)b*NN + n0 + row)*64 + ch*8);
    }
    cpcommit();
    asm volatile("cp.async.wait_group 0;" ::: "memory");
    __syncthreads();

    const int lane = tid & 31, wid = tid >> 5;
    const int wm = (wid & 1)*64, wn = (wid >> 1)*32;
    const int frow = ((lane>>3)&1)*8 + (lane&7);
    const int fch  = lane >> 4;

    float acc[4][4][4] = {};
#pragma unroll
    for (int ks = 0; ks < 4; ks++) {
        uint32_t af[4][4], bf[2][4];
#pragma unroll
        for (int i = 0; i < 4; i++) {
            int rr = wm + i*16 + frow;
            int ch = 2*ks + fch;
            ldsm4(af[i], aU + rr*128 + ((ch ^ (rr&7)) << 4));
        }
#pragma unroll
        for (int jj = 0; jj < 2; jj++) {
            int rr = wn + jj*16 + frow;
            int ch = 2*ks + fch;
            ldsm4(bf[jj], bU + rr*128 + ((ch ^ (rr&7)) << 4));
        }
#pragma unroll
        for (int i = 0; i < 4; i++)
#pragma unroll
            for (int j = 0; j < 4; j++) {
                int jj = j >> 1, sb = j & 1;
                mma16816(acc[i][j], af[i], bf[jj][sb], bf[jj][sb+2]);
            }
    }
    const int r = lane >> 2, cq = (lane & 3)*2;
#pragma unroll
    for (int i = 0; i < 4; i++) {
        int rbase = m0 + wm + i*16 + r;
#pragma unroll
        for (int j = 0; j < 4; j++) {
            int cc = n0 + wn + j*8 + cq;
#pragma unroll
            for (int hh = 0; hh < 2; hh++) {
                int rr = rbase + hh*8;
                uchar2 mk = *(const uchar2*)&g_mask[(size_t)rr*NN + cc];
                float v0 = acc[i][j][hh*2+0], v1 = acc[i][j][hh*2+1];
                __half2 hc = __floats2half2_rn(mk.x == 1 ? v0 : 0.f, mk.y == 1 ? v1 : 0.f);
                __half2 hd = __floats2half2_rn(mk.x == 2 ? v0 : 0.f, mk.y == 2 ? v1 : 0.f);
                *(__half2*)&g_ac[((size_t)b*NN + rr)*NN + cc] = hc;
                *(__half2*)&g_ad[((size_t)b*NN + rr)*NN + cc] = hd;
            }
        }
    }
}

// ---------------- W (fp32 [k][n]) -> transposed fp16 Wt[n][k] ----------------
__global__ void k_convW(const float* __restrict__ W, int which) {
    __shared__ float t[32][33];
    int tx = threadIdx.x, ty = threadIdx.y;
    int bx = blockIdx.x*32, by = blockIdx.y*32;
    for (int j = 0; j < 32; j += 8)
        t[ty+j][tx] = W[(size_t)(by+ty+j)*NN + bx+tx];
    __syncthreads();
    __half* Wt = (which == 0) ? g_wc : g_wd;
    for (int j = 0; j < 32; j += 8) {
        float v = t[tx][ty+j];
        Wt[(size_t)(bx+ty+j)*NN + by+tx] = __float2half_rn(v);
    }
}

// ---------------- big GEMM: both branches, 256x128 CTA, 8 warps, warp tile 64x64 ----------------
#define BG_NSTG 3
__global__ void __launch_bounds__(256, 1) k_biggemm_mma() {
    __shared__ __align__(16) __half sA[BG_NSTG][256*32];   // 16KB / stage
    __shared__ __align__(16) __half sW[BG_NSTG][128*32];   // 8KB / stage
    __shared__ float smax[2][256];
    const int tid = threadIdx.x;
    const int bz = blockIdx.z, b = bz & 15, br = bz >> 4;
    const int m0 = blockIdx.y*256, n0 = blockIdx.x*128;
    const __half* Am = ((br == 0) ? g_ac : g_ad) + (size_t)b*NN*NN;
    const __half* Wt = (br == 0) ? g_wc : g_wd;
    uint32_t aU = s2u(sA), wU = s2u(sW);

    // A loader: rows rowA, rowA+128; chunks ap0, ap0+1 (4 cp16/thread)
    const int rowA = tid >> 1, ap0 = (tid & 1)*2;
    // W loader: rows rowW, rowW+64; chunk chW (2 cp16/thread)
    const int rowW = tid >> 2, chW = tid & 3;
    const size_t aRow0 = (size_t)(m0 + rowA)*NN;
    const size_t aRow1 = (size_t)(m0 + rowA + 128)*NN;
    const size_t wRow0 = (size_t)(n0 + rowW)*NN;
    const size_t wRow1 = (size_t)(n0 + rowW + 64)*NN;
    uint32_t dA[2];
#pragma unroll
    for (int t = 0; t < 2; t++) {
        int ch = ap0 + t;
        dA[t] = rowA*64 + ((ch ^ ((rowA>>1)&3)) << 4);
    }
    const uint32_t dW = rowW*64 + ((chW ^ ((rowW>>1)&3)) << 4);

    auto issue = [&](int c, int s) {
#pragma unroll
        for (int t = 0; t < 2; t++) {
            cp16(aU + s*16384 + dA[t],            Am + aRow0 + c*32 + (ap0+t)*8);
            cp16(aU + s*16384 + dA[t] + 128*64,   Am + aRow1 + c*32 + (ap0+t)*8);
        }
        cp16(wU + s*8192 + dW,           Wt + wRow0 + c*32 + chW*8);
        cp16(wU + s*8192 + dW + 64*64,   Wt + wRow1 + c*32 + chW*8);
        cpcommit();
    };

    const int lane = tid & 31, wid = tid >> 5;
    const int wm = (wid & 3)*64;      // 4 m-warps x 64 rows
    const int wn = (wid >> 2)*64;     // 2 n-warps x 64 cols
    const int frow = ((lane>>3)&1)*8 + (lane&7);
    const int fch  = lane >> 4;

    float acc[4][8][4] = {};
    issue(0, 0); issue(1, 1);
    const int NC = NN/32;
    for (int c = 0; c < NC; c++) {
        int s = c % BG_NSTG;
        if (c + 1 < NC) asm volatile("cp.async.wait_group 1;" ::: "memory");
        else            asm volatile("cp.async.wait_group 0;" ::: "memory");
        __syncthreads();
        if (c + 2 < NC) issue(c + 2, (c + 2) % BG_NSTG);
        uint32_t aB = aU + s*16384, wB = wU + s*8192;
#pragma unroll
        for (int ks = 0; ks < 2; ks++) {
            uint32_t af[4][4], bf[4][4];
#pragma unroll
            for (int i = 0; i < 4; i++) {
                int row = wm + i*16 + frow;
                int ch = 2*ks + fch;
                ldsm4(af[i], aB + row*64 + ((ch ^ ((row>>1)&3)) << 4));
            }
#pragma unroll
            for (int jj = 0; jj < 4; jj++) {
                int row = wn + jj*16 + frow;
                int ch = 2*ks + fch;
                ldsm4(bf[jj], wB + row*64 + ((ch ^ ((row>>1)&3)) << 4));
            }
#pragma unroll
            for (int i = 0; i < 4; i++)
#pragma unroll
                for (int j = 0; j < 8; j++) {
                    int jj = j >> 1, sb = j & 1;
                    mma16816(acc[i][j], af[i], bf[jj][sb], bf[jj][sb+2]);
                }
        }
    }
    // epilogue: fp16 store + per-CTA row max
    __half* C = g_deg16 + (((size_t)br*BB + b)*NN)*NN;
    const int r = lane >> 2, cq = (lane & 3)*2;
#pragma unroll
    for (int i = 0; i < 4; i++) {
#pragma unroll
        for (int hh = 0; hh < 2; hh++) {
            int r0 = m0 + wm + i*16 + hh*8 + r;
            float m = -1e30f;
#pragma unroll
            for (int j = 0; j < 8; j++) {
                float v0 = acc[i][j][hh*2+0], v1 = acc[i][j][hh*2+1];
                m = fmaxf(m, fmaxf(v0, v1));
                int cc = n0 + wn + j*8 + cq;
                *(__half2*)&C[(size_t)r0*NN + cc] = __floats2half2_rn(v0, v1);
            }
            m = fmaxf(m, __shfl_xor_sync(0xffffffff, m, 1));
            m = fmaxf(m, __shfl_xor_sync(0xffffffff, m, 2));
            if ((lane & 3) == 0) smax[wid >> 2][wm + i*16 + hh*8 + r] = m;
        }
    }
    __syncthreads();
    if (tid < 256) {
        float m2 = fmaxf(smax[0][tid], smax[1][tid]);
        g_pmax[(((size_t)br*BB + b)*16 + blockIdx.x)*NN + m0 + tid] = m2;
    }
}

// ---------------- deg @ h on HMMA ----------------
#define DH_NSTG 3
__global__ void __launch_bounds__(256, 2) k_deg_h_mma(float* __restrict__ out,
                                                      float alpha, int mode, int br) {
    __shared__ __align__(16) __half sA[DH_NSTG][128*32];
    __shared__ __align__(16) __half sB[DH_NSTG][32*64];
    const int tid = threadIdx.x;
    const int b = blockIdx.z, m0 = blockIdx.y*128;
    const __half* Ap = g_deg16 + (((size_t)br*BB + b)*NN)*NN;
    const __half* Hp = g_h16 + (size_t)b*NN*DD;
    const float* inv = g_invsum + ((size_t)br*BB + b)*NN;
    uint32_t aU = s2u(sA), bU = s2u(sB);

    const int rowA = tid >> 1, ap0 = (tid & 1)*2;
    const size_t aRow = (size_t)(m0 + rowA)*NN;
    const int rowB = tid >> 3, chB = tid & 7;
    const uint32_t dB = rowB*128 + ((chB ^ (rowB&7)) << 4);

    auto issue = [&](int c, int s) {
#pragma unroll
        for (int t = 0; t < 2; t++) {
            int ch = ap0 + t;
            cp16(aU + s*8192 + rowA*64 + ((ch ^ ((rowA>>1)&3)) << 4),
                 Ap + aRow + c*32 + ch*8);
        }
        cp16(bU + s*4096 + dB, Hp + (size_t)(c*32 + rowB)*DD + chB*8);
        cpcommit();
    };

    const int lane = tid & 31, wid = tid >> 5;
    const int wm = (wid & 3)*32;
    const int wn = (wid >> 2)*32;
    const int frow = ((lane>>3)&1)*8 + (lane&7);
    const int fch  = lane >> 4;

    float acc[2][4][4] = {};
    issue(0, 0); issue(1, 1);
    const int NC = NN/32;
    for (int c = 0; c < NC; c++) {
        int s = c % DH_NSTG;
        if (c + 1 < NC) asm volatile("cp.async.wait_group 1;" ::: "memory");
        else            asm volatile("cp.async.wait_group 0;" ::: "memory");
        __syncthreads();
        if (c + 2 < NC) issue(c + 2, (c + 2) % DH_NSTG);
        uint32_t aB = aU + s*8192, bBs = bU + s*4096;
#pragma unroll
        for (int ks = 0; ks < 2; ks++) {
            uint32_t af[2][4], bt[2][4];
#pragma unroll
            for (int i = 0; i < 2; i++) {
                int row = wm + i*16 + frow;
                int ch = 2*ks + fch;
                ldsm4(af[i], aB + row*64 + ((ch ^ ((row>>1)&3)) << 4));
            }
#pragma unroll
            for (int jj = 0; jj < 2; jj++) {
                int krow = ks*16 + frow;
                int ch = (wn >> 3) + jj*2 + fch;
                ldsm4t(bt[jj], bBs + krow*128 + ((ch ^ (krow&7)) << 4));
            }
#pragma unroll
            for (int i = 0; i < 2; i++)
#pragma unroll
                for (int j = 0; j < 4; j++) {
                    int jj = j >> 1, sb = (j & 1)*2;
                    mma16816(acc[i][j], af[i], bt[jj][sb], bt[jj][sb+1]);
                }
        }
    }
    const int r = lane >> 2, cq = (lane & 3)*2;
#pragma unroll
    for (int i = 0; i < 2; i++) {
#pragma unroll
        for (int hh = 0; hh < 2; hh++) {
            int r0 = m0 + wm + i*16 + hh*8 + r;
            float sc = alpha * inv[r0];
#pragma unroll
            for (int j = 0; j < 4; j++) {
                int cc = wn + j*8 + cq;
                size_t ix = ((size_t)b*NN + r0)*DD + cc;
                float v0 = sc * acc[i][j][hh*2+0];
                float v1 = sc * acc[i][j][hh*2+1];
                if (mode == 0) {
                    v0 += 0.8f * g_h[ix];
                    v1 += 0.8f * g_h[ix+1];
                } else {
                    v0 += out[ix];
                    v1 += out[ix+1];
                }
                *(float2*)&out[ix] = make_float2(v0, v1);
            }
        }
    }
}

// ---------------- launch ----------------
extern "C" void kernel_launch(void* const* d_in, const int* in_sizes, int n_in,
                              void* d_out, int out_size) {
    const float* x       = (const float*)d_in[0];
    const float* state   = (const float*)d_in[1];
    const float* E       = (const float*)d_in[2];
    const float* Wc      = (const float*)d_in[3];
    const float* Wd      = (const float*)d_in[4];
    const float* gate_w  = (const float*)d_in[5];
    const float* gate_b  = (const float*)d_in[6];
    const float* upd_w   = (const float*)d_in[7];
    const float* upd_b   = (const float*)d_in[8];
    float* out = (float*)d_out;

    const int SX_SMEM = SX_NSTG * 32768;
    cudaFuncSetAttribute(k_sx_mma, cudaFuncAttributeMaxDynamicSharedMemorySize, SX_SMEM);

    float* d_Wg; cudaGetSymbolAddress((void**)&d_Wg, g_Wg);
    float* d_Wu; cudaGetSymbolAddress((void**)&d_Wu, g_Wu);

    // adjacency + supports + sign mask
    k_embed_outer<<<dim3(128,128), dim3(16,16)>>>(E);
    k_srowsoftmax<<<NN, 256>>>();

    // per-node weights + weight transposes
    k_mkW2<<<dim3((2*DIN*OG)/128, NN/128), 256>>>(E, gate_w, 2*DIN*OG, d_Wg);
    k_mkW2<<<dim3((2*DIN*OU)/128, NN/128), 256>>>(E, upd_w,  2*DIN*OU, d_Wu);
    k_convW<<<dim3(64,64), dim3(32,8)>>>(Wc, 0);
    k_convW<<<dim3(64,64), dim3(32,8)>>>(Wd, 1);

    // gate path
    k_concat<<<(NN*XCOLS + 255)/256, 256>>>(x, state);
    k_sx_mma<<<dim3(XPAD/128, NN/128), 256, SX_SMEM>>>(0);
    k_gate_apply<<<NN, 128>>>(E, gate_b, state);

    // update path
    k_sx_mma<<<dim3(XPAD/128, NN/128), 256, SX_SMEM>>>(1);
    k_upd_apply<<<NN, 64>>>(E, upd_b, state);

    // HHT -> masked fp16 (both branches)
    k_hht_mma<<<dim3(16,16,16), 256>>>();

    // both-branch big GEMM + softmax
    k_biggemm_mma<<<dim3(16, 8, 32), 256>>>();
    k_expsum<<<dim3(NN, 2*BB), 256>>>();

    // output
    k_deg_h_mma<<<dim3(1,16,16), 256>>>(out, -0.1f, 0, 0);
    k_deg_h_mma<<<dim3(1,16,16), 256>>>(out, +0.1f, 1, 1);
}